// round 1
// baseline (speedup 1.0000x reference)
#include <cuda_runtime.h>
#include <math.h>

#define B_   4
#define T_   2048
#define D_   1024
#define H_   16
#define DH_  64
#define R_   8
#define MTOT (B_*T_)          // 8192
#define LORA_SCALE 4.0f

// ---------------- scratch (device globals: no allocation allowed) -------------
__device__ float g_q  [MTOT*D_];
__device__ float g_k  [MTOT*D_];
__device__ float g_v  [MTOT*D_];
__device__ float g_ao [MTOT*D_];
__device__ float g_xaq[MTOT*R_];
__device__ float g_xav[MTOT*R_];
__device__ float g_sin[T_*32];
__device__ float g_cos[T_*32];

// ---------------- sin/cos table ----------------------------------------------
__global__ void sincos_kernel() {
    int idx = blockIdx.x * blockDim.x + threadIdx.x;
    if (idx >= T_*32) return;
    int t = idx >> 5, j = idx & 31;
    double theta = (double)t / pow(10000.0, (double)j / 32.0);
    g_sin[idx] = (float)sin(theta);
    g_cos[idx] = (float)cos(theta);
}

// ---------------- LoRA down-projection: XA = X @ A  (rank 8, both q and v) ----
__global__ void lora_down_kernel(const float* __restrict__ X,
                                 const float* __restrict__ Aq,
                                 const float* __restrict__ Av) {
    int m    = blockIdx.x;
    int lane = threadIdx.x & 31;
    int w    = threadIdx.x >> 5;       // 8 warps
    const float* x = X + m * D_;
    #pragma unroll
    for (int cc = 0; cc < 2; cc++) {
        int c = w * 2 + cc;            // 0..15 : 0-7 -> Aq, 8-15 -> Av
        const float* A = (c < 8) ? Aq : Av;
        int col = c & 7;
        float s = 0.f;
        for (int k = lane; k < D_; k += 32)
            s += x[k] * A[k * R_ + col];
        #pragma unroll
        for (int off = 16; off; off >>= 1)
            s += __shfl_down_sync(0xffffffffu, s, off);
        if (lane == 0) {
            float* XA = (c < 8) ? g_xaq : g_xav;
            XA[m * R_ + col] = s;
        }
    }
}

// ---------------- tiled fp32 SGEMM, 64x64x16, LoRA epilogue -------------------
// C[M,N] = A[M,K] @ B[K,N]  (+ loraScale * XA[M,8] @ LB[8,N] if XA != null)
__global__ void __launch_bounds__(256)
gemm_kernel(const float* __restrict__ A, const float* __restrict__ B,
            float* __restrict__ C,
            const float* __restrict__ XA, const float* __restrict__ LB,
            int M, int N, int K, float loraScale)
{
    __shared__ float As[16][64];
    __shared__ float Bs[16][64];

    const int tid  = threadIdx.x;
    const int tx   = tid & 15, ty = tid >> 4;
    const int row0 = blockIdx.y * 64, col0 = blockIdx.x * 64;

    const int aRow  = tid >> 2;          // 0..63
    const int aCol  = (tid & 3) * 4;     // 0,4,8,12
    const int bRow  = tid >> 4;          // 0..15
    const int bCol  = (tid & 15) * 4;    // 0..60

    float acc[4][4];
    #pragma unroll
    for (int i = 0; i < 4; i++)
        #pragma unroll
        for (int j = 0; j < 4; j++) acc[i][j] = 0.f;

    const float* Aptr = A + (size_t)(row0 + aRow) * K + aCol;
    const float* Bptr = B + (size_t)bRow * N + col0 + bCol;

    for (int kt = 0; kt < K; kt += 16) {
        float4 av = *(const float4*)(Aptr + kt);
        float4 bv = *(const float4*)(Bptr + (size_t)kt * N);
        __syncthreads();
        As[aCol + 0][aRow] = av.x;
        As[aCol + 1][aRow] = av.y;
        As[aCol + 2][aRow] = av.z;
        As[aCol + 3][aRow] = av.w;
        *(float4*)&Bs[bRow][bCol] = bv;
        __syncthreads();
        #pragma unroll
        for (int k = 0; k < 16; k++) {
            float4 ra = *(const float4*)&As[k][ty * 4];
            float4 rb = *(const float4*)&Bs[k][tx * 4];
            acc[0][0] += ra.x * rb.x; acc[0][1] += ra.x * rb.y;
            acc[0][2] += ra.x * rb.z; acc[0][3] += ra.x * rb.w;
            acc[1][0] += ra.y * rb.x; acc[1][1] += ra.y * rb.y;
            acc[1][2] += ra.y * rb.z; acc[1][3] += ra.y * rb.w;
            acc[2][0] += ra.z * rb.x; acc[2][1] += ra.z * rb.y;
            acc[2][2] += ra.z * rb.z; acc[2][3] += ra.z * rb.w;
            acc[3][0] += ra.w * rb.x; acc[3][1] += ra.w * rb.y;
            acc[3][2] += ra.w * rb.z; acc[3][3] += ra.w * rb.w;
        }
    }

    #pragma unroll
    for (int i = 0; i < 4; i++) {
        int m = row0 + ty * 4 + i;
        float4 o;
        float* op = &o.x;
        #pragma unroll
        for (int j = 0; j < 4; j++) {
            int n = col0 + tx * 4 + j;
            float val = acc[i][j];
            if (XA) {
                float s = 0.f;
                #pragma unroll
                for (int r = 0; r < R_; r++)
                    s += XA[m * R_ + r] * LB[r * N + n];
                val += loraScale * s;
            }
            op[j] = val;
        }
        *(float4*)&C[(size_t)m * N + col0 + tx * 4] = o;
    }
}

// ---------------- RoPE on q and k in place ------------------------------------
__global__ void rope_kernel() {
    int idx = blockIdx.x * blockDim.x + threadIdx.x;
    if (idx >= MTOT * H_ * 32) return;
    int j  = idx & 31;
    int h  = (idx >> 5) & 15;
    int bt = idx >> 9;
    int t  = bt & (T_ - 1);
    float s = g_sin[t * 32 + j];
    float c = g_cos[t * 32 + j];
    int base = bt * D_ + h * DH_ + j * 2;
    float2 q = *(float2*)&g_q[base];
    *(float2*)&g_q[base] = make_float2(q.x * c - q.y * s, q.x * s + q.y * c);
    float2 k = *(float2*)&g_k[base];
    *(float2*)&g_k[base] = make_float2(k.x * c - k.y * s, k.x * s + k.y * c);
}

// ---------------- flash attention, fp32, causal -------------------------------
__global__ void __launch_bounds__(64) attn_kernel() {
    __shared__ float Ks[64][64];
    __shared__ float Vs[64][64];

    const int qb = blockIdx.x, h = blockIdx.y, b = blockIdx.z;
    const int tid = threadIdx.x;
    const int t   = qb * 64 + tid;
    const int rowbase = (b * T_ + t) * D_ + h * DH_;

    float4 qv[16];
    #pragma unroll
    for (int i = 0; i < 16; i++) qv[i] = *(const float4*)&g_q[rowbase + i * 4];

    float4 acc[16];
    #pragma unroll
    for (int i = 0; i < 16; i++) acc[i] = make_float4(0.f, 0.f, 0.f, 0.f);
    float m_i = -1e30f, l_i = 0.f;

    for (int kt = 0; kt <= qb; kt++) {
        __syncthreads();
        const int kvbase = (b * T_ + kt * 64) * D_ + h * DH_;
        for (int idx = tid; idx < 1024; idx += 64) {
            int r = idx >> 4, c = (idx & 15) * 4;
            *(float4*)&Ks[r][c] = *(const float4*)&g_k[kvbase + r * D_ + c];
            *(float4*)&Vs[r][c] = *(const float4*)&g_v[kvbase + r * D_ + c];
        }
        __syncthreads();
        const bool diag = (kt == qb);

        #pragma unroll 1
        for (int cch = 0; cch < 4; cch++) {
            int j0 = cch * 16;
            if (diag && j0 > tid) break;
            float s[16];
            float mt = -1e30f;
            #pragma unroll
            for (int jj = 0; jj < 16; jj++) {
                int j = j0 + jj;
                const float4* kr = (const float4*)&Ks[j][0];
                float sum = 0.f;
                #pragma unroll
                for (int i = 0; i < 16; i++) {
                    float4 kk = kr[i];
                    sum += qv[i].x * kk.x + qv[i].y * kk.y
                         + qv[i].z * kk.z + qv[i].w * kk.w;
                }
                sum *= 0.125f;                       // 1/sqrt(64)
                if (diag && j > tid) sum = -1e30f;   // causal mask
                s[jj] = sum;
                mt = fmaxf(mt, sum);
            }
            float m_new = fmaxf(m_i, mt);
            float corr = __expf(m_i - m_new);
            l_i *= corr;
            #pragma unroll
            for (int i = 0; i < 16; i++) {
                acc[i].x *= corr; acc[i].y *= corr;
                acc[i].z *= corr; acc[i].w *= corr;
            }
            #pragma unroll
            for (int jj = 0; jj < 16; jj++) {
                float p = __expf(s[jj] - m_new);
                l_i += p;
                const float4* vr = (const float4*)&Vs[j0 + jj][0];
                #pragma unroll
                for (int i = 0; i < 16; i++) {
                    float4 vv = vr[i];
                    acc[i].x += p * vv.x; acc[i].y += p * vv.y;
                    acc[i].z += p * vv.z; acc[i].w += p * vv.w;
                }
            }
            m_i = m_new;
        }
    }

    float inv = 1.f / l_i;
    #pragma unroll
    for (int i = 0; i < 16; i++) {
        float4 o = acc[i];
        o.x *= inv; o.y *= inv; o.z *= inv; o.w *= inv;
        *(float4*)&g_ao[rowbase + i * 4] = o;
    }
}

// ---------------- launch -------------------------------------------------------
extern "C" void kernel_launch(void* const* d_in, const int* in_sizes, int n_in,
                              void* d_out, int out_size) {
    const float* X  = (const float*)d_in[0];
    const float* wq = (const float*)d_in[1];
    const float* wk = (const float*)d_in[2];
    const float* wv = (const float*)d_in[3];
    const float* wo = (const float*)d_in[4];
    const float* Aq = (const float*)d_in[5];
    const float* Bq = (const float*)d_in[6];
    const float* Av = (const float*)d_in[7];
    const float* Bv = (const float*)d_in[8];
    float* out = (float*)d_out;

    float *qp, *kp, *vp, *aop, *xaqp, *xavp;
    cudaGetSymbolAddress((void**)&qp,  g_q);
    cudaGetSymbolAddress((void**)&kp,  g_k);
    cudaGetSymbolAddress((void**)&vp,  g_v);
    cudaGetSymbolAddress((void**)&aop, g_ao);
    cudaGetSymbolAddress((void**)&xaqp, g_xaq);
    cudaGetSymbolAddress((void**)&xavp, g_xav);

    sincos_kernel<<<(T_*32 + 255) / 256, 256>>>();
    lora_down_kernel<<<MTOT, 256>>>(X, Aq, Av);

    dim3 gg(D_ / 64, MTOT / 64);   // (16, 128)
    gemm_kernel<<<gg, 256>>>(X, wq, qp, xaqp, Bq, MTOT, D_, D_, LORA_SCALE);
    gemm_kernel<<<gg, 256>>>(X, wk, kp, nullptr, nullptr, MTOT, D_, D_, 0.f);
    gemm_kernel<<<gg, 256>>>(X, wv, vp, xavp, Bv, MTOT, D_, D_, LORA_SCALE);

    rope_kernel<<<(MTOT * H_ * 32 + 255) / 256, 256>>>();

    attn_kernel<<<dim3(T_ / 64, H_, B_), 64>>>();

    gemm_kernel<<<gg, 256>>>(aop, wo, out, nullptr, nullptr, MTOT, D_, D_, 0.f);
}

// round 2
// speedup vs baseline: 1.1074x; 1.1074x over previous
#include <cuda_runtime.h>
#include <math.h>

#define B_   4
#define T_   2048
#define D_   1024
#define H_   16
#define DH_  64
#define R_   8
#define MTOT (B_*T_)          // 8192
#define M_   MTOT
#define N_   D_
#define K_   D_
#define LORA_SCALE 4.0f

// ---------------- scratch (device globals: no allocation allowed) -------------
__device__ float g_q  [MTOT*D_];
__device__ float g_k  [MTOT*D_];
__device__ float g_v  [MTOT*D_];
__device__ float g_ao [MTOT*D_];
__device__ float g_xaq[MTOT*R_];
__device__ float g_xav[MTOT*R_];
__device__ float g_sin[T_*32];
__device__ float g_cos[T_*32];

// ---------------- sin/cos table (double precision, one-time) ------------------
__global__ void sincos_kernel() {
    int idx = blockIdx.x * blockDim.x + threadIdx.x;
    if (idx >= T_*32) return;
    int t = idx >> 5, j = idx & 31;
    double theta = (double)t / pow(10000.0, (double)j / 32.0);
    g_sin[idx] = (float)sin(theta);
    g_cos[idx] = (float)cos(theta);
}

// ---------------- LoRA down-projection: XA = X @ A  (rank 8, q and v) ---------
__global__ void lora_down_kernel(const float* __restrict__ X,
                                 const float* __restrict__ Aq,
                                 const float* __restrict__ Av) {
    int m    = blockIdx.x;
    int lane = threadIdx.x & 31;
    int w    = threadIdx.x >> 5;       // 8 warps
    const float* x = X + m * D_;
    #pragma unroll
    for (int cc = 0; cc < 2; cc++) {
        int c = w * 2 + cc;            // 0..15 : 0-7 -> Aq, 8-15 -> Av
        const float* A = (c < 8) ? Aq : Av;
        int col = c & 7;
        float s = 0.f;
        for (int k = lane; k < D_; k += 32)
            s += x[k] * A[k * R_ + col];
        #pragma unroll
        for (int off = 16; off; off >>= 1)
            s += __shfl_down_sync(0xffffffffu, s, off);
        if (lane == 0) {
            float* XA = (c < 8) ? g_xaq : g_xav;
            XA[m * R_ + col] = s;
        }
    }
}

// ---------------- 128x128x8 double-buffered SGEMM, LoRA + RoPE epilogue -------
// C = A @ B  (+ loraScale * XA @ LB)   then optional RoPE on 64-wide heads.
__global__ void __launch_bounds__(256, 2)
gemm128_kernel(const float* __restrict__ A, const float* __restrict__ B,
               float* __restrict__ C,
               const float* __restrict__ XA, const float* __restrict__ LB,
               float loraScale, int ropeFlag)
{
    __shared__ float As[2][8][128];
    __shared__ float Bs[2][8][128];

    const int tid  = threadIdx.x;
    const int row0 = blockIdx.y * 128, col0 = blockIdx.x * 128;

    const int aRow = tid >> 1,  aCol = (tid & 1) * 4;   // A tile 128x8
    const int bRow = tid >> 5,  bCol = (tid & 31) * 4;  // B tile 8x128
    const int tx   = tid & 15,  ty   = tid >> 4;

    const float* Aptr = A + (size_t)(row0 + aRow) * K_ + aCol;
    const float* Bptr = B + (size_t)bRow * N_ + col0 + bCol;

    float acc[8][8];
    #pragma unroll
    for (int i = 0; i < 8; i++)
        #pragma unroll
        for (int j = 0; j < 8; j++) acc[i][j] = 0.f;

    // prologue: fill buffer 0
    {
        float4 av = *(const float4*)(Aptr);
        float4 bv = *(const float4*)(Bptr);
        As[0][aCol+0][aRow] = av.x;
        As[0][aCol+1][aRow] = av.y;
        As[0][aCol+2][aRow] = av.z;
        As[0][aCol+3][aRow] = av.w;
        *(float4*)&Bs[0][bRow][bCol] = bv;
    }
    __syncthreads();

    int buf = 0;
    for (int kt = 8; kt <= K_; kt += 8) {
        float4 av2, bv2;
        if (kt < K_) {
            av2 = *(const float4*)(Aptr + kt);
            bv2 = *(const float4*)(Bptr + (size_t)kt * N_);
        }
        #pragma unroll
        for (int k = 0; k < 8; k++) {
            float4 a0 = *(const float4*)&As[buf][k][ty*8];
            float4 a1 = *(const float4*)&As[buf][k][ty*8+4];
            float4 b0 = *(const float4*)&Bs[buf][k][tx*8];
            float4 b1 = *(const float4*)&Bs[buf][k][tx*8+4];
            float a[8] = {a0.x,a0.y,a0.z,a0.w,a1.x,a1.y,a1.z,a1.w};
            float b[8] = {b0.x,b0.y,b0.z,b0.w,b1.x,b1.y,b1.z,b1.w};
            #pragma unroll
            for (int i = 0; i < 8; i++)
                #pragma unroll
                for (int j = 0; j < 8; j++)
                    acc[i][j] += a[i] * b[j];
        }
        if (kt < K_) {
            buf ^= 1;
            As[buf][aCol+0][aRow] = av2.x;
            As[buf][aCol+1][aRow] = av2.y;
            As[buf][aCol+2][aRow] = av2.z;
            As[buf][aCol+3][aRow] = av2.w;
            *(float4*)&Bs[buf][bRow][bCol] = bv2;
            __syncthreads();
        }
    }

    // epilogue: LoRA + RoPE + store
    const int n0 = col0 + tx * 8;
    #pragma unroll
    for (int i = 0; i < 8; i++) {
        const int m = row0 + ty * 8 + i;
        float v[8];
        #pragma unroll
        for (int j = 0; j < 8; j++) v[j] = acc[i][j];

        if (XA) {
            float xa[8];
            #pragma unroll
            for (int r = 0; r < R_; r++) xa[r] = XA[m * R_ + r];
            #pragma unroll
            for (int j = 0; j < 8; j++) {
                float s = 0.f;
                #pragma unroll
                for (int r = 0; r < R_; r++)
                    s += xa[r] * LB[r * N_ + n0 + j];
                v[j] += loraScale * s;
            }
        }
        if (ropeFlag) {
            const int t = m & (T_ - 1);
            #pragma unroll
            for (int p = 0; p < 4; p++) {
                const int jj = (((n0 + 2*p) & 63) >> 1);
                const float sn = g_sin[t * 32 + jj];
                const float cs = g_cos[t * 32 + jj];
                const float e = v[2*p], o = v[2*p+1];
                v[2*p]   = e * cs - o * sn;
                v[2*p+1] = e * sn + o * cs;
            }
        }
        float* cp = &C[(size_t)m * N_ + n0];
        *(float4*)(cp)     = make_float4(v[0], v[1], v[2], v[3]);
        *(float4*)(cp + 4) = make_float4(v[4], v[5], v[6], v[7]);
    }
}

// ---------------- flash attention, fp32, causal, 128-query tiles --------------
__global__ void __launch_bounds__(128) attn_kernel() {
    __shared__ float Ks[64][64];
    __shared__ float Vs[64][64];

    const int qb = blockIdx.x, h = blockIdx.y, b = blockIdx.z;
    const int tid = threadIdx.x;
    const int t   = qb * 128 + tid;
    const int rowbase = (b * T_ + t) * D_ + h * DH_;

    float4 qv[16];
    #pragma unroll
    for (int i = 0; i < 16; i++) {
        float4 q = *(const float4*)&g_q[rowbase + i * 4];
        q.x *= 0.125f; q.y *= 0.125f; q.z *= 0.125f; q.w *= 0.125f;
        qv[i] = q;
    }

    float4 acc[16];
    #pragma unroll
    for (int i = 0; i < 16; i++) acc[i] = make_float4(0.f, 0.f, 0.f, 0.f);
    float m_i = -1e30f, l_i = 0.f;

    const int lastTile = (qb * 128 + 127) >> 6;   // inclusive

    for (int kt = 0; kt <= lastTile; kt++) {
        __syncthreads();
        const int kvbase = (b * T_ + kt * 64) * D_ + h * DH_;
        for (int idx = tid; idx < 1024; idx += 128) {
            int r = idx >> 4, c = (idx & 15) * 4;
            *(float4*)&Ks[r][c] = *(const float4*)&g_k[kvbase + r * D_ + c];
            *(float4*)&Vs[r][c] = *(const float4*)&g_v[kvbase + r * D_ + c];
        }
        __syncthreads();

        const int kmax = t - kt * 64;     // keys j <= kmax are visible
        if (kmax < 0) continue;
        const bool full = (kmax >= 63);

        #pragma unroll 1
        for (int cch = 0; cch < 4; cch++) {
            int j0 = cch * 16;
            if (j0 > kmax) break;
            float s[16];
            float mt = -1e30f;
            #pragma unroll
            for (int jj = 0; jj < 16; jj++) {
                int j = j0 + jj;
                const float4* kr = (const float4*)&Ks[j][0];
                float sum = 0.f;
                #pragma unroll
                for (int i = 0; i < 16; i++) {
                    float4 kk = kr[i];
                    sum += qv[i].x * kk.x + qv[i].y * kk.y
                         + qv[i].z * kk.z + qv[i].w * kk.w;
                }
                if (!full && j > kmax) sum = -1e30f;
                s[jj] = sum;
                mt = fmaxf(mt, sum);
            }
            float m_new = fmaxf(m_i, mt);
            float corr = __expf(m_i - m_new);
            l_i *= corr;
            #pragma unroll
            for (int i = 0; i < 16; i++) {
                acc[i].x *= corr; acc[i].y *= corr;
                acc[i].z *= corr; acc[i].w *= corr;
            }
            #pragma unroll
            for (int jj = 0; jj < 16; jj++) {
                float p = __expf(s[jj] - m_new);
                l_i += p;
                const float4* vr = (const float4*)&Vs[j0 + jj][0];
                #pragma unroll
                for (int i = 0; i < 16; i++) {
                    float4 vv = vr[i];
                    acc[i].x += p * vv.x; acc[i].y += p * vv.y;
                    acc[i].z += p * vv.z; acc[i].w += p * vv.w;
                }
            }
            m_i = m_new;
        }
    }

    float inv = 1.f / l_i;
    #pragma unroll
    for (int i = 0; i < 16; i++) {
        float4 o = acc[i];
        o.x *= inv; o.y *= inv; o.z *= inv; o.w *= inv;
        *(float4*)&g_ao[rowbase + i * 4] = o;
    }
}

// ---------------- launch -------------------------------------------------------
extern "C" void kernel_launch(void* const* d_in, const int* in_sizes, int n_in,
                              void* d_out, int out_size) {
    const float* X  = (const float*)d_in[0];
    const float* wq = (const float*)d_in[1];
    const float* wk = (const float*)d_in[2];
    const float* wv = (const float*)d_in[3];
    const float* wo = (const float*)d_in[4];
    const float* Aq = (const float*)d_in[5];
    const float* Bq = (const float*)d_in[6];
    const float* Av = (const float*)d_in[7];
    const float* Bv = (const float*)d_in[8];
    float* out = (float*)d_out;

    float *qp, *kp, *vp, *aop, *xaqp, *xavp;
    cudaGetSymbolAddress((void**)&qp,  g_q);
    cudaGetSymbolAddress((void**)&kp,  g_k);
    cudaGetSymbolAddress((void**)&vp,  g_v);
    cudaGetSymbolAddress((void**)&aop, g_ao);
    cudaGetSymbolAddress((void**)&xaqp, g_xaq);
    cudaGetSymbolAddress((void**)&xavp, g_xav);

    sincos_kernel<<<(T_*32 + 255) / 256, 256>>>();
    lora_down_kernel<<<MTOT, 256>>>(X, Aq, Av);

    dim3 gg(N_ / 128, M_ / 128);   // (8, 64)
    gemm128_kernel<<<gg, 256>>>(X, wq, qp, xaqp, Bq, LORA_SCALE, 1);
    gemm128_kernel<<<gg, 256>>>(X, wk, kp, nullptr, nullptr, 0.f, 1);
    gemm128_kernel<<<gg, 256>>>(X, wv, vp, xavp, Bv, LORA_SCALE, 0);

    attn_kernel<<<dim3(T_ / 128, H_, B_), 128>>>();

    gemm128_kernel<<<gg, 256>>>(aop, wo, out, nullptr, nullptr, 0.f, 0);
}

// round 4
// speedup vs baseline: 1.4761x; 1.3330x over previous
#include <cuda_runtime.h>
#include <cuda_bf16.h>
#include <math.h>
#include <cstdint>

#define B_   4
#define T_   2048
#define D_   1024
#define H_   16
#define DH_  64
#define R_   8
#define MTOT (B_*T_)          // 8192
#define KTOT 3072             // split-bf16 concatenated K
#define NCHUNK 48             // KTOT / 64
#define LORA_SCALE 4.0f

// ---------------- scratch (device globals: no allocation allowed) -------------
__device__ float g_q  [MTOT*D_];
__device__ float g_k  [MTOT*D_];
__device__ float g_v  [MTOT*D_];
__device__ float g_xaq[MTOT*R_];
__device__ float g_xav[MTOT*R_];
__device__ float g_sin[T_*32];
__device__ float g_cos[T_*32];
__device__ __nv_bfloat16 g_xcat [MTOT*KTOT];     // [Xhi | Xhi | Xlo]
__device__ __nv_bfloat16 g_aocat[MTOT*KTOT];     // attention out, same layout
__device__ __nv_bfloat16 g_wtcat[4ull*D_*KTOT];  // per weight: rows n, [hi|lo|hi]

// ---------------- warp-level MMA helpers (sm_80+, no 'a' features) ------------
__device__ __forceinline__ uint32_t smem_u32(const void* p) {
    uint32_t a;
    asm("{ .reg .u64 t; cvta.to.shared.u64 t, %1; cvt.u32.u64 %0, t; }" : "=r"(a) : "l"(p));
    return a;
}
__device__ __forceinline__ void ldsm_x4(uint32_t& r0, uint32_t& r1,
                                        uint32_t& r2, uint32_t& r3, uint32_t addr) {
    asm volatile("ldmatrix.sync.aligned.m8n8.x4.shared.b16 {%0,%1,%2,%3}, [%4];"
                 : "=r"(r0), "=r"(r1), "=r"(r2), "=r"(r3) : "r"(addr));
}
__device__ __forceinline__ void mma16816(float* d, const uint32_t* a,
                                         uint32_t b0, uint32_t b1) {
    asm volatile("mma.sync.aligned.m16n8k16.row.col.f32.bf16.bf16.f32 "
                 "{%0,%1,%2,%3}, {%4,%5,%6,%7}, {%8,%9}, {%0,%1,%2,%3};"
                 : "+f"(d[0]), "+f"(d[1]), "+f"(d[2]), "+f"(d[3])
                 : "r"(a[0]), "r"(a[1]), "r"(a[2]), "r"(a[3]), "r"(b0), "r"(b1));
}

// ---------------- sin/cos table -----------------------------------------------
__global__ void sincos_kernel() {
    int idx = blockIdx.x * blockDim.x + threadIdx.x;
    if (idx >= T_*32) return;
    int t = idx >> 5, j = idx & 31;
    double theta = (double)t / pow(10000.0, (double)j / 32.0);
    g_sin[idx] = (float)sin(theta);
    g_cos[idx] = (float)cos(theta);
}

// ---------------- LoRA down-projection ----------------------------------------
__global__ void lora_down_kernel(const float* __restrict__ X,
                                 const float* __restrict__ Aq,
                                 const float* __restrict__ Av) {
    int m    = blockIdx.x;
    int lane = threadIdx.x & 31;
    int w    = threadIdx.x >> 5;
    const float* x = X + m * D_;
    #pragma unroll
    for (int cc = 0; cc < 2; cc++) {
        int c = w * 2 + cc;
        const float* A = (c < 8) ? Aq : Av;
        int col = c & 7;
        float s = 0.f;
        for (int k = lane; k < D_; k += 32)
            s += x[k] * A[k * R_ + col];
        #pragma unroll
        for (int off = 16; off; off >>= 1)
            s += __shfl_down_sync(0xffffffffu, s, off);
        if (lane == 0) {
            float* XA = (c < 8) ? g_xaq : g_xav;
            XA[m * R_ + col] = s;
        }
    }
}

// ---------------- split X -> [hi|hi|lo] bf16 ----------------------------------
__global__ void split_x_kernel(const float* __restrict__ X) {
    int idx4 = blockIdx.x * blockDim.x + threadIdx.x;
    if (idx4 >= MTOT * D_ / 4) return;
    int m = idx4 >> 8;
    int k = (idx4 & 255) * 4;
    float4 x = ((const float4*)X)[idx4];
    float xs[4] = {x.x, x.y, x.z, x.w};
    __nv_bfloat16 h[4], l[4];
    #pragma unroll
    for (int i = 0; i < 4; i++) {
        h[i] = __float2bfloat16(xs[i]);
        l[i] = __float2bfloat16(xs[i] - __bfloat162float(h[i]));
    }
    size_t base = (size_t)m * KTOT + k;
    *(__nv_bfloat162*)&g_xcat[base]        = __nv_bfloat162(h[0], h[1]);
    *(__nv_bfloat162*)&g_xcat[base+2]      = __nv_bfloat162(h[2], h[3]);
    *(__nv_bfloat162*)&g_xcat[base+1024]   = __nv_bfloat162(h[0], h[1]);
    *(__nv_bfloat162*)&g_xcat[base+1026]   = __nv_bfloat162(h[2], h[3]);
    *(__nv_bfloat162*)&g_xcat[base+2048]   = __nv_bfloat162(l[0], l[1]);
    *(__nv_bfloat162*)&g_xcat[base+2050]   = __nv_bfloat162(l[2], l[3]);
}

// ---------------- transpose + split weights -> Wt[n][hi|lo|hi] ----------------
__global__ void split_wt_kernel(const float* __restrict__ W0, const float* __restrict__ W1,
                                const float* __restrict__ W2, const float* __restrict__ W3) {
    const float* Ws[4] = {W0, W1, W2, W3};
    const float* W = Ws[blockIdx.z];
    __shared__ float tile[32][33];
    int bx = blockIdx.x * 32, by = blockIdx.y * 32;
    for (int i = threadIdx.y; i < 32; i += 8)
        tile[i][threadIdx.x] = W[(size_t)(by + i) * D_ + bx + threadIdx.x];
    __syncthreads();
    __nv_bfloat16* out = g_wtcat + (size_t)blockIdx.z * D_ * KTOT;
    for (int i = threadIdx.y; i < 32; i += 8) {
        int n = bx + i, k = by + threadIdx.x;
        float x = tile[threadIdx.x][i];
        __nv_bfloat16 h = __float2bfloat16(x);
        __nv_bfloat16 l = __float2bfloat16(x - __bfloat162float(h));
        out[(size_t)n * KTOT + k]        = h;
        out[(size_t)n * KTOT + 1024 + k] = l;
        out[(size_t)n * KTOT + 2048 + k] = h;
    }
}

// ================= HMMA split-bf16 GEMM ========================================
// C[MTOT, D] (fp32) = Acat[MTOT, KTOT] x Bcat[D, KTOT]^T  (+ LoRA, + RoPE)
// 256 threads, 128x128 tile, warp = 64x32, atoms m16n8k16.
#define SA(buf) ((buf) * 16384)
#define SB(buf) (32768 + (buf) * 16384)
#define SM_LB   65536
#define SM_TOTAL 69632

__global__ void __launch_bounds__(256)
gemm_mma_kernel(const __nv_bfloat16* __restrict__ Acat,
                const __nv_bfloat16* __restrict__ Bcat,
                float* __restrict__ C,
                const float* __restrict__ XA, const float* __restrict__ LB,
                float loraScale, int ropeFlag)
{
    extern __shared__ char smem[];
    const uint32_t sbase = smem_u32(smem);
    const int tid  = threadIdx.x;
    const int lane = tid & 31;
    const int wid  = tid >> 5;
    const int wm   = wid & 1;        // 2 m-blocks of 64
    const int wn   = wid >> 1;       // 4 n-blocks of 32
    const int row0 = blockIdx.y * 128, col0 = blockIdx.x * 128;

    float acc[4][4][4];
    #pragma unroll
    for (int i = 0; i < 4; i++)
        #pragma unroll
        for (int j = 0; j < 4; j++)
            #pragma unroll
            for (int r = 0; r < 4; r++) acc[i][j][r] = 0.f;

    uint4 av[4], bv[4];
    auto fetch = [&](const __nv_bfloat16* g, int r0, int kb, uint4* v) {
        #pragma unroll
        for (int i = 0; i < 4; i++) {
            int idx = i * 256 + tid;
            int r = idx >> 3, c = idx & 7;
            v[i] = *((const uint4*)(g + (size_t)(r0 + r) * KTOT + kb) + c);
        }
    };
    auto stash = [&](const uint4* v, int soff) {
        #pragma unroll
        for (int i = 0; i < 4; i++) {
            int idx = i * 256 + tid;
            int r = idx >> 3, c = idx & 7;
            uint32_t off = (uint32_t)(c * 16) ^ (uint32_t)((r & 7) << 4);
            *(uint4*)(smem + soff + r * 128 + off) = v[i];
        }
    };

    // prologue: chunk 0
    fetch(Acat, row0, 0, av);
    fetch(Bcat, col0, 0, bv);
    stash(av, SA(0));
    stash(bv, SB(0));
    __syncthreads();

    for (int c = 0; c < NCHUNK; c++) {
        const int buf = c & 1;
        if (c < NCHUNK - 1) {
            fetch(Acat, row0, (c + 1) * 64, av);
            fetch(Bcat, col0, (c + 1) * 64, bv);
        }
        const uint32_t sa = sbase + SA(buf);
        const uint32_t sb = sbase + SB(buf);
        #pragma unroll
        for (int ks = 0; ks < 4; ks++) {
            uint32_t af[4][4], bfr[2][4];
            #pragma unroll
            for (int ma = 0; ma < 4; ma++) {
                int r = wm * 64 + ma * 16 + (lane & 15);
                uint32_t off = (uint32_t)(ks * 32 + ((lane >> 4) << 4));
                uint32_t addr = sa + r * 128 + (off ^ ((r & 7) << 4));
                ldsm_x4(af[ma][0], af[ma][1], af[ma][2], af[ma][3], addr);
            }
            #pragma unroll
            for (int nb = 0; nb < 2; nb++) {
                int r = wn * 32 + nb * 16 + ((lane >> 4) << 3) + (lane & 7);
                uint32_t off = (uint32_t)(ks * 32 + (((lane >> 3) & 1) << 4));
                uint32_t addr = sb + r * 128 + (off ^ ((r & 7) << 4));
                ldsm_x4(bfr[nb][0], bfr[nb][1], bfr[nb][2], bfr[nb][3], addr);
            }
            #pragma unroll
            for (int ma = 0; ma < 4; ma++)
                #pragma unroll
                for (int na = 0; na < 4; na++)
                    mma16816(acc[ma][na], af[ma],
                             bfr[na >> 1][(na & 1) * 2], bfr[na >> 1][(na & 1) * 2 + 1]);
        }
        __syncthreads();
        if (c < NCHUNK - 1) {
            stash(av, SA(buf ^ 1));
            stash(bv, SB(buf ^ 1));
            __syncthreads();
        }
    }

    // LoRA LB tile -> SMEM
    float* LBs = (float*)(smem + SM_LB);
    if (XA) {
        for (int idx = tid; idx < 8 * 128; idx += 256)
            LBs[idx] = LB[(idx >> 7) * D_ + col0 + (idx & 127)];
        __syncthreads();
    }

    // epilogue: LoRA + RoPE + store
    #pragma unroll
    for (int ma = 0; ma < 4; ma++) {
        const int mlo = row0 + wm * 64 + ma * 16 + (lane >> 2);
        const int mhi = mlo + 8;
        float xal[8], xah[8];
        if (XA) {
            #pragma unroll
            for (int r = 0; r < R_; r++) {
                xal[r] = XA[mlo * R_ + r];
                xah[r] = XA[mhi * R_ + r];
            }
        }
        const int tlo = mlo & (T_ - 1), thi = mhi & (T_ - 1);
        #pragma unroll
        for (int na = 0; na < 4; na++) {
            const int n  = col0 + wn * 32 + na * 8 + (lane & 3) * 2;
            const int nl = n - col0;
            float v0 = acc[ma][na][0], v1 = acc[ma][na][1];
            float v2 = acc[ma][na][2], v3 = acc[ma][na][3];
            if (XA) {
                float s0 = 0.f, s1 = 0.f, s2 = 0.f, s3 = 0.f;
                #pragma unroll
                for (int r = 0; r < R_; r++) {
                    float b0 = LBs[r * 128 + nl], b1 = LBs[r * 128 + nl + 1];
                    s0 += xal[r] * b0; s1 += xal[r] * b1;
                    s2 += xah[r] * b0; s3 += xah[r] * b1;
                }
                v0 += loraScale * s0; v1 += loraScale * s1;
                v2 += loraScale * s2; v3 += loraScale * s3;
            }
            if (ropeFlag) {
                const int jj = (n & 63) >> 1;
                float sn = g_sin[tlo * 32 + jj], cs = g_cos[tlo * 32 + jj];
                float e = v0, o = v1;
                v0 = e * cs - o * sn; v1 = e * sn + o * cs;
                sn = g_sin[thi * 32 + jj]; cs = g_cos[thi * 32 + jj];
                e = v2; o = v3;
                v2 = e * cs - o * sn; v3 = e * sn + o * cs;
            }
            *(float2*)&C[(size_t)mlo * D_ + n] = make_float2(v0, v1);
            *(float2*)&C[(size_t)mhi * D_ + n] = make_float2(v2, v3);
        }
    }
}

// ---------------- flash attention, fp32, causal; writes split-bf16 out --------
__global__ void __launch_bounds__(128) attn_kernel() {
    __shared__ float Ks[64][64];
    __shared__ float Vs[64][64];

    const int qb = blockIdx.x, h = blockIdx.y, b = blockIdx.z;
    const int tid = threadIdx.x;
    const int t   = qb * 128 + tid;
    const int rowbase = (b * T_ + t) * D_ + h * DH_;

    float4 qv[16];
    #pragma unroll
    for (int i = 0; i < 16; i++) {
        float4 q = *(const float4*)&g_q[rowbase + i * 4];
        q.x *= 0.125f; q.y *= 0.125f; q.z *= 0.125f; q.w *= 0.125f;
        qv[i] = q;
    }

    float4 acc[16];
    #pragma unroll
    for (int i = 0; i < 16; i++) acc[i] = make_float4(0.f, 0.f, 0.f, 0.f);
    float m_i = -1e30f, l_i = 0.f;

    const int lastTile = (qb * 128 + 127) >> 6;

    for (int kt = 0; kt <= lastTile; kt++) {
        __syncthreads();
        const int kvbase = (b * T_ + kt * 64) * D_ + h * DH_;
        for (int idx = tid; idx < 1024; idx += 128) {
            int r = idx >> 4, c = (idx & 15) * 4;
            *(float4*)&Ks[r][c] = *(const float4*)&g_k[kvbase + r * D_ + c];
            *(float4*)&Vs[r][c] = *(const float4*)&g_v[kvbase + r * D_ + c];
        }
        __syncthreads();

        const int kmax = t - kt * 64;
        if (kmax < 0) continue;
        const bool full = (kmax >= 63);

        #pragma unroll 1
        for (int cch = 0; cch < 4; cch++) {
            int j0 = cch * 16;
            if (j0 > kmax) break;
            float s[16];
            float mt = -1e30f;
            #pragma unroll
            for (int jj = 0; jj < 16; jj++) {
                int j = j0 + jj;
                const float4* kr = (const float4*)&Ks[j][0];
                float sum = 0.f;
                #pragma unroll
                for (int i = 0; i < 16; i++) {
                    float4 kk = kr[i];
                    sum += qv[i].x * kk.x + qv[i].y * kk.y
                         + qv[i].z * kk.z + qv[i].w * kk.w;
                }
                if (!full && j > kmax) sum = -1e30f;
                s[jj] = sum;
                mt = fmaxf(mt, sum);
            }
            float m_new = fmaxf(m_i, mt);
            float corr = __expf(m_i - m_new);
            l_i *= corr;
            #pragma unroll
            for (int i = 0; i < 16; i++) {
                acc[i].x *= corr; acc[i].y *= corr;
                acc[i].z *= corr; acc[i].w *= corr;
            }
            #pragma unroll
            for (int jj = 0; jj < 16; jj++) {
                float p = __expf(s[jj] - m_new);
                l_i += p;
                const float4* vr = (const float4*)&Vs[j0 + jj][0];
                #pragma unroll
                for (int i = 0; i < 16; i++) {
                    float4 vv = vr[i];
                    acc[i].x += p * vv.x; acc[i].y += p * vv.y;
                    acc[i].z += p * vv.z; acc[i].w += p * vv.w;
                }
            }
            m_i = m_new;
        }
    }

    float inv = 1.f / l_i;
    const size_t obase = (size_t)(b * T_ + t) * KTOT + h * DH_;
    #pragma unroll
    for (int i = 0; i < 16; i++) {
        float o[4] = {acc[i].x * inv, acc[i].y * inv, acc[i].z * inv, acc[i].w * inv};
        __nv_bfloat16 hh[4], ll[4];
        #pragma unroll
        for (int j = 0; j < 4; j++) {
            hh[j] = __float2bfloat16(o[j]);
            ll[j] = __float2bfloat16(o[j] - __bfloat162float(hh[j]));
        }
        size_t p = obase + i * 4;
        *(__nv_bfloat162*)&g_aocat[p]        = __nv_bfloat162(hh[0], hh[1]);
        *(__nv_bfloat162*)&g_aocat[p+2]      = __nv_bfloat162(hh[2], hh[3]);
        *(__nv_bfloat162*)&g_aocat[p+1024]   = __nv_bfloat162(hh[0], hh[1]);
        *(__nv_bfloat162*)&g_aocat[p+1026]   = __nv_bfloat162(hh[2], hh[3]);
        *(__nv_bfloat162*)&g_aocat[p+2048]   = __nv_bfloat162(ll[0], ll[1]);
        *(__nv_bfloat162*)&g_aocat[p+2050]   = __nv_bfloat162(ll[2], ll[3]);
    }
}

// ---------------- launch --------------------------------------------------------
extern "C" void kernel_launch(void* const* d_in, const int* in_sizes, int n_in,
                              void* d_out, int out_size) {
    const float* X  = (const float*)d_in[0];
    const float* wq = (const float*)d_in[1];
    const float* wk = (const float*)d_in[2];
    const float* wv = (const float*)d_in[3];
    const float* wo = (const float*)d_in[4];
    const float* Aq = (const float*)d_in[5];
    const float* Bq = (const float*)d_in[6];
    const float* Av = (const float*)d_in[7];
    const float* Bv = (const float*)d_in[8];
    float* out = (float*)d_out;

    float *qp, *kp, *vp, *xaqp, *xavp;
    __nv_bfloat16 *xcat, *aocat, *wtcat;
    cudaGetSymbolAddress((void**)&qp,   g_q);
    cudaGetSymbolAddress((void**)&kp,   g_k);
    cudaGetSymbolAddress((void**)&vp,   g_v);
    cudaGetSymbolAddress((void**)&xaqp, g_xaq);
    cudaGetSymbolAddress((void**)&xavp, g_xav);
    cudaGetSymbolAddress((void**)&xcat, g_xcat);
    cudaGetSymbolAddress((void**)&aocat, g_aocat);
    cudaGetSymbolAddress((void**)&wtcat, g_wtcat);

    cudaFuncSetAttribute(gemm_mma_kernel,
                         cudaFuncAttributeMaxDynamicSharedMemorySize, SM_TOTAL);

    sincos_kernel<<<(T_*32 + 255) / 256, 256>>>();
    lora_down_kernel<<<MTOT, 256>>>(X, Aq, Av);
    split_x_kernel<<<(MTOT * D_ / 4 + 255) / 256, 256>>>(X);
    split_wt_kernel<<<dim3(32, 32, 4), dim3(32, 8)>>>(wq, wk, wv, wo);

    dim3 gg(D_ / 128, MTOT / 128);   // (8, 64)
    gemm_mma_kernel<<<gg, 256, SM_TOTAL>>>(xcat, wtcat + 0ull*D_*KTOT, qp, xaqp, Bq, LORA_SCALE, 1);
    gemm_mma_kernel<<<gg, 256, SM_TOTAL>>>(xcat, wtcat + 1ull*D_*KTOT, kp, nullptr, nullptr, 0.f, 1);
    gemm_mma_kernel<<<gg, 256, SM_TOTAL>>>(xcat, wtcat + 2ull*D_*KTOT, vp, xavp, Bv, LORA_SCALE, 0);

    attn_kernel<<<dim3(T_ / 128, H_, B_), 128>>>();

    gemm_mma_kernel<<<gg, 256, SM_TOTAL>>>(aocat, wtcat + 3ull*D_*KTOT, out, nullptr, nullptr, 0.f, 0);
}

// round 5
// speedup vs baseline: 2.7471x; 1.8610x over previous
#include <cuda_runtime.h>
#include <cuda_bf16.h>
#include <math.h>
#include <cstdint>

#define B_   4
#define T_   2048
#define D_   1024
#define H_   16
#define DH_  64
#define R_   8
#define MTOT (B_*T_)          // 8192
#define KTOT 3072             // split-bf16 concatenated K
#define NCHUNK 48             // KTOT / 64
#define LORA_SCALE 4.0f

// ---------------- scratch (device globals: no allocation allowed) -------------
__device__ float g_xaq[MTOT*R_];
__device__ float g_xav[MTOT*R_];
__device__ float g_sin[T_*32];
__device__ float g_cos[T_*32];
__device__ __nv_bfloat16 g_xcat [MTOT*KTOT];     // [Xhi | Xhi | Xlo]
__device__ __nv_bfloat16 g_aocat[MTOT*KTOT];     // attention out, same layout
__device__ __nv_bfloat16 g_wtcat[4ull*D_*KTOT];  // per weight: rows n, [hi|lo|hi]
// head-major [b,h,t,dh] bf16 split pairs
__device__ __nv_bfloat16 g_qhi[MTOT*D_];
__device__ __nv_bfloat16 g_qlo[MTOT*D_];
__device__ __nv_bfloat16 g_khi[MTOT*D_];
__device__ __nv_bfloat16 g_klo[MTOT*D_];
__device__ __nv_bfloat16 g_vhi[MTOT*D_];
__device__ __nv_bfloat16 g_vlo[MTOT*D_];

// ---------------- warp-level MMA helpers (sm_80+, no 'a' features) ------------
__device__ __forceinline__ uint32_t smem_u32(const void* p) {
    uint32_t a;
    asm("{ .reg .u64 t; cvta.to.shared.u64 t, %1; cvt.u32.u64 %0, t; }" : "=r"(a) : "l"(p));
    return a;
}
__device__ __forceinline__ void ldsm_x4(uint32_t* r, uint32_t addr) {
    asm volatile("ldmatrix.sync.aligned.m8n8.x4.shared.b16 {%0,%1,%2,%3}, [%4];"
                 : "=r"(r[0]), "=r"(r[1]), "=r"(r[2]), "=r"(r[3]) : "r"(addr));
}
__device__ __forceinline__ void ldsm_x4_t(uint32_t* r, uint32_t addr) {
    asm volatile("ldmatrix.sync.aligned.m8n8.x4.trans.shared.b16 {%0,%1,%2,%3}, [%4];"
                 : "=r"(r[0]), "=r"(r[1]), "=r"(r[2]), "=r"(r[3]) : "r"(addr));
}
__device__ __forceinline__ void mma16816(float* d, const uint32_t* a,
                                         uint32_t b0, uint32_t b1) {
    asm volatile("mma.sync.aligned.m16n8k16.row.col.f32.bf16.bf16.f32 "
                 "{%0,%1,%2,%3}, {%4,%5,%6,%7}, {%8,%9}, {%0,%1,%2,%3};"
                 : "+f"(d[0]), "+f"(d[1]), "+f"(d[2]), "+f"(d[3])
                 : "r"(a[0]), "r"(a[1]), "r"(a[2]), "r"(a[3]), "r"(b0), "r"(b1));
}
__device__ __forceinline__ uint32_t pack_bf16x2(float e, float o) {
    uint32_t d;
    asm("cvt.rn.bf16x2.f32 %0, %1, %2;" : "=r"(d) : "f"(o), "f"(e));  // lo=e, hi=o
    return d;
}
__device__ __forceinline__ void cpa16(uint32_t dst, const void* src) {
    asm volatile("cp.async.cg.shared.global [%0], [%1], 16;" :: "r"(dst), "l"(src) : "memory");
}
#define CP_COMMIT() asm volatile("cp.async.commit_group;" ::: "memory")
#define CP_WAIT1()  asm volatile("cp.async.wait_group 1;"  ::: "memory")

// ---------------- sin/cos table -----------------------------------------------
__global__ void sincos_kernel() {
    int idx = blockIdx.x * blockDim.x + threadIdx.x;
    if (idx >= T_*32) return;
    int t = idx >> 5, j = idx & 31;
    double theta = (double)t / pow(10000.0, (double)j / 32.0);
    g_sin[idx] = (float)sin(theta);
    g_cos[idx] = (float)cos(theta);
}

// ---------------- LoRA down-projection ----------------------------------------
__global__ void lora_down_kernel(const float* __restrict__ X,
                                 const float* __restrict__ Aq,
                                 const float* __restrict__ Av) {
    int m    = blockIdx.x;
    int lane = threadIdx.x & 31;
    int w    = threadIdx.x >> 5;
    const float* x = X + m * D_;
    #pragma unroll
    for (int cc = 0; cc < 2; cc++) {
        int c = w * 2 + cc;
        const float* A = (c < 8) ? Aq : Av;
        int col = c & 7;
        float s = 0.f;
        for (int k = lane; k < D_; k += 32)
            s += x[k] * A[k * R_ + col];
        #pragma unroll
        for (int off = 16; off; off >>= 1)
            s += __shfl_down_sync(0xffffffffu, s, off);
        if (lane == 0) {
            float* XA = (c < 8) ? g_xaq : g_xav;
            XA[m * R_ + col] = s;
        }
    }
}

// ---------------- split X -> [hi|hi|lo] bf16 ----------------------------------
__global__ void split_x_kernel(const float* __restrict__ X) {
    int idx4 = blockIdx.x * blockDim.x + threadIdx.x;
    if (idx4 >= MTOT * D_ / 4) return;
    int m = idx4 >> 8;
    int k = (idx4 & 255) * 4;
    float4 x = ((const float4*)X)[idx4];
    float xs[4] = {x.x, x.y, x.z, x.w};
    __nv_bfloat16 h[4], l[4];
    #pragma unroll
    for (int i = 0; i < 4; i++) {
        h[i] = __float2bfloat16(xs[i]);
        l[i] = __float2bfloat16(xs[i] - __bfloat162float(h[i]));
    }
    size_t base = (size_t)m * KTOT + k;
    *(__nv_bfloat162*)&g_xcat[base]        = __nv_bfloat162(h[0], h[1]);
    *(__nv_bfloat162*)&g_xcat[base+2]      = __nv_bfloat162(h[2], h[3]);
    *(__nv_bfloat162*)&g_xcat[base+1024]   = __nv_bfloat162(h[0], h[1]);
    *(__nv_bfloat162*)&g_xcat[base+1026]   = __nv_bfloat162(h[2], h[3]);
    *(__nv_bfloat162*)&g_xcat[base+2048]   = __nv_bfloat162(l[0], l[1]);
    *(__nv_bfloat162*)&g_xcat[base+2050]   = __nv_bfloat162(l[2], l[3]);
}

// ---------------- transpose + split weights -> Wt[n][hi|lo|hi] ----------------
__global__ void split_wt_kernel(const float* __restrict__ W0, const float* __restrict__ W1,
                                const float* __restrict__ W2, const float* __restrict__ W3) {
    const float* Ws[4] = {W0, W1, W2, W3};
    const float* W = Ws[blockIdx.z];
    __shared__ float tile[32][33];
    int bx = blockIdx.x * 32, by = blockIdx.y * 32;
    for (int i = threadIdx.y; i < 32; i += 8)
        tile[i][threadIdx.x] = W[(size_t)(by + i) * D_ + bx + threadIdx.x];
    __syncthreads();
    __nv_bfloat16* out = g_wtcat + (size_t)blockIdx.z * D_ * KTOT;
    for (int i = threadIdx.y; i < 32; i += 8) {
        int n = bx + i, k = by + threadIdx.x;
        float x = tile[threadIdx.x][i];
        __nv_bfloat16 h = __float2bfloat16(x);
        __nv_bfloat16 l = __float2bfloat16(x - __bfloat162float(h));
        out[(size_t)n * KTOT + k]        = h;
        out[(size_t)n * KTOT + 1024 + k] = l;
        out[(size_t)n * KTOT + 2048 + k] = h;
    }
}

// ================= HMMA split-bf16 GEMM ========================================
// modes: 0 = fp32 C[m][D];  1 = Q (rope, *0.125, split);  2 = K (rope, split);
//        3 = V (split).  Split modes write head-major [b,h,t,dh] hi/lo.
#define SA(buf) ((buf) * 16384)
#define SB(buf) (32768 + (buf) * 16384)
#define SM_LB   65536
#define SM_TOTAL 69632

__global__ void __launch_bounds__(256)
gemm_mma_kernel(const __nv_bfloat16* __restrict__ Acat,
                const __nv_bfloat16* __restrict__ Bcat,
                float* __restrict__ C,
                __nv_bfloat16* __restrict__ Chi, __nv_bfloat16* __restrict__ Clo,
                const float* __restrict__ XA, const float* __restrict__ LB,
                float loraScale, int mode)
{
    extern __shared__ char smem[];
    const uint32_t sbase = smem_u32(smem);
    const int tid  = threadIdx.x;
    const int lane = tid & 31;
    const int wid  = tid >> 5;
    const int wm   = wid & 1;
    const int wn   = wid >> 1;
    const int row0 = blockIdx.y * 128, col0 = blockIdx.x * 128;

    float acc[4][4][4];
    #pragma unroll
    for (int i = 0; i < 4; i++)
        #pragma unroll
        for (int j = 0; j < 4; j++)
            #pragma unroll
            for (int r = 0; r < 4; r++) acc[i][j][r] = 0.f;

    uint4 av[4], bv[4];
    auto fetch = [&](const __nv_bfloat16* g, int r0, int kb, uint4* v) {
        #pragma unroll
        for (int i = 0; i < 4; i++) {
            int idx = i * 256 + tid;
            int r = idx >> 3, c = idx & 7;
            v[i] = *((const uint4*)(g + (size_t)(r0 + r) * KTOT + kb) + c);
        }
    };
    auto stash = [&](const uint4* v, int soff) {
        #pragma unroll
        for (int i = 0; i < 4; i++) {
            int idx = i * 256 + tid;
            int r = idx >> 3, c = idx & 7;
            uint32_t off = (uint32_t)(c * 16) ^ (uint32_t)((r & 7) << 4);
            *(uint4*)(smem + soff + r * 128 + off) = v[i];
        }
    };

    fetch(Acat, row0, 0, av);
    fetch(Bcat, col0, 0, bv);
    stash(av, SA(0));
    stash(bv, SB(0));
    __syncthreads();

    for (int c = 0; c < NCHUNK; c++) {
        const int buf = c & 1;
        if (c < NCHUNK - 1) {
            fetch(Acat, row0, (c + 1) * 64, av);
            fetch(Bcat, col0, (c + 1) * 64, bv);
        }
        const uint32_t sa = sbase + SA(buf);
        const uint32_t sb = sbase + SB(buf);
        #pragma unroll
        for (int ks = 0; ks < 4; ks++) {
            uint32_t af[4][4], bfr[2][4];
            #pragma unroll
            for (int ma = 0; ma < 4; ma++) {
                int r = wm * 64 + ma * 16 + (lane & 15);
                uint32_t off = (uint32_t)(ks * 32 + ((lane >> 4) << 4));
                ldsm_x4(af[ma], sa + r * 128 + (off ^ ((r & 7) << 4)));
            }
            #pragma unroll
            for (int nb = 0; nb < 2; nb++) {
                int r = wn * 32 + nb * 16 + ((lane >> 4) << 3) + (lane & 7);
                uint32_t off = (uint32_t)(ks * 32 + (((lane >> 3) & 1) << 4));
                ldsm_x4(bfr[nb], sb + r * 128 + (off ^ ((r & 7) << 4)));
            }
            #pragma unroll
            for (int ma = 0; ma < 4; ma++)
                #pragma unroll
                for (int na = 0; na < 4; na++)
                    mma16816(acc[ma][na], af[ma],
                             bfr[na >> 1][(na & 1) * 2], bfr[na >> 1][(na & 1) * 2 + 1]);
        }
        __syncthreads();
        if (c < NCHUNK - 1) {
            stash(av, SA(buf ^ 1));
            stash(bv, SB(buf ^ 1));
            __syncthreads();
        }
    }

    float* LBs = (float*)(smem + SM_LB);
    if (XA) {
        for (int idx = tid; idx < 8 * 128; idx += 256)
            LBs[idx] = LB[(idx >> 7) * D_ + col0 + (idx & 127)];
        __syncthreads();
    }

    #pragma unroll
    for (int ma = 0; ma < 4; ma++) {
        const int mlo = row0 + wm * 64 + ma * 16 + (lane >> 2);
        const int mhi = mlo + 8;
        float xal[8], xah[8];
        if (XA) {
            #pragma unroll
            for (int r = 0; r < R_; r++) {
                xal[r] = XA[mlo * R_ + r];
                xah[r] = XA[mhi * R_ + r];
            }
        }
        const int tlo = mlo & (T_ - 1), thi = mhi & (T_ - 1);
        #pragma unroll
        for (int na = 0; na < 4; na++) {
            const int n  = col0 + wn * 32 + na * 8 + (lane & 3) * 2;
            const int nl = n - col0;
            float v0 = acc[ma][na][0], v1 = acc[ma][na][1];
            float v2 = acc[ma][na][2], v3 = acc[ma][na][3];
            if (XA) {
                float s0 = 0.f, s1 = 0.f, s2 = 0.f, s3 = 0.f;
                #pragma unroll
                for (int r = 0; r < R_; r++) {
                    float b0 = LBs[r * 128 + nl], b1 = LBs[r * 128 + nl + 1];
                    s0 += xal[r] * b0; s1 += xal[r] * b1;
                    s2 += xah[r] * b0; s3 += xah[r] * b1;
                }
                v0 += loraScale * s0; v1 += loraScale * s1;
                v2 += loraScale * s2; v3 += loraScale * s3;
            }
            if (mode == 1 || mode == 2) {   // RoPE
                const int jj = (n & 63) >> 1;
                float sn = g_sin[tlo * 32 + jj], cs = g_cos[tlo * 32 + jj];
                float e = v0, o = v1;
                v0 = e * cs - o * sn; v1 = e * sn + o * cs;
                sn = g_sin[thi * 32 + jj]; cs = g_cos[thi * 32 + jj];
                e = v2; o = v3;
                v2 = e * cs - o * sn; v3 = e * sn + o * cs;
            }
            if (mode == 1) { v0 *= 0.125f; v1 *= 0.125f; v2 *= 0.125f; v3 *= 0.125f; }
            if (mode == 0) {
                *(float2*)&C[(size_t)mlo * D_ + n] = make_float2(v0, v1);
                *(float2*)&C[(size_t)mhi * D_ + n] = make_float2(v2, v3);
            } else {
                const int bq = mlo >> 11, hh = n >> 6, dd = n & 63;
                size_t olo = ((size_t)(bq * H_ + hh) * T_ + tlo) * DH_ + dd;
                size_t ohi = ((size_t)(bq * H_ + hh) * T_ + thi) * DH_ + dd;
                __nv_bfloat16 h0 = __float2bfloat16(v0), h1 = __float2bfloat16(v1);
                __nv_bfloat16 h2 = __float2bfloat16(v2), h3 = __float2bfloat16(v3);
                *(__nv_bfloat162*)&Chi[olo] = __nv_bfloat162(h0, h1);
                *(__nv_bfloat162*)&Chi[ohi] = __nv_bfloat162(h2, h3);
                *(__nv_bfloat162*)&Clo[olo] = __nv_bfloat162(
                    __float2bfloat16(v0 - __bfloat162float(h0)),
                    __float2bfloat16(v1 - __bfloat162float(h1)));
                *(__nv_bfloat162*)&Clo[ohi] = __nv_bfloat162(
                    __float2bfloat16(v2 - __bfloat162float(h2)),
                    __float2bfloat16(v3 - __bfloat162float(h3)));
            }
        }
    }
}

// ================= tensor-core flash attention =================================
// CTA: 128 queries x 1 head; 8 warps x 16 rows. Split-bf16 S and PV (3 terms).
#define AQ_HI 0
#define AQ_LO 16384
#define ATILE(buf) (32768 + (buf) * 32768)   // KHI | KLO | VHI | VLO (8KB each)
#define A_SMEM 98304

__global__ void __launch_bounds__(256)
attn_mma_kernel() {
    extern __shared__ char smem[];
    const uint32_t sbs = smem_u32(smem);
    const int tid = threadIdx.x, lane = tid & 31, w = tid >> 5;
    const int qb = gridDim.x - 1 - blockIdx.x;      // big tiles first
    const int h = blockIdx.y, b = blockIdx.z;
    const int bh = b * H_ + h;
    const __nv_bfloat16* qhi = g_qhi + (size_t)bh * T_ * DH_;
    const __nv_bfloat16* qlo = g_qlo + (size_t)bh * T_ * DH_;
    const __nv_bfloat16* khi = g_khi + (size_t)bh * T_ * DH_;
    const __nv_bfloat16* klo = g_klo + (size_t)bh * T_ * DH_;
    const __nv_bfloat16* vhi = g_vhi + (size_t)bh * T_ * DH_;
    const __nv_bfloat16* vlo = g_vlo + (size_t)bh * T_ * DH_;

    // stage Q tile (128 rows x 64 bf16, hi+lo) with SW128 swizzle
    {
        const __nv_bfloat16* sq = qhi + (size_t)(qb * 128) * DH_;
        const __nv_bfloat16* sl = qlo + (size_t)(qb * 128) * DH_;
        #pragma unroll
        for (int i = 0; i < 4; i++) {
            int idx = i * 256 + tid;
            int r = idx >> 3, c = idx & 7;
            uint32_t off = r * 128 + (((uint32_t)(c * 16)) ^ ((r & 7) << 4));
            *(uint4*)(smem + AQ_HI + off) = *((const uint4*)(sq + r * DH_) + c);
            *(uint4*)(smem + AQ_LO + off) = *((const uint4*)(sl + r * DH_) + c);
        }
    }
    __syncthreads();

    // Q fragments: [split][kstep][4]
    uint32_t qf[2][4][4];
    #pragma unroll
    for (int s = 0; s < 2; s++) {
        const uint32_t base = sbs + (s ? AQ_LO : AQ_HI);
        #pragma unroll
        for (int ks = 0; ks < 4; ks++) {
            int tsel = lane >> 3;
            int r = 16 * w + (lane & 7) + (tsel & 1) * 8;
            uint32_t off = ((uint32_t)(ks * 32 + ((tsel >> 1) & 1) * 16)) ^ ((r & 7) << 4);
            ldsm_x4(qf[s][ks], base + r * 128 + off);
        }
    }

    auto prefetch = [&](int c, int buf) {
        const int k0 = c * 64;
        const uint32_t tb = sbs + ATILE(buf);
        #pragma unroll
        for (int i = 0; i < 2; i++) {
            int idx = i * 256 + tid;
            int r = idx >> 3, cc = idx & 7;
            uint32_t off = r * 128 + (((uint32_t)(cc * 16)) ^ ((r & 7) << 4));
            const size_t g = (size_t)(k0 + r) * DH_ + cc * 8;
            cpa16(tb + off,         khi + g);
            cpa16(tb + 8192 + off,  klo + g);
            cpa16(tb + 16384 + off, vhi + g);
            cpa16(tb + 24576 + off, vlo + g);
        }
    };

    const int nch = 2 * qb + 2;
    prefetch(0, 0); CP_COMMIT();

    float o[8][4];
    #pragma unroll
    for (int j = 0; j < 8; j++)
        #pragma unroll
        for (int r = 0; r < 4; r++) o[j][r] = 0.f;
    float m0 = -1e30f, m1 = -1e30f, l0 = 0.f, l1 = 0.f;

    const int wrow0 = qb * 128 + 16 * w;
    const int r0 = wrow0 + (lane >> 2), r1 = r0 + 8;

    for (int c = 0; c < nch; c++) {
        const int buf = c & 1;
        if (c + 1 < nch) prefetch(c + 1, buf ^ 1);
        CP_COMMIT();
        CP_WAIT1();
        __syncthreads();

        const int k0 = c * 64;
        if (k0 <= wrow0 + 15) {
            const uint32_t skh = sbs + ATILE(buf);
            const uint32_t skl = skh + 8192;
            const uint32_t svh = skh + 16384;
            const uint32_t svl = skh + 24576;

            float s[8][4];
            #pragma unroll
            for (int j = 0; j < 8; j++)
                #pragma unroll
                for (int r = 0; r < 4; r++) s[j][r] = 0.f;

            #pragma unroll
            for (int ks = 0; ks < 4; ks++) {
                #pragma unroll
                for (int jp = 0; jp < 4; jp++) {
                    uint32_t bh_[4], bl_[4];
                    int rr = jp * 16 + ((lane >> 4) << 3) + (lane & 7);
                    uint32_t off = ((uint32_t)(ks * 32 + (((lane >> 3) & 1) << 4)))
                                   ^ ((rr & 7) << 4);
                    ldsm_x4(bh_, skh + rr * 128 + off);
                    ldsm_x4(bl_, skl + rr * 128 + off);
                    mma16816(s[2*jp],   qf[0][ks], bh_[0], bh_[1]);
                    mma16816(s[2*jp],   qf[0][ks], bl_[0], bl_[1]);
                    mma16816(s[2*jp],   qf[1][ks], bh_[0], bh_[1]);
                    mma16816(s[2*jp+1], qf[0][ks], bh_[2], bh_[3]);
                    mma16816(s[2*jp+1], qf[0][ks], bl_[2], bl_[3]);
                    mma16816(s[2*jp+1], qf[1][ks], bh_[2], bh_[3]);
                }
            }

            if (k0 + 63 > wrow0) {   // causal mask needed
                #pragma unroll
                for (int j = 0; j < 8; j++) {
                    int col = k0 + 8 * j + 2 * (lane & 3);
                    if (col     > r0) s[j][0] = -1e30f;
                    if (col + 1 > r0) s[j][1] = -1e30f;
                    if (col     > r1) s[j][2] = -1e30f;
                    if (col + 1 > r1) s[j][3] = -1e30f;
                }
            }

            float mx0 = -1e30f, mx1 = -1e30f;
            #pragma unroll
            for (int j = 0; j < 8; j++) {
                mx0 = fmaxf(mx0, fmaxf(s[j][0], s[j][1]));
                mx1 = fmaxf(mx1, fmaxf(s[j][2], s[j][3]));
            }
            mx0 = fmaxf(mx0, __shfl_xor_sync(0xffffffffu, mx0, 1));
            mx0 = fmaxf(mx0, __shfl_xor_sync(0xffffffffu, mx0, 2));
            mx1 = fmaxf(mx1, __shfl_xor_sync(0xffffffffu, mx1, 1));
            mx1 = fmaxf(mx1, __shfl_xor_sync(0xffffffffu, mx1, 2));
            float mn0 = fmaxf(m0, mx0), mn1 = fmaxf(m1, mx1);
            float cr0 = __expf(m0 - mn0), cr1 = __expf(m1 - mn1);
            l0 *= cr0; l1 *= cr1;
            #pragma unroll
            for (int j = 0; j < 8; j++) {
                o[j][0] *= cr0; o[j][1] *= cr0;
                o[j][2] *= cr1; o[j][3] *= cr1;
            }
            m0 = mn0; m1 = mn1;

            uint32_t ph[8][2], pl[8][2];
            #pragma unroll
            for (int j = 0; j < 8; j++) {
                float p0 = __expf(s[j][0] - mn0), p1 = __expf(s[j][1] - mn0);
                float p2 = __expf(s[j][2] - mn1), p3 = __expf(s[j][3] - mn1);
                l0 += p0 + p1; l1 += p2 + p3;
                __nv_bfloat16 b0 = __float2bfloat16(p0), b1 = __float2bfloat16(p1);
                __nv_bfloat16 b2 = __float2bfloat16(p2), b3 = __float2bfloat16(p3);
                ph[j][0] = pack_bf16x2(__bfloat162float(b0), __bfloat162float(b1));
                ph[j][1] = pack_bf16x2(__bfloat162float(b2), __bfloat162float(b3));
                pl[j][0] = pack_bf16x2(p0 - __bfloat162float(b0), p1 - __bfloat162float(b1));
                pl[j][1] = pack_bf16x2(p2 - __bfloat162float(b2), p3 - __bfloat162float(b3));
            }

            #pragma unroll
            for (int ks = 0; ks < 4; ks++) {
                uint32_t ahi[4] = {ph[2*ks][0], ph[2*ks][1], ph[2*ks+1][0], ph[2*ks+1][1]};
                uint32_t alo[4] = {pl[2*ks][0], pl[2*ks][1], pl[2*ks+1][0], pl[2*ks+1][1]};
                #pragma unroll
                for (int jp = 0; jp < 4; jp++) {
                    uint32_t vh_[4], vl_[4];
                    int tsel = lane >> 3;
                    int key = 16 * ks + (tsel & 1) * 8 + (lane & 7);
                    uint32_t off = ((uint32_t)((16 * jp + ((tsel >> 1) & 1) * 8) * 2))
                                   ^ ((key & 7) << 4);
                    ldsm_x4_t(vh_, svh + key * 128 + off);
                    ldsm_x4_t(vl_, svl + key * 128 + off);
                    mma16816(o[2*jp],   ahi, vh_[0], vh_[1]);
                    mma16816(o[2*jp],   ahi, vl_[0], vl_[1]);
                    mma16816(o[2*jp],   alo, vh_[0], vh_[1]);
                    mma16816(o[2*jp+1], ahi, vh_[2], vh_[3]);
                    mma16816(o[2*jp+1], ahi, vl_[2], vl_[3]);
                    mma16816(o[2*jp+1], alo, vh_[2], vh_[3]);
                }
            }
        }
        __syncthreads();
    }

    l0 += __shfl_xor_sync(0xffffffffu, l0, 1);
    l0 += __shfl_xor_sync(0xffffffffu, l0, 2);
    l1 += __shfl_xor_sync(0xffffffffu, l1, 1);
    l1 += __shfl_xor_sync(0xffffffffu, l1, 2);
    const float i0 = 1.f / l0, i1 = 1.f / l1;

    const int tok0 = b * T_ + r0, tok1 = b * T_ + r1;
    #pragma unroll
    for (int j = 0; j < 8; j++) {
        const int n = h * DH_ + 8 * j + 2 * (lane & 3);
        float v0 = o[j][0] * i0, v1 = o[j][1] * i0;
        float v2 = o[j][2] * i1, v3 = o[j][3] * i1;
        __nv_bfloat16 h0 = __float2bfloat16(v0), h1 = __float2bfloat16(v1);
        __nv_bfloat16 h2 = __float2bfloat16(v2), h3 = __float2bfloat16(v3);
        __nv_bfloat162 hi0(h0, h1), hi1(h2, h3);
        __nv_bfloat162 lo0(__float2bfloat16(v0 - __bfloat162float(h0)),
                           __float2bfloat16(v1 - __bfloat162float(h1)));
        __nv_bfloat162 lo1(__float2bfloat16(v2 - __bfloat162float(h2)),
                           __float2bfloat16(v3 - __bfloat162float(h3)));
        size_t p0 = (size_t)tok0 * KTOT + n;
        size_t p1 = (size_t)tok1 * KTOT + n;
        *(__nv_bfloat162*)&g_aocat[p0]        = hi0;
        *(__nv_bfloat162*)&g_aocat[p0 + 1024] = hi0;
        *(__nv_bfloat162*)&g_aocat[p0 + 2048] = lo0;
        *(__nv_bfloat162*)&g_aocat[p1]        = hi1;
        *(__nv_bfloat162*)&g_aocat[p1 + 1024] = hi1;
        *(__nv_bfloat162*)&g_aocat[p1 + 2048] = lo1;
    }
}

// ---------------- launch --------------------------------------------------------
extern "C" void kernel_launch(void* const* d_in, const int* in_sizes, int n_in,
                              void* d_out, int out_size) {
    const float* X  = (const float*)d_in[0];
    const float* wq = (const float*)d_in[1];
    const float* wk = (const float*)d_in[2];
    const float* wv = (const float*)d_in[3];
    const float* wo = (const float*)d_in[4];
    const float* Aq = (const float*)d_in[5];
    const float* Bq = (const float*)d_in[6];
    const float* Av = (const float*)d_in[7];
    const float* Bv = (const float*)d_in[8];
    float* out = (float*)d_out;

    float *xaqp, *xavp;
    __nv_bfloat16 *xcat, *aocat, *wtcat, *qhi, *qlo, *khi, *klo, *vhi, *vlo;
    cudaGetSymbolAddress((void**)&xaqp, g_xaq);
    cudaGetSymbolAddress((void**)&xavp, g_xav);
    cudaGetSymbolAddress((void**)&xcat, g_xcat);
    cudaGetSymbolAddress((void**)&aocat, g_aocat);
    cudaGetSymbolAddress((void**)&wtcat, g_wtcat);
    cudaGetSymbolAddress((void**)&qhi, g_qhi);
    cudaGetSymbolAddress((void**)&qlo, g_qlo);
    cudaGetSymbolAddress((void**)&khi, g_khi);
    cudaGetSymbolAddress((void**)&klo, g_klo);
    cudaGetSymbolAddress((void**)&vhi, g_vhi);
    cudaGetSymbolAddress((void**)&vlo, g_vlo);

    cudaFuncSetAttribute(gemm_mma_kernel,
                         cudaFuncAttributeMaxDynamicSharedMemorySize, SM_TOTAL);
    cudaFuncSetAttribute(attn_mma_kernel,
                         cudaFuncAttributeMaxDynamicSharedMemorySize, A_SMEM);

    sincos_kernel<<<(T_*32 + 255) / 256, 256>>>();
    lora_down_kernel<<<MTOT, 256>>>(X, Aq, Av);
    split_x_kernel<<<(MTOT * D_ / 4 + 255) / 256, 256>>>(X);
    split_wt_kernel<<<dim3(32, 32, 4), dim3(32, 8)>>>(wq, wk, wv, wo);

    dim3 gg(D_ / 128, MTOT / 128);
    gemm_mma_kernel<<<gg, 256, SM_TOTAL>>>(xcat, wtcat + 0ull*D_*KTOT, nullptr,
                                           qhi, qlo, xaqp, Bq, LORA_SCALE, 1);
    gemm_mma_kernel<<<gg, 256, SM_TOTAL>>>(xcat, wtcat + 1ull*D_*KTOT, nullptr,
                                           khi, klo, nullptr, nullptr, 0.f, 2);
    gemm_mma_kernel<<<gg, 256, SM_TOTAL>>>(xcat, wtcat + 2ull*D_*KTOT, nullptr,
                                           vhi, vlo, xavp, Bv, LORA_SCALE, 3);

    attn_mma_kernel<<<dim3(T_ / 128, H_, B_), 256, A_SMEM>>>();

    gemm_mma_kernel<<<gg, 256, SM_TOTAL>>>(aocat, wtcat + 3ull*D_*KTOT, out,
                                           nullptr, nullptr, nullptr, nullptr, 0.f, 0);
}

// round 6
// speedup vs baseline: 3.2417x; 1.1800x over previous
#include <cuda_runtime.h>
#include <cuda_bf16.h>
#include <math.h>
#include <cstdint>

#define B_   4
#define T_   2048
#define D_   1024
#define H_   16
#define DH_  64
#define R_   8
#define MTOT (B_*T_)          // 8192
#define KTOT 3072             // split-bf16 concatenated K
#define NCHUNK 48             // KTOT / 64
#define LORA_SCALE 4.0f

// ---------------- scratch (device globals: no allocation allowed) -------------
__device__ float g_xaq[MTOT*R_];
__device__ float g_xav[MTOT*R_];
__device__ float g_sin[T_*32];
__device__ float g_cos[T_*32];
__device__ __nv_bfloat16 g_xcat [MTOT*KTOT];       // [Xhi | Xhi | Xlo]
__device__ __nv_bfloat16 g_aocat[MTOT*KTOT];       // attention out, same layout
__device__ __nv_bfloat16 g_wtqkv[3072ull*KTOT];    // rows n: [wq|wk|wv] cols, k = [hi|lo|hi]
__device__ __nv_bfloat16 g_wto  [(size_t)D_*KTOT];
// head-major [b,h,t,dh] bf16 split pairs
__device__ __nv_bfloat16 g_qhi[MTOT*D_];
__device__ __nv_bfloat16 g_qlo[MTOT*D_];
__device__ __nv_bfloat16 g_khi[MTOT*D_];
__device__ __nv_bfloat16 g_klo[MTOT*D_];
__device__ __nv_bfloat16 g_vhi[MTOT*D_];
__device__ __nv_bfloat16 g_vlo[MTOT*D_];

// ---------------- warp-level MMA helpers ---------------------------------------
__device__ __forceinline__ uint32_t smem_u32(const void* p) {
    uint32_t a;
    asm("{ .reg .u64 t; cvta.to.shared.u64 t, %1; cvt.u32.u64 %0, t; }" : "=r"(a) : "l"(p));
    return a;
}
__device__ __forceinline__ void ldsm_x4(uint32_t* r, uint32_t addr) {
    asm volatile("ldmatrix.sync.aligned.m8n8.x4.shared.b16 {%0,%1,%2,%3}, [%4];"
                 : "=r"(r[0]), "=r"(r[1]), "=r"(r[2]), "=r"(r[3]) : "r"(addr));
}
__device__ __forceinline__ void ldsm_x4_t(uint32_t* r, uint32_t addr) {
    asm volatile("ldmatrix.sync.aligned.m8n8.x4.trans.shared.b16 {%0,%1,%2,%3}, [%4];"
                 : "=r"(r[0]), "=r"(r[1]), "=r"(r[2]), "=r"(r[3]) : "r"(addr));
}
__device__ __forceinline__ void mma16816(float* d, const uint32_t* a,
                                         uint32_t b0, uint32_t b1) {
    asm volatile("mma.sync.aligned.m16n8k16.row.col.f32.bf16.bf16.f32 "
                 "{%0,%1,%2,%3}, {%4,%5,%6,%7}, {%8,%9}, {%0,%1,%2,%3};"
                 : "+f"(d[0]), "+f"(d[1]), "+f"(d[2]), "+f"(d[3])
                 : "r"(a[0]), "r"(a[1]), "r"(a[2]), "r"(a[3]), "r"(b0), "r"(b1));
}
__device__ __forceinline__ uint32_t pack_bf16x2(float e, float o) {
    uint32_t d;
    asm("cvt.rn.bf16x2.f32 %0, %1, %2;" : "=r"(d) : "f"(o), "f"(e));
    return d;
}
__device__ __forceinline__ void cpa16(uint32_t dst, const void* src) {
    asm volatile("cp.async.cg.shared.global [%0], [%1], 16;" :: "r"(dst), "l"(src) : "memory");
}
#define CP_COMMIT() asm volatile("cp.async.commit_group;" ::: "memory")
#define CP_WAIT1()  asm volatile("cp.async.wait_group 1;"  ::: "memory")

// ---------------- sin/cos table -----------------------------------------------
__global__ void sincos_kernel() {
    int idx = blockIdx.x * blockDim.x + threadIdx.x;
    if (idx >= T_*32) return;
    int t = idx >> 5, j = idx & 31;
    double theta = (double)t / pow(10000.0, (double)j / 32.0);
    g_sin[idx] = (float)sin(theta);
    g_cos[idx] = (float)cos(theta);
}

// ---------------- LoRA down-projection ----------------------------------------
__global__ void lora_down_kernel(const float* __restrict__ X,
                                 const float* __restrict__ Aq,
                                 const float* __restrict__ Av) {
    int m    = blockIdx.x;
    int lane = threadIdx.x & 31;
    int w    = threadIdx.x >> 5;
    const float* x = X + m * D_;
    #pragma unroll
    for (int cc = 0; cc < 2; cc++) {
        int c = w * 2 + cc;
        const float* A = (c < 8) ? Aq : Av;
        int col = c & 7;
        float s = 0.f;
        for (int k = lane; k < D_; k += 32)
            s += x[k] * A[k * R_ + col];
        #pragma unroll
        for (int off = 16; off; off >>= 1)
            s += __shfl_down_sync(0xffffffffu, s, off);
        if (lane == 0) {
            float* XA = (c < 8) ? g_xaq : g_xav;
            XA[m * R_ + col] = s;
        }
    }
}

// ---------------- split X -> [hi|hi|lo] bf16 ----------------------------------
__global__ void split_x_kernel(const float* __restrict__ X) {
    int idx4 = blockIdx.x * blockDim.x + threadIdx.x;
    if (idx4 >= MTOT * D_ / 4) return;
    int m = idx4 >> 8;
    int k = (idx4 & 255) * 4;
    float4 x = ((const float4*)X)[idx4];
    float xs[4] = {x.x, x.y, x.z, x.w};
    __nv_bfloat16 h[4], l[4];
    #pragma unroll
    for (int i = 0; i < 4; i++) {
        h[i] = __float2bfloat16(xs[i]);
        l[i] = __float2bfloat16(xs[i] - __bfloat162float(h[i]));
    }
    size_t base = (size_t)m * KTOT + k;
    *(__nv_bfloat162*)&g_xcat[base]        = __nv_bfloat162(h[0], h[1]);
    *(__nv_bfloat162*)&g_xcat[base+2]      = __nv_bfloat162(h[2], h[3]);
    *(__nv_bfloat162*)&g_xcat[base+1024]   = __nv_bfloat162(h[0], h[1]);
    *(__nv_bfloat162*)&g_xcat[base+1026]   = __nv_bfloat162(h[2], h[3]);
    *(__nv_bfloat162*)&g_xcat[base+2048]   = __nv_bfloat162(l[0], l[1]);
    *(__nv_bfloat162*)&g_xcat[base+2050]   = __nv_bfloat162(l[2], l[3]);
}

// ---------------- transpose + split weights ------------------------------------
__global__ void split_wt_kernel(const float* __restrict__ W0, const float* __restrict__ W1,
                                const float* __restrict__ W2, const float* __restrict__ W3) {
    const float* Ws[4] = {W0, W1, W2, W3};
    const float* W = Ws[blockIdx.z];
    __shared__ float tile[32][33];
    int bx = blockIdx.x * 32, by = blockIdx.y * 32;
    for (int i = threadIdx.y; i < 32; i += 8)
        tile[i][threadIdx.x] = W[(size_t)(by + i) * D_ + bx + threadIdx.x];
    __syncthreads();
    for (int i = threadIdx.y; i < 32; i += 8) {
        int n = bx + i, k = by + threadIdx.x;
        float x = tile[threadIdx.x][i];
        __nv_bfloat16 h = __float2bfloat16(x);
        __nv_bfloat16 l = __float2bfloat16(x - __bfloat162float(h));
        __nv_bfloat16* out = (blockIdx.z < 3)
            ? g_wtqkv + (size_t)(blockIdx.z * 1024 + n) * KTOT
            : g_wto   + (size_t)n * KTOT;
        out[k]        = h;
        out[1024 + k] = l;
        out[2048 + k] = h;
    }
}

// ================= fused HMMA split-bf16 GEMM (128x256 tile, 512 thr) ==========
// qkv=1: Bcat rows are [wq|wk|wv] cols; per-CTA region decides epilogue.
// qkv=0: fp32 C (wo projection, N=1024).
#define GA(b)  ((b) * 16384)             // A: 128 rows x 128B
#define GB(b)  (32768 + (b) * 32768)     // B: 256 rows x 128B
#define G_LB   98304                     // 8 x 256 floats
#define G_TOTAL 106496

__global__ void __launch_bounds__(512)
gemm_fused_kernel(const __nv_bfloat16* __restrict__ Acat,
                  const __nv_bfloat16* __restrict__ Bcat,
                  float* __restrict__ C, int qkv,
                  const float* __restrict__ Bq, const float* __restrict__ Bv)
{
    extern __shared__ char smem[];
    const uint32_t sbase = smem_u32(smem);
    const int tid  = threadIdx.x;
    const int lane = tid & 31;
    const int wid  = tid >> 5;          // 0..15
    const int wm   = wid & 1;           // 2 x 64 rows
    const int wn   = wid >> 1;          // 8 x 32 cols
    const int row0 = blockIdx.y * 128, col0 = blockIdx.x * 256;

    float acc[4][4][4];
    #pragma unroll
    for (int i = 0; i < 4; i++)
        #pragma unroll
        for (int j = 0; j < 4; j++)
            #pragma unroll
            for (int r = 0; r < 4; r++) acc[i][j][r] = 0.f;

    auto prefetch = [&](int c, int buf) {
        const int kb = c * 64;
        #pragma unroll
        for (int i = 0; i < 2; i++) {        // A: 1024 x 16B
            int idx = i * 512 + tid;
            int r = idx >> 3, cc = idx & 7;
            uint32_t off = r * 128 + (((uint32_t)(cc * 16)) ^ ((r & 7) << 4));
            cpa16(sbase + GA(buf) + off, Acat + (size_t)(row0 + r) * KTOT + kb + cc * 8);
        }
        #pragma unroll
        for (int i = 0; i < 4; i++) {        // B: 2048 x 16B
            int idx = i * 512 + tid;
            int r = idx >> 3, cc = idx & 7;
            uint32_t off = r * 128 + (((uint32_t)(cc * 16)) ^ ((r & 7) << 4));
            cpa16(sbase + GB(buf) + off, Bcat + (size_t)(col0 + r) * KTOT + kb + cc * 8);
        }
    };

    prefetch(0, 0); CP_COMMIT();

    for (int c = 0; c < NCHUNK; c++) {
        const int buf = c & 1;
        __syncthreads();                         // buf^1 free for overwrite
        if (c + 1 < NCHUNK) { prefetch(c + 1, buf ^ 1); CP_COMMIT(); }
        CP_WAIT1();
        __syncthreads();                         // chunk c visible to all
        const uint32_t sa = sbase + GA(buf);
        const uint32_t sb = sbase + GB(buf);
        #pragma unroll
        for (int ks = 0; ks < 4; ks++) {
            uint32_t af[4][4], bfr[2][4];
            #pragma unroll
            for (int ma = 0; ma < 4; ma++) {
                int r = wm * 64 + ma * 16 + (lane & 15);
                uint32_t off = (uint32_t)(ks * 32 + ((lane >> 4) << 4));
                ldsm_x4(af[ma], sa + r * 128 + (off ^ ((r & 7) << 4)));
            }
            #pragma unroll
            for (int nb = 0; nb < 2; nb++) {
                int r = wn * 32 + nb * 16 + ((lane >> 4) << 3) + (lane & 7);
                uint32_t off = (uint32_t)(ks * 32 + (((lane >> 3) & 1) << 4));
                ldsm_x4(bfr[nb], sb + r * 128 + (off ^ ((r & 7) << 4)));
            }
            #pragma unroll
            for (int ma = 0; ma < 4; ma++)
                #pragma unroll
                for (int na = 0; na < 4; na++)
                    mma16816(acc[ma][na], af[ma],
                             bfr[na >> 1][(na & 1) * 2], bfr[na >> 1][(na & 1) * 2 + 1]);
        }
    }
    __syncthreads();

    // region: 0=Q, 1=K, 2=V (qkv mode); LoRA for Q/V
    const int region = qkv ? (col0 >> 10) : 3;
    const float* XA = (region == 0) ? g_xaq : (region == 2) ? g_xav : nullptr;
    float* LBs = (float*)(smem + G_LB);
    if (qkv && region != 1) {
        const float* Bsrc = (region == 0) ? Bq : Bv;
        const int cbase = col0 & 1023;
        #pragma unroll
        for (int i = 0; i < 4; i++) {
            int idx = i * 512 + tid;
            LBs[idx] = Bsrc[(idx >> 8) * D_ + cbase + (idx & 255)];
        }
        __syncthreads();
    }

    #pragma unroll
    for (int ma = 0; ma < 4; ma++) {
        const int mlo = row0 + wm * 64 + ma * 16 + (lane >> 2);
        const int mhi = mlo + 8;
        float xal[8], xah[8];
        if (XA) {
            #pragma unroll
            for (int r = 0; r < R_; r++) {
                xal[r] = XA[mlo * R_ + r];
                xah[r] = XA[mhi * R_ + r];
            }
        }
        const int tlo = mlo & (T_ - 1), thi = mhi & (T_ - 1);
        #pragma unroll
        for (int na = 0; na < 4; na++) {
            const int n  = col0 + wn * 32 + na * 8 + (lane & 3) * 2;
            const int nl = n - col0;
            float v0 = acc[ma][na][0], v1 = acc[ma][na][1];
            float v2 = acc[ma][na][2], v3 = acc[ma][na][3];
            if (XA) {
                float s0 = 0.f, s1 = 0.f, s2 = 0.f, s3 = 0.f;
                #pragma unroll
                for (int r = 0; r < R_; r++) {
                    float b0 = LBs[r * 256 + nl], b1 = LBs[r * 256 + nl + 1];
                    s0 += xal[r] * b0; s1 += xal[r] * b1;
                    s2 += xah[r] * b0; s3 += xah[r] * b1;
                }
                v0 += LORA_SCALE * s0; v1 += LORA_SCALE * s1;
                v2 += LORA_SCALE * s2; v3 += LORA_SCALE * s3;
            }
            if (region <= 1) {              // RoPE for Q and K
                const int jj = (n & 63) >> 1;
                float sn = g_sin[tlo * 32 + jj], cs = g_cos[tlo * 32 + jj];
                float e = v0, o = v1;
                v0 = e * cs - o * sn; v1 = e * sn + o * cs;
                sn = g_sin[thi * 32 + jj]; cs = g_cos[thi * 32 + jj];
                e = v2; o = v3;
                v2 = e * cs - o * sn; v3 = e * sn + o * cs;
            }
            if (region == 0) { v0 *= 0.125f; v1 *= 0.125f; v2 *= 0.125f; v3 *= 0.125f; }
            if (!qkv) {
                *(float2*)&C[(size_t)mlo * D_ + n] = make_float2(v0, v1);
                *(float2*)&C[(size_t)mhi * D_ + n] = make_float2(v2, v3);
            } else {
                __nv_bfloat16* Chi = (region == 0) ? g_qhi : (region == 1) ? g_khi : g_vhi;
                __nv_bfloat16* Clo = (region == 0) ? g_qlo : (region == 1) ? g_klo : g_vlo;
                const int bq = mlo >> 11, hh = (n & 1023) >> 6, dd = n & 63;
                size_t olo = ((size_t)(bq * H_ + hh) * T_ + tlo) * DH_ + dd;
                size_t ohi = ((size_t)(bq * H_ + hh) * T_ + thi) * DH_ + dd;
                __nv_bfloat16 h0 = __float2bfloat16(v0), h1 = __float2bfloat16(v1);
                __nv_bfloat16 h2 = __float2bfloat16(v2), h3 = __float2bfloat16(v3);
                *(__nv_bfloat162*)&Chi[olo] = __nv_bfloat162(h0, h1);
                *(__nv_bfloat162*)&Chi[ohi] = __nv_bfloat162(h2, h3);
                *(__nv_bfloat162*)&Clo[olo] = __nv_bfloat162(
                    __float2bfloat16(v0 - __bfloat162float(h0)),
                    __float2bfloat16(v1 - __bfloat162float(h1)));
                *(__nv_bfloat162*)&Clo[ohi] = __nv_bfloat162(
                    __float2bfloat16(v2 - __bfloat162float(h2)),
                    __float2bfloat16(v3 - __bfloat162float(h3)));
            }
        }
    }
}

// ================= tensor-core flash attention =================================
#define AQ_HI 0
#define AQ_LO 16384
#define ATILE(buf) (32768 + (buf) * 32768)   // KHI | KLO | VHI | VLO (8KB each)
#define A_SMEM 98304

__global__ void __launch_bounds__(256)
attn_mma_kernel() {
    extern __shared__ char smem[];
    const uint32_t sbs = smem_u32(smem);
    const int tid = threadIdx.x, lane = tid & 31, w = tid >> 5;
    const int qb = gridDim.x - 1 - blockIdx.x;
    const int h = blockIdx.y, b = blockIdx.z;
    const int bh = b * H_ + h;
    const __nv_bfloat16* qhi = g_qhi + (size_t)bh * T_ * DH_;
    const __nv_bfloat16* qlo = g_qlo + (size_t)bh * T_ * DH_;
    const __nv_bfloat16* khi = g_khi + (size_t)bh * T_ * DH_;
    const __nv_bfloat16* klo = g_klo + (size_t)bh * T_ * DH_;
    const __nv_bfloat16* vhi = g_vhi + (size_t)bh * T_ * DH_;
    const __nv_bfloat16* vlo = g_vlo + (size_t)bh * T_ * DH_;

    {
        const __nv_bfloat16* sq = qhi + (size_t)(qb * 128) * DH_;
        const __nv_bfloat16* sl = qlo + (size_t)(qb * 128) * DH_;
        #pragma unroll
        for (int i = 0; i < 4; i++) {
            int idx = i * 256 + tid;
            int r = idx >> 3, c = idx & 7;
            uint32_t off = r * 128 + (((uint32_t)(c * 16)) ^ ((r & 7) << 4));
            *(uint4*)(smem + AQ_HI + off) = *((const uint4*)(sq + r * DH_) + c);
            *(uint4*)(smem + AQ_LO + off) = *((const uint4*)(sl + r * DH_) + c);
        }
    }
    __syncthreads();

    uint32_t qf[2][4][4];
    #pragma unroll
    for (int s = 0; s < 2; s++) {
        const uint32_t base = sbs + (s ? AQ_LO : AQ_HI);
        #pragma unroll
        for (int ks = 0; ks < 4; ks++) {
            int tsel = lane >> 3;
            int r = 16 * w + (lane & 7) + (tsel & 1) * 8;
            uint32_t off = ((uint32_t)(ks * 32 + ((tsel >> 1) & 1) * 16)) ^ ((r & 7) << 4);
            ldsm_x4(qf[s][ks], base + r * 128 + off);
        }
    }

    auto prefetch = [&](int c, int buf) {
        const int k0 = c * 64;
        const uint32_t tb = sbs + ATILE(buf);
        #pragma unroll
        for (int i = 0; i < 2; i++) {
            int idx = i * 256 + tid;
            int r = idx >> 3, cc = idx & 7;
            uint32_t off = r * 128 + (((uint32_t)(cc * 16)) ^ ((r & 7) << 4));
            const size_t g = (size_t)(k0 + r) * DH_ + cc * 8;
            cpa16(tb + off,         khi + g);
            cpa16(tb + 8192 + off,  klo + g);
            cpa16(tb + 16384 + off, vhi + g);
            cpa16(tb + 24576 + off, vlo + g);
        }
    };

    const int nch = 2 * qb + 2;
    prefetch(0, 0); CP_COMMIT();

    float o[8][4];
    #pragma unroll
    for (int j = 0; j < 8; j++)
        #pragma unroll
        for (int r = 0; r < 4; r++) o[j][r] = 0.f;
    float m0 = -1e30f, m1 = -1e30f, l0 = 0.f, l1 = 0.f;

    const int wrow0 = qb * 128 + 16 * w;
    const int r0 = wrow0 + (lane >> 2), r1 = r0 + 8;

    for (int c = 0; c < nch; c++) {
        const int buf = c & 1;
        if (c + 1 < nch) prefetch(c + 1, buf ^ 1);
        CP_COMMIT();
        CP_WAIT1();
        __syncthreads();

        const int k0 = c * 64;
        if (k0 <= wrow0 + 15) {
            const uint32_t skh = sbs + ATILE(buf);
            const uint32_t skl = skh + 8192;
            const uint32_t svh = skh + 16384;
            const uint32_t svl = skh + 24576;

            float s[8][4];
            #pragma unroll
            for (int j = 0; j < 8; j++)
                #pragma unroll
                for (int r = 0; r < 4; r++) s[j][r] = 0.f;

            #pragma unroll
            for (int ks = 0; ks < 4; ks++) {
                #pragma unroll
                for (int jp = 0; jp < 4; jp++) {
                    uint32_t bh_[4], bl_[4];
                    int rr = jp * 16 + ((lane >> 4) << 3) + (lane & 7);
                    uint32_t off = ((uint32_t)(ks * 32 + (((lane >> 3) & 1) << 4)))
                                   ^ ((rr & 7) << 4);
                    ldsm_x4(bh_, skh + rr * 128 + off);
                    ldsm_x4(bl_, skl + rr * 128 + off);
                    mma16816(s[2*jp],   qf[0][ks], bh_[0], bh_[1]);
                    mma16816(s[2*jp],   qf[0][ks], bl_[0], bl_[1]);
                    mma16816(s[2*jp],   qf[1][ks], bh_[0], bh_[1]);
                    mma16816(s[2*jp+1], qf[0][ks], bh_[2], bh_[3]);
                    mma16816(s[2*jp+1], qf[0][ks], bl_[2], bl_[3]);
                    mma16816(s[2*jp+1], qf[1][ks], bh_[2], bh_[3]);
                }
            }

            if (k0 + 63 > wrow0) {
                #pragma unroll
                for (int j = 0; j < 8; j++) {
                    int col = k0 + 8 * j + 2 * (lane & 3);
                    if (col     > r0) s[j][0] = -1e30f;
                    if (col + 1 > r0) s[j][1] = -1e30f;
                    if (col     > r1) s[j][2] = -1e30f;
                    if (col + 1 > r1) s[j][3] = -1e30f;
                }
            }

            float mx0 = -1e30f, mx1 = -1e30f;
            #pragma unroll
            for (int j = 0; j < 8; j++) {
                mx0 = fmaxf(mx0, fmaxf(s[j][0], s[j][1]));
                mx1 = fmaxf(mx1, fmaxf(s[j][2], s[j][3]));
            }
            mx0 = fmaxf(mx0, __shfl_xor_sync(0xffffffffu, mx0, 1));
            mx0 = fmaxf(mx0, __shfl_xor_sync(0xffffffffu, mx0, 2));
            mx1 = fmaxf(mx1, __shfl_xor_sync(0xffffffffu, mx1, 1));
            mx1 = fmaxf(mx1, __shfl_xor_sync(0xffffffffu, mx1, 2));
            float mn0 = fmaxf(m0, mx0), mn1 = fmaxf(m1, mx1);
            float cr0 = __expf(m0 - mn0), cr1 = __expf(m1 - mn1);
            l0 *= cr0; l1 *= cr1;
            #pragma unroll
            for (int j = 0; j < 8; j++) {
                o[j][0] *= cr0; o[j][1] *= cr0;
                o[j][2] *= cr1; o[j][3] *= cr1;
            }
            m0 = mn0; m1 = mn1;

            uint32_t ph[8][2], pl[8][2];
            #pragma unroll
            for (int j = 0; j < 8; j++) {
                float p0 = __expf(s[j][0] - mn0), p1 = __expf(s[j][1] - mn0);
                float p2 = __expf(s[j][2] - mn1), p3 = __expf(s[j][3] - mn1);
                l0 += p0 + p1; l1 += p2 + p3;
                __nv_bfloat16 b0 = __float2bfloat16(p0), b1 = __float2bfloat16(p1);
                __nv_bfloat16 b2 = __float2bfloat16(p2), b3 = __float2bfloat16(p3);
                ph[j][0] = pack_bf16x2(__bfloat162float(b0), __bfloat162float(b1));
                ph[j][1] = pack_bf16x2(__bfloat162float(b2), __bfloat162float(b3));
                pl[j][0] = pack_bf16x2(p0 - __bfloat162float(b0), p1 - __bfloat162float(b1));
                pl[j][1] = pack_bf16x2(p2 - __bfloat162float(b2), p3 - __bfloat162float(b3));
            }

            #pragma unroll
            for (int ks = 0; ks < 4; ks++) {
                uint32_t ahi[4] = {ph[2*ks][0], ph[2*ks][1], ph[2*ks+1][0], ph[2*ks+1][1]};
                uint32_t alo[4] = {pl[2*ks][0], pl[2*ks][1], pl[2*ks+1][0], pl[2*ks+1][1]};
                #pragma unroll
                for (int jp = 0; jp < 4; jp++) {
                    uint32_t vh_[4], vl_[4];
                    int tsel = lane >> 3;
                    int key = 16 * ks + (tsel & 1) * 8 + (lane & 7);
                    uint32_t off = ((uint32_t)((16 * jp + ((tsel >> 1) & 1) * 8) * 2))
                                   ^ ((key & 7) << 4);
                    ldsm_x4_t(vh_, svh + key * 128 + off);
                    ldsm_x4_t(vl_, svl + key * 128 + off);
                    mma16816(o[2*jp],   ahi, vh_[0], vh_[1]);
                    mma16816(o[2*jp],   ahi, vl_[0], vl_[1]);
                    mma16816(o[2*jp],   alo, vh_[0], vh_[1]);
                    mma16816(o[2*jp+1], ahi, vh_[2], vh_[3]);
                    mma16816(o[2*jp+1], ahi, vl_[2], vl_[3]);
                    mma16816(o[2*jp+1], alo, vh_[2], vh_[3]);
                }
            }
        }
        __syncthreads();
    }

    l0 += __shfl_xor_sync(0xffffffffu, l0, 1);
    l0 += __shfl_xor_sync(0xffffffffu, l0, 2);
    l1 += __shfl_xor_sync(0xffffffffu, l1, 1);
    l1 += __shfl_xor_sync(0xffffffffu, l1, 2);
    const float i0 = 1.f / l0, i1 = 1.f / l1;

    const int tok0 = b * T_ + r0, tok1 = b * T_ + r1;
    #pragma unroll
    for (int j = 0; j < 8; j++) {
        const int n = h * DH_ + 8 * j + 2 * (lane & 3);
        float v0 = o[j][0] * i0, v1 = o[j][1] * i0;
        float v2 = o[j][2] * i1, v3 = o[j][3] * i1;
        __nv_bfloat16 h0 = __float2bfloat16(v0), h1 = __float2bfloat16(v1);
        __nv_bfloat16 h2 = __float2bfloat16(v2), h3 = __float2bfloat16(v3);
        __nv_bfloat162 hi0(h0, h1), hi1(h2, h3);
        __nv_bfloat162 lo0(__float2bfloat16(v0 - __bfloat162float(h0)),
                           __float2bfloat16(v1 - __bfloat162float(h1)));
        __nv_bfloat162 lo1(__float2bfloat16(v2 - __bfloat162float(h2)),
                           __float2bfloat16(v3 - __bfloat162float(h3)));
        size_t p0 = (size_t)tok0 * KTOT + n;
        size_t p1 = (size_t)tok1 * KTOT + n;
        *(__nv_bfloat162*)&g_aocat[p0]        = hi0;
        *(__nv_bfloat162*)&g_aocat[p0 + 1024] = hi0;
        *(__nv_bfloat162*)&g_aocat[p0 + 2048] = lo0;
        *(__nv_bfloat162*)&g_aocat[p1]        = hi1;
        *(__nv_bfloat162*)&g_aocat[p1 + 1024] = hi1;
        *(__nv_bfloat162*)&g_aocat[p1 + 2048] = lo1;
    }
}

// ---------------- launch --------------------------------------------------------
extern "C" void kernel_launch(void* const* d_in, const int* in_sizes, int n_in,
                              void* d_out, int out_size) {
    const float* X  = (const float*)d_in[0];
    const float* wq = (const float*)d_in[1];
    const float* wk = (const float*)d_in[2];
    const float* wv = (const float*)d_in[3];
    const float* wo = (const float*)d_in[4];
    const float* Aq = (const float*)d_in[5];
    const float* Bq = (const float*)d_in[6];
    const float* Av = (const float*)d_in[7];
    const float* Bv = (const float*)d_in[8];
    float* out = (float*)d_out;

    __nv_bfloat16 *xcat, *aocat, *wtqkv, *wto;
    cudaGetSymbolAddress((void**)&xcat,  g_xcat);
    cudaGetSymbolAddress((void**)&aocat, g_aocat);
    cudaGetSymbolAddress((void**)&wtqkv, g_wtqkv);
    cudaGetSymbolAddress((void**)&wto,   g_wto);

    cudaFuncSetAttribute(gemm_fused_kernel,
                         cudaFuncAttributeMaxDynamicSharedMemorySize, G_TOTAL);
    cudaFuncSetAttribute(attn_mma_kernel,
                         cudaFuncAttributeMaxDynamicSharedMemorySize, A_SMEM);

    sincos_kernel<<<(T_*32 + 255) / 256, 256>>>();
    lora_down_kernel<<<MTOT, 256>>>(X, Aq, Av);
    split_x_kernel<<<(MTOT * D_ / 4 + 255) / 256, 256>>>(X);
    split_wt_kernel<<<dim3(32, 32, 4), dim3(32, 8)>>>(wq, wk, wv, wo);

    gemm_fused_kernel<<<dim3(12, 64), 512, G_TOTAL>>>(xcat, wtqkv, nullptr, 1, Bq, Bv);

    attn_mma_kernel<<<dim3(T_ / 128, H_, B_), 256, A_SMEM>>>();

    gemm_fused_kernel<<<dim3(4, 64), 512, G_TOTAL>>>(aocat, wto, out, 0, nullptr, nullptr);
}

// round 8
// speedup vs baseline: 3.4292x; 1.0578x over previous
#include <cuda_runtime.h>
#include <cuda_bf16.h>
#include <math.h>
#include <cstdint>

#define B_   4
#define T_   2048
#define D_   1024
#define H_   16
#define DH_  64
#define R_   8
#define MTOT (B_*T_)          // 8192
#define KTOT 3072             // split-bf16 concatenated K
#define NCHUNK 48             // KTOT / 64
#define LORA_SCALE 4.0f

// ---------------- scratch (device globals: no allocation allowed) -------------
__device__ float g_xaq[MTOT*R_];
__device__ float g_xav[MTOT*R_];
__device__ float g_sin[T_*32];
__device__ float g_cos[T_*32];
__device__ __nv_bfloat16 g_xcat [MTOT*KTOT];       // [Xhi | Xhi | Xlo]
__device__ __nv_bfloat16 g_aocat[MTOT*KTOT];       // attention out, same layout
__device__ __nv_bfloat16 g_wtqkv[3072ull*KTOT];    // rows n: [wq|wk|wv] cols, k = [hi|lo|hi]
__device__ __nv_bfloat16 g_wto  [(size_t)D_*KTOT];
// head-major [b,h,t,dh] bf16 split pairs
__device__ __nv_bfloat16 g_qhi[MTOT*D_];
__device__ __nv_bfloat16 g_qlo[MTOT*D_];
__device__ __nv_bfloat16 g_khi[MTOT*D_];
__device__ __nv_bfloat16 g_klo[MTOT*D_];
__device__ __nv_bfloat16 g_vhi[MTOT*D_];
__device__ __nv_bfloat16 g_vlo[MTOT*D_];

// ---------------- warp-level MMA helpers ---------------------------------------
__device__ __forceinline__ uint32_t smem_u32(const void* p) {
    uint32_t a;
    asm("{ .reg .u64 t; cvta.to.shared.u64 t, %1; cvt.u32.u64 %0, t; }" : "=r"(a) : "l"(p));
    return a;
}
__device__ __forceinline__ void ldsm_x4(uint32_t* r, uint32_t addr) {
    asm volatile("ldmatrix.sync.aligned.m8n8.x4.shared.b16 {%0,%1,%2,%3}, [%4];"
                 : "=r"(r[0]), "=r"(r[1]), "=r"(r[2]), "=r"(r[3]) : "r"(addr));
}
__device__ __forceinline__ void ldsm_x4_t(uint32_t* r, uint32_t addr) {
    asm volatile("ldmatrix.sync.aligned.m8n8.x4.trans.shared.b16 {%0,%1,%2,%3}, [%4];"
                 : "=r"(r[0]), "=r"(r[1]), "=r"(r[2]), "=r"(r[3]) : "r"(addr));
}
__device__ __forceinline__ void mma16816(float* d, const uint32_t* a,
                                         uint32_t b0, uint32_t b1) {
    asm volatile("mma.sync.aligned.m16n8k16.row.col.f32.bf16.bf16.f32 "
                 "{%0,%1,%2,%3}, {%4,%5,%6,%7}, {%8,%9}, {%0,%1,%2,%3};"
                 : "+f"(d[0]), "+f"(d[1]), "+f"(d[2]), "+f"(d[3])
                 : "r"(a[0]), "r"(a[1]), "r"(a[2]), "r"(a[3]), "r"(b0), "r"(b1));
}
__device__ __forceinline__ uint32_t pack_bf16x2(float e, float o) {
    uint32_t d;
    asm("cvt.rn.bf16x2.f32 %0, %1, %2;" : "=r"(d) : "f"(o), "f"(e));
    return d;
}
__device__ __forceinline__ void cpa16(uint32_t dst, const void* src) {
    asm volatile("cp.async.cg.shared.global [%0], [%1], 16;" :: "r"(dst), "l"(src) : "memory");
}
#define CP_COMMIT() asm volatile("cp.async.commit_group;" ::: "memory")
#define CP_WAIT1()  asm volatile("cp.async.wait_group 1;"  ::: "memory")
#define CP_WAIT0()  asm volatile("cp.async.wait_group 0;"  ::: "memory")

// ---------------- sin/cos table -----------------------------------------------
__global__ void sincos_kernel() {
    int idx = blockIdx.x * blockDim.x + threadIdx.x;
    if (idx >= T_*32) return;
    int t = idx >> 5, j = idx & 31;
    double theta = (double)t / pow(10000.0, (double)j / 32.0);
    g_sin[idx] = (float)sin(theta);
    g_cos[idx] = (float)cos(theta);
}

// ---------------- LoRA down-projection ----------------------------------------
__global__ void lora_down_kernel(const float* __restrict__ X,
                                 const float* __restrict__ Aq,
                                 const float* __restrict__ Av) {
    int m    = blockIdx.x;
    int lane = threadIdx.x & 31;
    int w    = threadIdx.x >> 5;
    const float* x = X + m * D_;
    #pragma unroll
    for (int cc = 0; cc < 2; cc++) {
        int c = w * 2 + cc;
        const float* A = (c < 8) ? Aq : Av;
        int col = c & 7;
        float s = 0.f;
        for (int k = lane; k < D_; k += 32)
            s += x[k] * A[k * R_ + col];
        #pragma unroll
        for (int off = 16; off; off >>= 1)
            s += __shfl_down_sync(0xffffffffu, s, off);
        if (lane == 0) {
            float* XA = (c < 8) ? g_xaq : g_xav;
            XA[m * R_ + col] = s;
        }
    }
}

// ---------------- split X -> [hi|hi|lo] bf16 ----------------------------------
__global__ void split_x_kernel(const float* __restrict__ X) {
    int idx4 = blockIdx.x * blockDim.x + threadIdx.x;
    if (idx4 >= MTOT * D_ / 4) return;
    int m = idx4 >> 8;
    int k = (idx4 & 255) * 4;
    float4 x = ((const float4*)X)[idx4];
    float xs[4] = {x.x, x.y, x.z, x.w};
    __nv_bfloat16 h[4], l[4];
    #pragma unroll
    for (int i = 0; i < 4; i++) {
        h[i] = __float2bfloat16(xs[i]);
        l[i] = __float2bfloat16(xs[i] - __bfloat162float(h[i]));
    }
    size_t base = (size_t)m * KTOT + k;
    *(__nv_bfloat162*)&g_xcat[base]        = __nv_bfloat162(h[0], h[1]);
    *(__nv_bfloat162*)&g_xcat[base+2]      = __nv_bfloat162(h[2], h[3]);
    *(__nv_bfloat162*)&g_xcat[base+1024]   = __nv_bfloat162(h[0], h[1]);
    *(__nv_bfloat162*)&g_xcat[base+1026]   = __nv_bfloat162(h[2], h[3]);
    *(__nv_bfloat162*)&g_xcat[base+2048]   = __nv_bfloat162(l[0], l[1]);
    *(__nv_bfloat162*)&g_xcat[base+2050]   = __nv_bfloat162(l[2], l[3]);
}

// ---------------- transpose + split weights ------------------------------------
__global__ void split_wt_kernel(const float* __restrict__ W0, const float* __restrict__ W1,
                                const float* __restrict__ W2, const float* __restrict__ W3) {
    const float* Ws[4] = {W0, W1, W2, W3};
    const float* W = Ws[blockIdx.z];
    __shared__ float tile[32][33];
    int bx = blockIdx.x * 32, by = blockIdx.y * 32;
    for (int i = threadIdx.y; i < 32; i += 8)
        tile[i][threadIdx.x] = W[(size_t)(by + i) * D_ + bx + threadIdx.x];
    __syncthreads();
    for (int i = threadIdx.y; i < 32; i += 8) {
        int n = bx + i, k = by + threadIdx.x;
        float x = tile[threadIdx.x][i];
        __nv_bfloat16 h = __float2bfloat16(x);
        __nv_bfloat16 l = __float2bfloat16(x - __bfloat162float(h));
        __nv_bfloat16* out = (blockIdx.z < 3)
            ? g_wtqkv + (size_t)(blockIdx.z * 1024 + n) * KTOT
            : g_wto   + (size_t)n * KTOT;
        out[k]        = h;
        out[1024 + k] = l;
        out[2048 + k] = h;
    }
}

// ================= fused HMMA split-bf16 GEMM (128x256 tile, 512 thr) ==========
// 3-stage cp.async ring, single sync per chunk.
#define GSTG   49152                    // per stage: A 16K + B 32K
#define GA(s)  ((s) * GSTG)
#define GB(s)  ((s) * GSTG + 16384)
#define G_LB   147456                   // 8 x 256 floats
#define G_TOTAL 155648

__global__ void __launch_bounds__(512)
gemm_fused_kernel(const __nv_bfloat16* __restrict__ Acat,
                  const __nv_bfloat16* __restrict__ Bcat,
                  float* __restrict__ C, int qkv,
                  const float* __restrict__ Bq, const float* __restrict__ Bv)
{
    extern __shared__ char smem[];
    const uint32_t sbase = smem_u32(smem);
    const int tid  = threadIdx.x;
    const int lane = tid & 31;
    const int wid  = tid >> 5;          // 0..15
    const int wm   = wid & 1;           // 2 x 64 rows
    const int wn   = wid >> 1;          // 8 x 32 cols
    const int row0 = blockIdx.y * 128, col0 = blockIdx.x * 256;

    float acc[4][4][4];
    #pragma unroll
    for (int i = 0; i < 4; i++)
        #pragma unroll
        for (int j = 0; j < 4; j++)
            #pragma unroll
            for (int r = 0; r < 4; r++) acc[i][j][r] = 0.f;

    auto prefetch = [&](int c, int stg) {
        const int kb = c * 64;
        #pragma unroll
        for (int i = 0; i < 2; i++) {        // A: 1024 x 16B
            int idx = i * 512 + tid;
            int r = idx >> 3, cc = idx & 7;
            uint32_t off = r * 128 + (((uint32_t)(cc * 16)) ^ ((r & 7) << 4));
            cpa16(sbase + GA(stg) + off, Acat + (size_t)(row0 + r) * KTOT + kb + cc * 8);
        }
        #pragma unroll
        for (int i = 0; i < 4; i++) {        // B: 2048 x 16B
            int idx = i * 512 + tid;
            int r = idx >> 3, cc = idx & 7;
            uint32_t off = r * 128 + (((uint32_t)(cc * 16)) ^ ((r & 7) << 4));
            cpa16(sbase + GB(stg) + off, Bcat + (size_t)(col0 + r) * KTOT + kb + cc * 8);
        }
    };

    prefetch(0, 0); CP_COMMIT();
    prefetch(1, 1); CP_COMMIT();

    int sc = 0, s2 = 2;                      // compute stage, prefetch stage
    for (int c = 0; c < NCHUNK; c++) {
        CP_WAIT1();                          // chunk c landed (c+1 may be in flight)
        __syncthreads();                     // visible to all; stage s2 free
        if (c + 2 < NCHUNK) prefetch(c + 2, s2);
        CP_COMMIT();                         // always commit (tail: empty groups)
        const uint32_t sa = sbase + GA(sc);
        const uint32_t sb = sbase + GB(sc);
        #pragma unroll
        for (int ks = 0; ks < 4; ks++) {
            uint32_t af[4][4], bfr[2][4];
            #pragma unroll
            for (int ma = 0; ma < 4; ma++) {
                int r = wm * 64 + ma * 16 + (lane & 15);
                uint32_t off = (uint32_t)(ks * 32 + ((lane >> 4) << 4));
                ldsm_x4(af[ma], sa + r * 128 + (off ^ ((r & 7) << 4)));
            }
            #pragma unroll
            for (int nb = 0; nb < 2; nb++) {
                int r = wn * 32 + nb * 16 + ((lane >> 4) << 3) + (lane & 7);
                uint32_t off = (uint32_t)(ks * 32 + (((lane >> 3) & 1) << 4));
                ldsm_x4(bfr[nb], sb + r * 128 + (off ^ ((r & 7) << 4)));
            }
            #pragma unroll
            for (int ma = 0; ma < 4; ma++)
                #pragma unroll
                for (int na = 0; na < 4; na++)
                    mma16816(acc[ma][na], af[ma],
                             bfr[na >> 1][(na & 1) * 2], bfr[na >> 1][(na & 1) * 2 + 1]);
        }
        sc = (sc == 2) ? 0 : sc + 1;
        s2 = (s2 == 2) ? 0 : s2 + 1;
    }
    __syncthreads();

    // region: 0=Q, 1=K, 2=V (qkv mode); LoRA for Q/V
    const int region = qkv ? (col0 >> 10) : 3;
    const float* XA = (region == 0) ? g_xaq : (region == 2) ? g_xav : nullptr;
    float* LBs = (float*)(smem + G_LB);
    if (qkv && region != 1) {
        const float* Bsrc = (region == 0) ? Bq : Bv;
        const int cbase = col0 & 1023;
        #pragma unroll
        for (int i = 0; i < 4; i++) {
            int idx = i * 512 + tid;
            LBs[idx] = Bsrc[(idx >> 8) * D_ + cbase + (idx & 255)];
        }
        __syncthreads();
    }

    #pragma unroll
    for (int ma = 0; ma < 4; ma++) {
        const int mlo = row0 + wm * 64 + ma * 16 + (lane >> 2);
        const int mhi = mlo + 8;
        float xal[8], xah[8];
        if (XA) {
            #pragma unroll
            for (int r = 0; r < R_; r++) {
                xal[r] = XA[mlo * R_ + r];
                xah[r] = XA[mhi * R_ + r];
            }
        }
        const int tlo = mlo & (T_ - 1), thi = mhi & (T_ - 1);
        #pragma unroll
        for (int na = 0; na < 4; na++) {
            const int n  = col0 + wn * 32 + na * 8 + (lane & 3) * 2;
            const int nl = n - col0;
            float v0 = acc[ma][na][0], v1 = acc[ma][na][1];
            float v2 = acc[ma][na][2], v3 = acc[ma][na][3];
            if (XA) {
                float s0 = 0.f, s1 = 0.f, s2_ = 0.f, s3 = 0.f;
                #pragma unroll
                for (int r = 0; r < R_; r++) {
                    float b0 = LBs[r * 256 + nl], b1 = LBs[r * 256 + nl + 1];
                    s0 += xal[r] * b0; s1 += xal[r] * b1;
                    s2_ += xah[r] * b0; s3 += xah[r] * b1;
                }
                v0 += LORA_SCALE * s0; v1 += LORA_SCALE * s1;
                v2 += LORA_SCALE * s2_; v3 += LORA_SCALE * s3;
            }
            if (region <= 1) {              // RoPE for Q and K
                const int jj = (n & 63) >> 1;
                float sn = g_sin[tlo * 32 + jj], cs = g_cos[tlo * 32 + jj];
                float e = v0, o = v1;
                v0 = e * cs - o * sn; v1 = e * sn + o * cs;
                sn = g_sin[thi * 32 + jj]; cs = g_cos[thi * 32 + jj];
                e = v2; o = v3;
                v2 = e * cs - o * sn; v3 = e * sn + o * cs;
            }
            if (region == 0) { v0 *= 0.125f; v1 *= 0.125f; v2 *= 0.125f; v3 *= 0.125f; }
            if (!qkv) {
                *(float2*)&C[(size_t)mlo * D_ + n] = make_float2(v0, v1);
                *(float2*)&C[(size_t)mhi * D_ + n] = make_float2(v2, v3);
            } else {
                __nv_bfloat16* Chi = (region == 0) ? g_qhi : (region == 1) ? g_khi : g_vhi;
                __nv_bfloat16* Clo = (region == 0) ? g_qlo : (region == 1) ? g_klo : g_vlo;
                const int bq = mlo >> 11, hh = (n & 1023) >> 6, dd = n & 63;
                size_t olo = ((size_t)(bq * H_ + hh) * T_ + tlo) * DH_ + dd;
                size_t ohi = ((size_t)(bq * H_ + hh) * T_ + thi) * DH_ + dd;
                __nv_bfloat16 h0 = __float2bfloat16(v0), h1 = __float2bfloat16(v1);
                __nv_bfloat16 h2 = __float2bfloat16(v2), h3 = __float2bfloat16(v3);
                *(__nv_bfloat162*)&Chi[olo] = __nv_bfloat162(h0, h1);
                *(__nv_bfloat162*)&Chi[ohi] = __nv_bfloat162(h2, h3);
                *(__nv_bfloat162*)&Clo[olo] = __nv_bfloat162(
                    __float2bfloat16(v0 - __bfloat162float(h0)),
                    __float2bfloat16(v1 - __bfloat162float(h1)));
                *(__nv_bfloat162*)&Clo[ohi] = __nv_bfloat162(
                    __float2bfloat16(v2 - __bfloat162float(h2)),
                    __float2bfloat16(v3 - __bfloat162float(h3)));
            }
        }
    }
}

// ================= tensor-core flash attention =================================
// 2-stage, single sync per chunk. PV: 3-term split (p_hi, p_lo vs v_hi, v_lo),
// l accumulated from exact fp32 p — the validated 2.3e-5 configuration.
#define AQ_HI 0
#define AQ_LO 16384
#define ATILE(buf) (32768 + (buf) * 32768)   // KHI | KLO | VHI | VLO (8KB each)
#define A_SMEM 98304

__global__ void __launch_bounds__(256)
attn_mma_kernel() {
    extern __shared__ char smem[];
    const uint32_t sbs = smem_u32(smem);
    const int tid = threadIdx.x, lane = tid & 31, w = tid >> 5;
    const int qb = gridDim.x - 1 - blockIdx.x;
    const int h = blockIdx.y, b = blockIdx.z;
    const int bh = b * H_ + h;
    const __nv_bfloat16* qhi = g_qhi + (size_t)bh * T_ * DH_;
    const __nv_bfloat16* qlo = g_qlo + (size_t)bh * T_ * DH_;
    const __nv_bfloat16* khi = g_khi + (size_t)bh * T_ * DH_;
    const __nv_bfloat16* klo = g_klo + (size_t)bh * T_ * DH_;
    const __nv_bfloat16* vhi = g_vhi + (size_t)bh * T_ * DH_;
    const __nv_bfloat16* vlo = g_vlo + (size_t)bh * T_ * DH_;

    {
        const __nv_bfloat16* sq = qhi + (size_t)(qb * 128) * DH_;
        const __nv_bfloat16* sl = qlo + (size_t)(qb * 128) * DH_;
        #pragma unroll
        for (int i = 0; i < 4; i++) {
            int idx = i * 256 + tid;
            int r = idx >> 3, c = idx & 7;
            uint32_t off = r * 128 + (((uint32_t)(c * 16)) ^ ((r & 7) << 4));
            *(uint4*)(smem + AQ_HI + off) = *((const uint4*)(sq + r * DH_) + c);
            *(uint4*)(smem + AQ_LO + off) = *((const uint4*)(sl + r * DH_) + c);
        }
    }
    __syncthreads();

    uint32_t qf[2][4][4];
    #pragma unroll
    for (int s = 0; s < 2; s++) {
        const uint32_t base = sbs + (s ? AQ_LO : AQ_HI);
        #pragma unroll
        for (int ks = 0; ks < 4; ks++) {
            int tsel = lane >> 3;
            int r = 16 * w + (lane & 7) + (tsel & 1) * 8;
            uint32_t off = ((uint32_t)(ks * 32 + ((tsel >> 1) & 1) * 16)) ^ ((r & 7) << 4);
            ldsm_x4(qf[s][ks], base + r * 128 + off);
        }
    }

    auto prefetch = [&](int c, int buf) {
        const int k0 = c * 64;
        const uint32_t tb = sbs + ATILE(buf);
        #pragma unroll
        for (int i = 0; i < 2; i++) {
            int idx = i * 256 + tid;
            int r = idx >> 3, cc = idx & 7;
            uint32_t off = r * 128 + (((uint32_t)(cc * 16)) ^ ((r & 7) << 4));
            const size_t g = (size_t)(k0 + r) * DH_ + cc * 8;
            cpa16(tb + off,         khi + g);
            cpa16(tb + 8192 + off,  klo + g);
            cpa16(tb + 16384 + off, vhi + g);
            cpa16(tb + 24576 + off, vlo + g);
        }
    };

    const int nch = 2 * qb + 2;
    prefetch(0, 0); CP_COMMIT();

    float o[8][4];
    #pragma unroll
    for (int j = 0; j < 8; j++)
        #pragma unroll
        for (int r = 0; r < 4; r++) o[j][r] = 0.f;
    float m0 = -1e30f, m1 = -1e30f, l0 = 0.f, l1 = 0.f;

    const int wrow0 = qb * 128 + 16 * w;
    const int r0 = wrow0 + (lane >> 2), r1 = r0 + 8;

    for (int c = 0; c < nch; c++) {
        const int buf = c & 1;
        CP_WAIT0();                          // chunk c landed
        __syncthreads();                     // visible; other buf free
        if (c + 1 < nch) { prefetch(c + 1, buf ^ 1); CP_COMMIT(); }

        const int k0 = c * 64;
        if (k0 <= wrow0 + 15) {
            const uint32_t skh = sbs + ATILE(buf);
            const uint32_t skl = skh + 8192;
            const uint32_t svh = skh + 16384;
            const uint32_t svl = skh + 24576;

            float s[8][4];
            #pragma unroll
            for (int j = 0; j < 8; j++)
                #pragma unroll
                for (int r = 0; r < 4; r++) s[j][r] = 0.f;

            #pragma unroll
            for (int ks = 0; ks < 4; ks++) {
                #pragma unroll
                for (int jp = 0; jp < 4; jp++) {
                    uint32_t bh_[4], bl_[4];
                    int rr = jp * 16 + ((lane >> 4) << 3) + (lane & 7);
                    uint32_t off = ((uint32_t)(ks * 32 + (((lane >> 3) & 1) << 4)))
                                   ^ ((rr & 7) << 4);
                    ldsm_x4(bh_, skh + rr * 128 + off);
                    ldsm_x4(bl_, skl + rr * 128 + off);
                    mma16816(s[2*jp],   qf[0][ks], bh_[0], bh_[1]);
                    mma16816(s[2*jp],   qf[0][ks], bl_[0], bl_[1]);
                    mma16816(s[2*jp],   qf[1][ks], bh_[0], bh_[1]);
                    mma16816(s[2*jp+1], qf[0][ks], bh_[2], bh_[3]);
                    mma16816(s[2*jp+1], qf[0][ks], bl_[2], bl_[3]);
                    mma16816(s[2*jp+1], qf[1][ks], bh_[2], bh_[3]);
                }
            }

            if (k0 + 63 > wrow0) {
                #pragma unroll
                for (int j = 0; j < 8; j++) {
                    int col = k0 + 8 * j + 2 * (lane & 3);
                    if (col     > r0) s[j][0] = -1e30f;
                    if (col + 1 > r0) s[j][1] = -1e30f;
                    if (col     > r1) s[j][2] = -1e30f;
                    if (col + 1 > r1) s[j][3] = -1e30f;
                }
            }

            float mx0 = -1e30f, mx1 = -1e30f;
            #pragma unroll
            for (int j = 0; j < 8; j++) {
                mx0 = fmaxf(mx0, fmaxf(s[j][0], s[j][1]));
                mx1 = fmaxf(mx1, fmaxf(s[j][2], s[j][3]));
            }
            mx0 = fmaxf(mx0, __shfl_xor_sync(0xffffffffu, mx0, 1));
            mx0 = fmaxf(mx0, __shfl_xor_sync(0xffffffffu, mx0, 2));
            mx1 = fmaxf(mx1, __shfl_xor_sync(0xffffffffu, mx1, 1));
            mx1 = fmaxf(mx1, __shfl_xor_sync(0xffffffffu, mx1, 2));
            float mn0 = fmaxf(m0, mx0), mn1 = fmaxf(m1, mx1);
            float cr0 = __expf(m0 - mn0), cr1 = __expf(m1 - mn1);
            l0 *= cr0; l1 *= cr1;
            #pragma unroll
            for (int j = 0; j < 8; j++) {
                o[j][0] *= cr0; o[j][1] *= cr0;
                o[j][2] *= cr1; o[j][3] *= cr1;
            }
            m0 = mn0; m1 = mn1;

            uint32_t ph[8][2], pl[8][2];
            #pragma unroll
            for (int j = 0; j < 8; j++) {
                float p0 = __expf(s[j][0] - mn0), p1 = __expf(s[j][1] - mn0);
                float p2 = __expf(s[j][2] - mn1), p3 = __expf(s[j][3] - mn1);
                l0 += p0 + p1; l1 += p2 + p3;          // exact fp32 denominator
                __nv_bfloat16 b0 = __float2bfloat16(p0), b1 = __float2bfloat16(p1);
                __nv_bfloat16 b2 = __float2bfloat16(p2), b3 = __float2bfloat16(p3);
                ph[j][0] = pack_bf16x2(__bfloat162float(b0), __bfloat162float(b1));
                ph[j][1] = pack_bf16x2(__bfloat162float(b2), __bfloat162float(b3));
                pl[j][0] = pack_bf16x2(p0 - __bfloat162float(b0), p1 - __bfloat162float(b1));
                pl[j][1] = pack_bf16x2(p2 - __bfloat162float(b2), p3 - __bfloat162float(b3));
            }

            #pragma unroll
            for (int ks = 0; ks < 4; ks++) {
                uint32_t ahi[4] = {ph[2*ks][0], ph[2*ks][1], ph[2*ks+1][0], ph[2*ks+1][1]};
                uint32_t alo[4] = {pl[2*ks][0], pl[2*ks][1], pl[2*ks+1][0], pl[2*ks+1][1]};
                #pragma unroll
                for (int jp = 0; jp < 4; jp++) {
                    uint32_t vh_[4], vl_[4];
                    int tsel = lane >> 3;
                    int key = 16 * ks + (tsel & 1) * 8 + (lane & 7);
                    uint32_t off = ((uint32_t)((16 * jp + ((tsel >> 1) & 1) * 8) * 2))
                                   ^ ((key & 7) << 4);
                    ldsm_x4_t(vh_, svh + key * 128 + off);
                    ldsm_x4_t(vl_, svl + key * 128 + off);
                    mma16816(o[2*jp],   ahi, vh_[0], vh_[1]);
                    mma16816(o[2*jp],   ahi, vl_[0], vl_[1]);
                    mma16816(o[2*jp],   alo, vh_[0], vh_[1]);
                    mma16816(o[2*jp+1], ahi, vh_[2], vh_[3]);
                    mma16816(o[2*jp+1], ahi, vl_[2], vl_[3]);
                    mma16816(o[2*jp+1], alo, vh_[2], vh_[3]);
                }
            }
        }
    }

    l0 += __shfl_xor_sync(0xffffffffu, l0, 1);
    l0 += __shfl_xor_sync(0xffffffffu, l0, 2);
    l1 += __shfl_xor_sync(0xffffffffu, l1, 1);
    l1 += __shfl_xor_sync(0xffffffffu, l1, 2);
    const float i0 = 1.f / l0, i1 = 1.f / l1;

    const int tok0 = b * T_ + r0, tok1 = b * T_ + r1;
    #pragma unroll
    for (int j = 0; j < 8; j++) {
        const int n = h * DH_ + 8 * j + 2 * (lane & 3);
        float v0 = o[j][0] * i0, v1 = o[j][1] * i0;
        float v2 = o[j][2] * i1, v3 = o[j][3] * i1;
        __nv_bfloat16 h0 = __float2bfloat16(v0), h1 = __float2bfloat16(v1);
        __nv_bfloat16 h2 = __float2bfloat16(v2), h3 = __float2bfloat16(v3);
        __nv_bfloat162 hi0(h0, h1), hi1(h2, h3);
        __nv_bfloat162 lo0(__float2bfloat16(v0 - __bfloat162float(h0)),
                           __float2bfloat16(v1 - __bfloat162float(h1)));
        __nv_bfloat162 lo1(__float2bfloat16(v2 - __bfloat162float(h2)),
                           __float2bfloat16(v3 - __bfloat162float(h3)));
        size_t p0 = (size_t)tok0 * KTOT + n;
        size_t p1 = (size_t)tok1 * KTOT + n;
        *(__nv_bfloat162*)&g_aocat[p0]        = hi0;
        *(__nv_bfloat162*)&g_aocat[p0 + 1024] = hi0;
        *(__nv_bfloat162*)&g_aocat[p0 + 2048] = lo0;
        *(__nv_bfloat162*)&g_aocat[p1]        = hi1;
        *(__nv_bfloat162*)&g_aocat[p1 + 1024] = hi1;
        *(__nv_bfloat162*)&g_aocat[p1 + 2048] = lo1;
    }
}

// ---------------- launch --------------------------------------------------------
extern "C" void kernel_launch(void* const* d_in, const int* in_sizes, int n_in,
                              void* d_out, int out_size) {
    const float* X  = (const float*)d_in[0];
    const float* wq = (const float*)d_in[1];
    const float* wk = (const float*)d_in[2];
    const float* wv = (const float*)d_in[3];
    const float* wo = (const float*)d_in[4];
    const float* Aq = (const float*)d_in[5];
    const float* Bq = (const float*)d_in[6];
    const float* Av = (const float*)d_in[7];
    const float* Bv = (const float*)d_in[8];
    float* out = (float*)d_out;

    __nv_bfloat16 *xcat, *aocat, *wtqkv, *wto;
    cudaGetSymbolAddress((void**)&xcat,  g_xcat);
    cudaGetSymbolAddress((void**)&aocat, g_aocat);
    cudaGetSymbolAddress((void**)&wtqkv, g_wtqkv);
    cudaGetSymbolAddress((void**)&wto,   g_wto);

    cudaFuncSetAttribute(gemm_fused_kernel,
                         cudaFuncAttributeMaxDynamicSharedMemorySize, G_TOTAL);
    cudaFuncSetAttribute(attn_mma_kernel,
                         cudaFuncAttributeMaxDynamicSharedMemorySize, A_SMEM);

    sincos_kernel<<<(T_*32 + 255) / 256, 256>>>();
    lora_down_kernel<<<MTOT, 256>>>(X, Aq, Av);
    split_x_kernel<<<(MTOT * D_ / 4 + 255) / 256, 256>>>(X);
    split_wt_kernel<<<dim3(32, 32, 4), dim3(32, 8)>>>(wq, wk, wv, wo);

    gemm_fused_kernel<<<dim3(12, 64), 512, G_TOTAL>>>(xcat, wtqkv, nullptr, 1, Bq, Bv);

    attn_mma_kernel<<<dim3(T_ / 128, H_, B_), 256, A_SMEM>>>();

    gemm_fused_kernel<<<dim3(4, 64), 512, G_TOTAL>>>(aocat, wto, out, 0, nullptr, nullptr);
}

// round 9
// speedup vs baseline: 3.4310x; 1.0005x over previous
#include <cuda_runtime.h>
#include <cuda_bf16.h>
#include <math.h>
#include <cstdint>

#define B_   4
#define T_   2048
#define D_   1024
#define H_   16
#define DH_  64
#define R_   8
#define MTOT (B_*T_)          // 8192
#define KTOT 3072             // split-bf16 concatenated K
#define NCHUNK 48             // KTOT / 64
#define LORA_SCALE 4.0f
#define QSCALE 0.180336880f   // 0.125 * log2(e)  — exp2-domain logits

// ---------------- scratch (device globals: no allocation allowed) -------------
__device__ float g_xaq[MTOT*R_];
__device__ float g_xav[MTOT*R_];
__device__ float g_sin[T_*32];
__device__ float g_cos[T_*32];
__device__ __nv_bfloat16 g_xcat [MTOT*KTOT];       // [Xhi | Xhi | Xlo]
__device__ __nv_bfloat16 g_aocat[MTOT*KTOT];       // attention out, same layout
__device__ __nv_bfloat16 g_wtqkv[3072ull*KTOT];    // rows n: [wq|wk|wv] cols, k = [hi|lo|hi]
__device__ __nv_bfloat16 g_wto  [(size_t)D_*KTOT];
// head-major [b,h,t,dh] bf16 split pairs
__device__ __nv_bfloat16 g_qhi[MTOT*D_];
__device__ __nv_bfloat16 g_qlo[MTOT*D_];
__device__ __nv_bfloat16 g_khi[MTOT*D_];
__device__ __nv_bfloat16 g_klo[MTOT*D_];
__device__ __nv_bfloat16 g_vhi[MTOT*D_];
__device__ __nv_bfloat16 g_vlo[MTOT*D_];

// ---------------- warp-level MMA helpers ---------------------------------------
__device__ __forceinline__ uint32_t smem_u32(const void* p) {
    uint32_t a;
    asm("{ .reg .u64 t; cvta.to.shared.u64 t, %1; cvt.u32.u64 %0, t; }" : "=r"(a) : "l"(p));
    return a;
}
__device__ __forceinline__ void ldsm_x4(uint32_t* r, uint32_t addr) {
    asm volatile("ldmatrix.sync.aligned.m8n8.x4.shared.b16 {%0,%1,%2,%3}, [%4];"
                 : "=r"(r[0]), "=r"(r[1]), "=r"(r[2]), "=r"(r[3]) : "r"(addr));
}
__device__ __forceinline__ void ldsm_x4_t(uint32_t* r, uint32_t addr) {
    asm volatile("ldmatrix.sync.aligned.m8n8.x4.trans.shared.b16 {%0,%1,%2,%3}, [%4];"
                 : "=r"(r[0]), "=r"(r[1]), "=r"(r[2]), "=r"(r[3]) : "r"(addr));
}
__device__ __forceinline__ void mma16816(float* d, const uint32_t* a,
                                         uint32_t b0, uint32_t b1) {
    asm volatile("mma.sync.aligned.m16n8k16.row.col.f32.bf16.bf16.f32 "
                 "{%0,%1,%2,%3}, {%4,%5,%6,%7}, {%8,%9}, {%0,%1,%2,%3};"
                 : "+f"(d[0]), "+f"(d[1]), "+f"(d[2]), "+f"(d[3])
                 : "r"(a[0]), "r"(a[1]), "r"(a[2]), "r"(a[3]), "r"(b0), "r"(b1));
}
__device__ __forceinline__ uint32_t pack_bf16x2(float e, float o) {
    uint32_t d;
    asm("cvt.rn.bf16x2.f32 %0, %1, %2;" : "=r"(d) : "f"(o), "f"(e));
    return d;
}
__device__ __forceinline__ float ex2f(float x) {
    float r;
    asm("ex2.approx.ftz.f32 %0, %1;" : "=f"(r) : "f"(x));
    return r;
}
__device__ __forceinline__ void cpa16(uint32_t dst, const void* src) {
    asm volatile("cp.async.cg.shared.global [%0], [%1], 16;" :: "r"(dst), "l"(src) : "memory");
}
#define CP_COMMIT() asm volatile("cp.async.commit_group;" ::: "memory")
#define CP_WAIT1()  asm volatile("cp.async.wait_group 1;"  ::: "memory")
#define CP_WAIT0()  asm volatile("cp.async.wait_group 0;"  ::: "memory")

// ---------------- sin/cos table -----------------------------------------------
__global__ void sincos_kernel() {
    int idx = blockIdx.x * blockDim.x + threadIdx.x;
    if (idx >= T_*32) return;
    int t = idx >> 5, j = idx & 31;
    double theta = (double)t / pow(10000.0, (double)j / 32.0);
    g_sin[idx] = (float)sin(theta);
    g_cos[idx] = (float)cos(theta);
}

// ---------------- LoRA down-projection ----------------------------------------
__global__ void lora_down_kernel(const float* __restrict__ X,
                                 const float* __restrict__ Aq,
                                 const float* __restrict__ Av) {
    int m    = blockIdx.x;
    int lane = threadIdx.x & 31;
    int w    = threadIdx.x >> 5;
    const float* x = X + m * D_;
    #pragma unroll
    for (int cc = 0; cc < 2; cc++) {
        int c = w * 2 + cc;
        const float* A = (c < 8) ? Aq : Av;
        int col = c & 7;
        float s = 0.f;
        for (int k = lane; k < D_; k += 32)
            s += x[k] * A[k * R_ + col];
        #pragma unroll
        for (int off = 16; off; off >>= 1)
            s += __shfl_down_sync(0xffffffffu, s, off);
        if (lane == 0) {
            float* XA = (c < 8) ? g_xaq : g_xav;
            XA[m * R_ + col] = s;
        }
    }
}

// ---------------- split X -> [hi|hi|lo] bf16 ----------------------------------
__global__ void split_x_kernel(const float* __restrict__ X) {
    int idx4 = blockIdx.x * blockDim.x + threadIdx.x;
    if (idx4 >= MTOT * D_ / 4) return;
    int m = idx4 >> 8;
    int k = (idx4 & 255) * 4;
    float4 x = ((const float4*)X)[idx4];
    float xs[4] = {x.x, x.y, x.z, x.w};
    __nv_bfloat16 h[4], l[4];
    #pragma unroll
    for (int i = 0; i < 4; i++) {
        h[i] = __float2bfloat16(xs[i]);
        l[i] = __float2bfloat16(xs[i] - __bfloat162float(h[i]));
    }
    size_t base = (size_t)m * KTOT + k;
    *(__nv_bfloat162*)&g_xcat[base]        = __nv_bfloat162(h[0], h[1]);
    *(__nv_bfloat162*)&g_xcat[base+2]      = __nv_bfloat162(h[2], h[3]);
    *(__nv_bfloat162*)&g_xcat[base+1024]   = __nv_bfloat162(h[0], h[1]);
    *(__nv_bfloat162*)&g_xcat[base+1026]   = __nv_bfloat162(h[2], h[3]);
    *(__nv_bfloat162*)&g_xcat[base+2048]   = __nv_bfloat162(l[0], l[1]);
    *(__nv_bfloat162*)&g_xcat[base+2050]   = __nv_bfloat162(l[2], l[3]);
}

// ---------------- transpose + split weights ------------------------------------
__global__ void split_wt_kernel(const float* __restrict__ W0, const float* __restrict__ W1,
                                const float* __restrict__ W2, const float* __restrict__ W3) {
    const float* Ws[4] = {W0, W1, W2, W3};
    const float* W = Ws[blockIdx.z];
    __shared__ float tile[32][33];
    int bx = blockIdx.x * 32, by = blockIdx.y * 32;
    for (int i = threadIdx.y; i < 32; i += 8)
        tile[i][threadIdx.x] = W[(size_t)(by + i) * D_ + bx + threadIdx.x];
    __syncthreads();
    for (int i = threadIdx.y; i < 32; i += 8) {
        int n = bx + i, k = by + threadIdx.x;
        float x = tile[threadIdx.x][i];
        __nv_bfloat16 h = __float2bfloat16(x);
        __nv_bfloat16 l = __float2bfloat16(x - __bfloat162float(h));
        __nv_bfloat16* out = (blockIdx.z < 3)
            ? g_wtqkv + (size_t)(blockIdx.z * 1024 + n) * KTOT
            : g_wto   + (size_t)n * KTOT;
        out[k]        = h;
        out[1024 + k] = l;
        out[2048 + k] = h;
    }
}

// ================= fused HMMA split-bf16 GEMM (128x256 tile, 512 thr) ==========
#define GSTG   49152
#define GA(s)  ((s) * GSTG)
#define GB(s)  ((s) * GSTG + 16384)
#define G_LB   147456
#define G_TOTAL 155648

__global__ void __launch_bounds__(512)
gemm_fused_kernel(const __nv_bfloat16* __restrict__ Acat,
                  const __nv_bfloat16* __restrict__ Bcat,
                  float* __restrict__ C, int qkv,
                  const float* __restrict__ Bq, const float* __restrict__ Bv)
{
    extern __shared__ char smem[];
    const uint32_t sbase = smem_u32(smem);
    const int tid  = threadIdx.x;
    const int lane = tid & 31;
    const int wid  = tid >> 5;
    const int wm   = wid & 1;
    const int wn   = wid >> 1;
    const int row0 = blockIdx.y * 128, col0 = blockIdx.x * 256;

    float acc[4][4][4];
    #pragma unroll
    for (int i = 0; i < 4; i++)
        #pragma unroll
        for (int j = 0; j < 4; j++)
            #pragma unroll
            for (int r = 0; r < 4; r++) acc[i][j][r] = 0.f;

    auto prefetch = [&](int c, int stg) {
        const int kb = c * 64;
        #pragma unroll
        for (int i = 0; i < 2; i++) {
            int idx = i * 512 + tid;
            int r = idx >> 3, cc = idx & 7;
            uint32_t off = r * 128 + (((uint32_t)(cc * 16)) ^ ((r & 7) << 4));
            cpa16(sbase + GA(stg) + off, Acat + (size_t)(row0 + r) * KTOT + kb + cc * 8);
        }
        #pragma unroll
        for (int i = 0; i < 4; i++) {
            int idx = i * 512 + tid;
            int r = idx >> 3, cc = idx & 7;
            uint32_t off = r * 128 + (((uint32_t)(cc * 16)) ^ ((r & 7) << 4));
            cpa16(sbase + GB(stg) + off, Bcat + (size_t)(col0 + r) * KTOT + kb + cc * 8);
        }
    };

    prefetch(0, 0); CP_COMMIT();
    prefetch(1, 1); CP_COMMIT();

    int sc = 0, s2 = 2;
    for (int c = 0; c < NCHUNK; c++) {
        CP_WAIT1();
        __syncthreads();
        if (c + 2 < NCHUNK) prefetch(c + 2, s2);
        CP_COMMIT();
        const uint32_t sa = sbase + GA(sc);
        const uint32_t sb = sbase + GB(sc);
        #pragma unroll
        for (int ks = 0; ks < 4; ks++) {
            uint32_t af[4][4], bfr[2][4];
            #pragma unroll
            for (int ma = 0; ma < 4; ma++) {
                int r = wm * 64 + ma * 16 + (lane & 15);
                uint32_t off = (uint32_t)(ks * 32 + ((lane >> 4) << 4));
                ldsm_x4(af[ma], sa + r * 128 + (off ^ ((r & 7) << 4)));
            }
            #pragma unroll
            for (int nb = 0; nb < 2; nb++) {
                int r = wn * 32 + nb * 16 + ((lane >> 4) << 3) + (lane & 7);
                uint32_t off = (uint32_t)(ks * 32 + (((lane >> 3) & 1) << 4));
                ldsm_x4(bfr[nb], sb + r * 128 + (off ^ ((r & 7) << 4)));
            }
            #pragma unroll
            for (int ma = 0; ma < 4; ma++)
                #pragma unroll
                for (int na = 0; na < 4; na++)
                    mma16816(acc[ma][na], af[ma],
                             bfr[na >> 1][(na & 1) * 2], bfr[na >> 1][(na & 1) * 2 + 1]);
        }
        sc = (sc == 2) ? 0 : sc + 1;
        s2 = (s2 == 2) ? 0 : s2 + 1;
    }
    __syncthreads();

    const int region = qkv ? (col0 >> 10) : 3;
    const float* XA = (region == 0) ? g_xaq : (region == 2) ? g_xav : nullptr;
    float* LBs = (float*)(smem + G_LB);
    if (qkv && region != 1) {
        const float* Bsrc = (region == 0) ? Bq : Bv;
        const int cbase = col0 & 1023;
        #pragma unroll
        for (int i = 0; i < 4; i++) {
            int idx = i * 512 + tid;
            LBs[idx] = Bsrc[(idx >> 8) * D_ + cbase + (idx & 255)];
        }
        __syncthreads();
    }

    #pragma unroll
    for (int ma = 0; ma < 4; ma++) {
        const int mlo = row0 + wm * 64 + ma * 16 + (lane >> 2);
        const int mhi = mlo + 8;
        float xal[8], xah[8];
        if (XA) {
            #pragma unroll
            for (int r = 0; r < R_; r++) {
                xal[r] = XA[mlo * R_ + r];
                xah[r] = XA[mhi * R_ + r];
            }
        }
        const int tlo = mlo & (T_ - 1), thi = mhi & (T_ - 1);
        #pragma unroll
        for (int na = 0; na < 4; na++) {
            const int n  = col0 + wn * 32 + na * 8 + (lane & 3) * 2;
            const int nl = n - col0;
            float v0 = acc[ma][na][0], v1 = acc[ma][na][1];
            float v2 = acc[ma][na][2], v3 = acc[ma][na][3];
            if (XA) {
                float s0 = 0.f, s1 = 0.f, s2_ = 0.f, s3 = 0.f;
                #pragma unroll
                for (int r = 0; r < R_; r++) {
                    float b0 = LBs[r * 256 + nl], b1 = LBs[r * 256 + nl + 1];
                    s0 += xal[r] * b0; s1 += xal[r] * b1;
                    s2_ += xah[r] * b0; s3 += xah[r] * b1;
                }
                v0 += LORA_SCALE * s0; v1 += LORA_SCALE * s1;
                v2 += LORA_SCALE * s2_; v3 += LORA_SCALE * s3;
            }
            if (region <= 1) {              // RoPE for Q and K
                const int jj = (n & 63) >> 1;
                float sn = g_sin[tlo * 32 + jj], cs = g_cos[tlo * 32 + jj];
                float e = v0, o = v1;
                v0 = e * cs - o * sn; v1 = e * sn + o * cs;
                sn = g_sin[thi * 32 + jj]; cs = g_cos[thi * 32 + jj];
                e = v2; o = v3;
                v2 = e * cs - o * sn; v3 = e * sn + o * cs;
            }
            if (region == 0) { v0 *= QSCALE; v1 *= QSCALE; v2 *= QSCALE; v3 *= QSCALE; }
            if (!qkv) {
                *(float2*)&C[(size_t)mlo * D_ + n] = make_float2(v0, v1);
                *(float2*)&C[(size_t)mhi * D_ + n] = make_float2(v2, v3);
            } else {
                __nv_bfloat16* Chi = (region == 0) ? g_qhi : (region == 1) ? g_khi : g_vhi;
                __nv_bfloat16* Clo = (region == 0) ? g_qlo : (region == 1) ? g_klo : g_vlo;
                const int bq = mlo >> 11, hh = (n & 1023) >> 6, dd = n & 63;
                size_t olo = ((size_t)(bq * H_ + hh) * T_ + tlo) * DH_ + dd;
                size_t ohi = ((size_t)(bq * H_ + hh) * T_ + thi) * DH_ + dd;
                __nv_bfloat16 h0 = __float2bfloat16(v0), h1 = __float2bfloat16(v1);
                __nv_bfloat16 h2 = __float2bfloat16(v2), h3 = __float2bfloat16(v3);
                *(__nv_bfloat162*)&Chi[olo] = __nv_bfloat162(h0, h1);
                *(__nv_bfloat162*)&Chi[ohi] = __nv_bfloat162(h2, h3);
                *(__nv_bfloat162*)&Clo[olo] = __nv_bfloat162(
                    __float2bfloat16(v0 - __bfloat162float(h0)),
                    __float2bfloat16(v1 - __bfloat162float(h1)));
                *(__nv_bfloat162*)&Clo[ohi] = __nv_bfloat162(
                    __float2bfloat16(v2 - __bfloat162float(h2)),
                    __float2bfloat16(v3 - __bfloat162float(h3)));
            }
        }
    }
}

// ================= tensor-core flash attention =================================
// 2-stage, single sync per chunk; 32-key sub-blocks to cut register pressure
// (target 2 CTAs/SM); exp2-domain logits (QSCALE folded in Q epilogue).
#define AQ_HI 0
#define AQ_LO 16384
#define ATILE(buf) (32768 + (buf) * 32768)   // KHI | KLO | VHI | VLO (8KB each)
#define A_SMEM 98304

__global__ void __launch_bounds__(256, 2)
attn_mma_kernel() {
    extern __shared__ char smem[];
    const uint32_t sbs = smem_u32(smem);
    const int tid = threadIdx.x, lane = tid & 31, w = tid >> 5;
    const int qb = gridDim.x - 1 - blockIdx.x;
    const int h = blockIdx.y, b = blockIdx.z;
    const int bh = b * H_ + h;
    const __nv_bfloat16* qhi = g_qhi + (size_t)bh * T_ * DH_;
    const __nv_bfloat16* qlo = g_qlo + (size_t)bh * T_ * DH_;
    const __nv_bfloat16* khi = g_khi + (size_t)bh * T_ * DH_;
    const __nv_bfloat16* klo = g_klo + (size_t)bh * T_ * DH_;
    const __nv_bfloat16* vhi = g_vhi + (size_t)bh * T_ * DH_;
    const __nv_bfloat16* vlo = g_vlo + (size_t)bh * T_ * DH_;

    {
        const __nv_bfloat16* sq = qhi + (size_t)(qb * 128) * DH_;
        const __nv_bfloat16* sl = qlo + (size_t)(qb * 128) * DH_;
        #pragma unroll
        for (int i = 0; i < 4; i++) {
            int idx = i * 256 + tid;
            int r = idx >> 3, c = idx & 7;
            uint32_t off = r * 128 + (((uint32_t)(c * 16)) ^ ((r & 7) << 4));
            *(uint4*)(smem + AQ_HI + off) = *((const uint4*)(sq + r * DH_) + c);
            *(uint4*)(smem + AQ_LO + off) = *((const uint4*)(sl + r * DH_) + c);
        }
    }
    __syncthreads();

    uint32_t qf[2][4][4];
    #pragma unroll
    for (int s = 0; s < 2; s++) {
        const uint32_t base = sbs + (s ? AQ_LO : AQ_HI);
        #pragma unroll
        for (int ks = 0; ks < 4; ks++) {
            int tsel = lane >> 3;
            int r = 16 * w + (lane & 7) + (tsel & 1) * 8;
            uint32_t off = ((uint32_t)(ks * 32 + ((tsel >> 1) & 1) * 16)) ^ ((r & 7) << 4);
            ldsm_x4(qf[s][ks], base + r * 128 + off);
        }
    }

    auto prefetch = [&](int c, int buf) {
        const int k0 = c * 64;
        const uint32_t tb = sbs + ATILE(buf);
        #pragma unroll
        for (int i = 0; i < 2; i++) {
            int idx = i * 256 + tid;
            int r = idx >> 3, cc = idx & 7;
            uint32_t off = r * 128 + (((uint32_t)(cc * 16)) ^ ((r & 7) << 4));
            const size_t g = (size_t)(k0 + r) * DH_ + cc * 8;
            cpa16(tb + off,         khi + g);
            cpa16(tb + 8192 + off,  klo + g);
            cpa16(tb + 16384 + off, vhi + g);
            cpa16(tb + 24576 + off, vlo + g);
        }
    };

    const int nch = 2 * qb + 2;
    prefetch(0, 0); CP_COMMIT();

    float o[8][4];
    #pragma unroll
    for (int j = 0; j < 8; j++)
        #pragma unroll
        for (int r = 0; r < 4; r++) o[j][r] = 0.f;
    float m0 = -1e30f, m1 = -1e30f, l0 = 0.f, l1 = 0.f;

    const int wrow0 = qb * 128 + 16 * w;
    const int r0 = wrow0 + (lane >> 2), r1 = r0 + 8;

    for (int c = 0; c < nch; c++) {
        const int buf = c & 1;
        CP_WAIT0();
        __syncthreads();
        if (c + 1 < nch) { prefetch(c + 1, buf ^ 1); CP_COMMIT(); }

        const int k0 = c * 64;
        const uint32_t skh = sbs + ATILE(buf);
        const uint32_t skl = skh + 8192;
        const uint32_t svh = skh + 16384;
        const uint32_t svl = skh + 24576;

        #pragma unroll
        for (int hb = 0; hb < 2; hb++) {              // 32-key sub-block
            const int kb0 = k0 + hb * 32;
            if (kb0 > wrow0 + 15) break;

            float s[4][4];
            #pragma unroll
            for (int j = 0; j < 4; j++)
                #pragma unroll
                for (int r = 0; r < 4; r++) s[j][r] = 0.f;

            #pragma unroll
            for (int ks = 0; ks < 4; ks++) {
                #pragma unroll
                for (int jp = 0; jp < 2; jp++) {
                    uint32_t bh_[4], bl_[4];
                    int rr = hb * 32 + jp * 16 + ((lane >> 4) << 3) + (lane & 7);
                    uint32_t off = ((uint32_t)(ks * 32 + (((lane >> 3) & 1) << 4)))
                                   ^ ((rr & 7) << 4);
                    ldsm_x4(bh_, skh + rr * 128 + off);
                    ldsm_x4(bl_, skl + rr * 128 + off);
                    mma16816(s[2*jp],   qf[0][ks], bh_[0], bh_[1]);
                    mma16816(s[2*jp],   qf[0][ks], bl_[0], bl_[1]);
                    mma16816(s[2*jp],   qf[1][ks], bh_[0], bh_[1]);
                    mma16816(s[2*jp+1], qf[0][ks], bh_[2], bh_[3]);
                    mma16816(s[2*jp+1], qf[0][ks], bl_[2], bl_[3]);
                    mma16816(s[2*jp+1], qf[1][ks], bh_[2], bh_[3]);
                }
            }

            if (kb0 + 31 > wrow0) {                   // causal mask
                #pragma unroll
                for (int j = 0; j < 4; j++) {
                    int col = kb0 + 8 * j + 2 * (lane & 3);
                    if (col     > r0) s[j][0] = -1e30f;
                    if (col + 1 > r0) s[j][1] = -1e30f;
                    if (col     > r1) s[j][2] = -1e30f;
                    if (col + 1 > r1) s[j][3] = -1e30f;
                }
            }

            float mx0 = -1e30f, mx1 = -1e30f;
            #pragma unroll
            for (int j = 0; j < 4; j++) {
                mx0 = fmaxf(mx0, fmaxf(s[j][0], s[j][1]));
                mx1 = fmaxf(mx1, fmaxf(s[j][2], s[j][3]));
            }
            mx0 = fmaxf(mx0, __shfl_xor_sync(0xffffffffu, mx0, 1));
            mx0 = fmaxf(mx0, __shfl_xor_sync(0xffffffffu, mx0, 2));
            mx1 = fmaxf(mx1, __shfl_xor_sync(0xffffffffu, mx1, 1));
            mx1 = fmaxf(mx1, __shfl_xor_sync(0xffffffffu, mx1, 2));
            float mn0 = fmaxf(m0, mx0), mn1 = fmaxf(m1, mx1);
            float cr0 = ex2f(m0 - mn0), cr1 = ex2f(m1 - mn1);
            l0 *= cr0; l1 *= cr1;
            #pragma unroll
            for (int j = 0; j < 8; j++) {
                o[j][0] *= cr0; o[j][1] *= cr0;
                o[j][2] *= cr1; o[j][3] *= cr1;
            }
            m0 = mn0; m1 = mn1;

            uint32_t ph[4][2], pl[4][2];
            #pragma unroll
            for (int j = 0; j < 4; j++) {
                float p0 = ex2f(s[j][0] - mn0), p1 = ex2f(s[j][1] - mn0);
                float p2 = ex2f(s[j][2] - mn1), p3 = ex2f(s[j][3] - mn1);
                l0 += p0 + p1; l1 += p2 + p3;
                __nv_bfloat16 b0 = __float2bfloat16(p0), b1 = __float2bfloat16(p1);
                __nv_bfloat16 b2 = __float2bfloat16(p2), b3 = __float2bfloat16(p3);
                ph[j][0] = pack_bf16x2(__bfloat162float(b0), __bfloat162float(b1));
                ph[j][1] = pack_bf16x2(__bfloat162float(b2), __bfloat162float(b3));
                pl[j][0] = pack_bf16x2(p0 - __bfloat162float(b0), p1 - __bfloat162float(b1));
                pl[j][1] = pack_bf16x2(p2 - __bfloat162float(b2), p3 - __bfloat162float(b3));
            }

            #pragma unroll
            for (int kk = 0; kk < 2; kk++) {          // 16 keys per PV k-step
                uint32_t ahi[4] = {ph[2*kk][0], ph[2*kk][1], ph[2*kk+1][0], ph[2*kk+1][1]};
                uint32_t alo[4] = {pl[2*kk][0], pl[2*kk][1], pl[2*kk+1][0], pl[2*kk+1][1]};
                #pragma unroll
                for (int jp = 0; jp < 4; jp++) {
                    uint32_t vh_[4], vl_[4];
                    int tsel = lane >> 3;
                    int key = hb * 32 + 16 * kk + (tsel & 1) * 8 + (lane & 7);
                    uint32_t off = ((uint32_t)((16 * jp + ((tsel >> 1) & 1) * 8) * 2))
                                   ^ ((key & 7) << 4);
                    ldsm_x4_t(vh_, svh + key * 128 + off);
                    ldsm_x4_t(vl_, svl + key * 128 + off);
                    mma16816(o[2*jp],   ahi, vh_[0], vh_[1]);
                    mma16816(o[2*jp],   ahi, vl_[0], vl_[1]);
                    mma16816(o[2*jp],   alo, vh_[0], vh_[1]);
                    mma16816(o[2*jp+1], ahi, vh_[2], vh_[3]);
                    mma16816(o[2*jp+1], ahi, vl_[2], vl_[3]);
                    mma16816(o[2*jp+1], alo, vh_[2], vh_[3]);
                }
            }
        }
    }

    l0 += __shfl_xor_sync(0xffffffffu, l0, 1);
    l0 += __shfl_xor_sync(0xffffffffu, l0, 2);
    l1 += __shfl_xor_sync(0xffffffffu, l1, 1);
    l1 += __shfl_xor_sync(0xffffffffu, l1, 2);
    const float i0 = 1.f / l0, i1 = 1.f / l1;

    const int tok0 = b * T_ + r0, tok1 = b * T_ + r1;
    #pragma unroll
    for (int j = 0; j < 8; j++) {
        const int n = h * DH_ + 8 * j + 2 * (lane & 3);
        float v0 = o[j][0] * i0, v1 = o[j][1] * i0;
        float v2 = o[j][2] * i1, v3 = o[j][3] * i1;
        __nv_bfloat16 h0 = __float2bfloat16(v0), h1 = __float2bfloat16(v1);
        __nv_bfloat16 h2 = __float2bfloat16(v2), h3 = __float2bfloat16(v3);
        __nv_bfloat162 hi0(h0, h1), hi1(h2, h3);
        __nv_bfloat162 lo0(__float2bfloat16(v0 - __bfloat162float(h0)),
                           __float2bfloat16(v1 - __bfloat162float(h1)));
        __nv_bfloat162 lo1(__float2bfloat16(v2 - __bfloat162float(h2)),
                           __float2bfloat16(v3 - __bfloat162float(h3)));
        size_t p0 = (size_t)tok0 * KTOT + n;
        size_t p1 = (size_t)tok1 * KTOT + n;
        *(__nv_bfloat162*)&g_aocat[p0]        = hi0;
        *(__nv_bfloat162*)&g_aocat[p0 + 1024] = hi0;
        *(__nv_bfloat162*)&g_aocat[p0 + 2048] = lo0;
        *(__nv_bfloat162*)&g_aocat[p1]        = hi1;
        *(__nv_bfloat162*)&g_aocat[p1 + 1024] = hi1;
        *(__nv_bfloat162*)&g_aocat[p1 + 2048] = lo1;
    }
}

// ---------------- launch --------------------------------------------------------
extern "C" void kernel_launch(void* const* d_in, const int* in_sizes, int n_in,
                              void* d_out, int out_size) {
    const float* X  = (const float*)d_in[0];
    const float* wq = (const float*)d_in[1];
    const float* wk = (const float*)d_in[2];
    const float* wv = (const float*)d_in[3];
    const float* wo = (const float*)d_in[4];
    const float* Aq = (const float*)d_in[5];
    const float* Bq = (const float*)d_in[6];
    const float* Av = (const float*)d_in[7];
    const float* Bv = (const float*)d_in[8];
    float* out = (float*)d_out;

    __nv_bfloat16 *xcat, *aocat, *wtqkv, *wto;
    cudaGetSymbolAddress((void**)&xcat,  g_xcat);
    cudaGetSymbolAddress((void**)&aocat, g_aocat);
    cudaGetSymbolAddress((void**)&wtqkv, g_wtqkv);
    cudaGetSymbolAddress((void**)&wto,   g_wto);

    cudaFuncSetAttribute(gemm_fused_kernel,
                         cudaFuncAttributeMaxDynamicSharedMemorySize, G_TOTAL);
    cudaFuncSetAttribute(attn_mma_kernel,
                         cudaFuncAttributeMaxDynamicSharedMemorySize, A_SMEM);

    sincos_kernel<<<(T_*32 + 255) / 256, 256>>>();
    lora_down_kernel<<<MTOT, 256>>>(X, Aq, Av);
    split_x_kernel<<<(MTOT * D_ / 4 + 255) / 256, 256>>>(X);
    split_wt_kernel<<<dim3(32, 32, 4), dim3(32, 8)>>>(wq, wk, wv, wo);

    gemm_fused_kernel<<<dim3(12, 64), 512, G_TOTAL>>>(xcat, wtqkv, nullptr, 1, Bq, Bv);

    attn_mma_kernel<<<dim3(T_ / 128, H_, B_), 256, A_SMEM>>>();

    gemm_fused_kernel<<<dim3(4, 64), 512, G_TOTAL>>>(aocat, wto, out, 0, nullptr, nullptr);
}

// round 10
// speedup vs baseline: 3.4525x; 1.0063x over previous
#include <cuda_runtime.h>
#include <cuda_bf16.h>
#include <math.h>
#include <cstdint>

#define B_   4
#define T_   2048
#define D_   1024
#define H_   16
#define DH_  64
#define R_   8
#define MTOT (B_*T_)          // 8192
#define KSRC 2048             // stored split width: [hi | lo]
#define NCHUNK 48             // 3 terms x 16 chunks of 64
#define LORA_SCALE 4.0f
#define QSCALE 0.180336880f   // 0.125 * log2(e)  — exp2-domain logits

// ---------------- scratch (device globals: no allocation allowed) -------------
__device__ float g_xaq[MTOT*R_];
__device__ float g_xav[MTOT*R_];
__device__ float g_sin[T_*32];
__device__ float g_cos[T_*32];
__device__ __nv_bfloat16 g_xcat [MTOT*KSRC];       // [Xhi | Xlo]
__device__ __nv_bfloat16 g_aocat[MTOT*KSRC];       // attention out [hi | lo]
__device__ __nv_bfloat16 g_wtqkv[3072ull*KSRC];    // rows n of [wq|wk|wv], k = [hi|lo]
__device__ __nv_bfloat16 g_wto  [(size_t)D_*KSRC];
// head-major [b,h,t,dh] bf16 split pairs
__device__ __nv_bfloat16 g_qhi[MTOT*D_];
__device__ __nv_bfloat16 g_qlo[MTOT*D_];
__device__ __nv_bfloat16 g_khi[MTOT*D_];
__device__ __nv_bfloat16 g_klo[MTOT*D_];
__device__ __nv_bfloat16 g_vhi[MTOT*D_];
__device__ __nv_bfloat16 g_vlo[MTOT*D_];

// ---------------- warp-level MMA helpers ---------------------------------------
__device__ __forceinline__ uint32_t smem_u32(const void* p) {
    uint32_t a;
    asm("{ .reg .u64 t; cvta.to.shared.u64 t, %1; cvt.u32.u64 %0, t; }" : "=r"(a) : "l"(p));
    return a;
}
__device__ __forceinline__ void ldsm_x4(uint32_t* r, uint32_t addr) {
    asm volatile("ldmatrix.sync.aligned.m8n8.x4.shared.b16 {%0,%1,%2,%3}, [%4];"
                 : "=r"(r[0]), "=r"(r[1]), "=r"(r[2]), "=r"(r[3]) : "r"(addr));
}
__device__ __forceinline__ void ldsm_x4_t(uint32_t* r, uint32_t addr) {
    asm volatile("ldmatrix.sync.aligned.m8n8.x4.trans.shared.b16 {%0,%1,%2,%3}, [%4];"
                 : "=r"(r[0]), "=r"(r[1]), "=r"(r[2]), "=r"(r[3]) : "r"(addr));
}
__device__ __forceinline__ void mma16816(float* d, const uint32_t* a,
                                         uint32_t b0, uint32_t b1) {
    asm volatile("mma.sync.aligned.m16n8k16.row.col.f32.bf16.bf16.f32 "
                 "{%0,%1,%2,%3}, {%4,%5,%6,%7}, {%8,%9}, {%0,%1,%2,%3};"
                 : "+f"(d[0]), "+f"(d[1]), "+f"(d[2]), "+f"(d[3])
                 : "r"(a[0]), "r"(a[1]), "r"(a[2]), "r"(a[3]), "r"(b0), "r"(b1));
}
__device__ __forceinline__ uint32_t pack_bf16x2(float e, float o) {
    uint32_t d;
    asm("cvt.rn.bf16x2.f32 %0, %1, %2;" : "=r"(d) : "f"(o), "f"(e));
    return d;
}
__device__ __forceinline__ float ex2f(float x) {
    float r;
    asm("ex2.approx.ftz.f32 %0, %1;" : "=f"(r) : "f"(x));
    return r;
}
__device__ __forceinline__ void cpa16(uint32_t dst, const void* src) {
    asm volatile("cp.async.cg.shared.global [%0], [%1], 16;" :: "r"(dst), "l"(src) : "memory");
}
#define CP_COMMIT() asm volatile("cp.async.commit_group;" ::: "memory")
#define CP_WAIT1()  asm volatile("cp.async.wait_group 1;"  ::: "memory")
#define CP_WAIT0()  asm volatile("cp.async.wait_group 0;"  ::: "memory")

// ---------------- sin/cos table -----------------------------------------------
__global__ void sincos_kernel() {
    int idx = blockIdx.x * blockDim.x + threadIdx.x;
    if (idx >= T_*32) return;
    int t = idx >> 5, j = idx & 31;
    double theta = (double)t / pow(10000.0, (double)j / 32.0);
    g_sin[idx] = (float)sin(theta);
    g_cos[idx] = (float)cos(theta);
}

// ---------------- fused LoRA down-proj + X split --------------------------------
__global__ void lora_split_kernel(const float* __restrict__ X,
                                  const float* __restrict__ Aq,
                                  const float* __restrict__ Av) {
    __shared__ float xrow[1024];
    const int m = blockIdx.x;
    const int tid = threadIdx.x;
    const int lane = tid & 31, w = tid >> 5;

    float4 x = ((const float4*)(X + (size_t)m * D_))[tid];
    ((float4*)xrow)[tid] = x;

    float xs[4] = {x.x, x.y, x.z, x.w};
    __nv_bfloat16 h[4], l[4];
    #pragma unroll
    for (int i = 0; i < 4; i++) {
        h[i] = __float2bfloat16(xs[i]);
        l[i] = __float2bfloat16(xs[i] - __bfloat162float(h[i]));
    }
    size_t base = (size_t)m * KSRC + tid * 4;
    *(__nv_bfloat162*)&g_xcat[base]      = __nv_bfloat162(h[0], h[1]);
    *(__nv_bfloat162*)&g_xcat[base+2]    = __nv_bfloat162(h[2], h[3]);
    *(__nv_bfloat162*)&g_xcat[base+1024] = __nv_bfloat162(l[0], l[1]);
    *(__nv_bfloat162*)&g_xcat[base+1026] = __nv_bfloat162(l[2], l[3]);
    __syncthreads();

    #pragma unroll
    for (int cc = 0; cc < 2; cc++) {
        int c = w * 2 + cc;
        const float* A = (c < 8) ? Aq : Av;
        int col = c & 7;
        float s = 0.f;
        for (int k = lane; k < D_; k += 32)
            s += xrow[k] * A[k * R_ + col];
        #pragma unroll
        for (int off = 16; off; off >>= 1)
            s += __shfl_down_sync(0xffffffffu, s, off);
        if (lane == 0) {
            float* XA = (c < 8) ? g_xaq : g_xav;
            XA[m * R_ + col] = s;
        }
    }
}

// ---------------- transpose + split weights ------------------------------------
__global__ void split_wt_kernel(const float* __restrict__ W0, const float* __restrict__ W1,
                                const float* __restrict__ W2, const float* __restrict__ W3) {
    const float* Ws[4] = {W0, W1, W2, W3};
    const float* W = Ws[blockIdx.z];
    __shared__ float tile[32][33];
    int bx = blockIdx.x * 32, by = blockIdx.y * 32;
    for (int i = threadIdx.y; i < 32; i += 8)
        tile[i][threadIdx.x] = W[(size_t)(by + i) * D_ + bx + threadIdx.x];
    __syncthreads();
    for (int i = threadIdx.y; i < 32; i += 8) {
        int n = bx + i, k = by + threadIdx.x;
        float x = tile[threadIdx.x][i];
        __nv_bfloat16 h = __float2bfloat16(x);
        __nv_bfloat16 l = __float2bfloat16(x - __bfloat162float(h));
        __nv_bfloat16* out = (blockIdx.z < 3)
            ? g_wtqkv + (size_t)(blockIdx.z * 1024 + n) * KSRC
            : g_wto   + (size_t)n * KSRC;
        out[k]        = h;
        out[1024 + k] = l;
    }
}

// ================= fused HMMA split-bf16 GEMM (128x256 tile, 512 thr) ==========
// 48 virtual chunks: c<16 -> A:hi B:hi ; 16..31 -> A:hi B:lo ; >=32 -> A:lo B:hi
#define GSTG   49152
#define GA(s)  ((s) * GSTG)
#define GB(s)  ((s) * GSTG + 16384)
#define G_LB   147456
#define G_TOTAL 155648

__global__ void __launch_bounds__(512)
gemm_fused_kernel(const __nv_bfloat16* __restrict__ Acat,
                  const __nv_bfloat16* __restrict__ Bcat,
                  float* __restrict__ C, int qkv,
                  const float* __restrict__ Bq, const float* __restrict__ Bv)
{
    extern __shared__ char smem[];
    const uint32_t sbase = smem_u32(smem);
    const int tid  = threadIdx.x;
    const int lane = tid & 31;
    const int wid  = tid >> 5;
    const int wm   = wid & 1;
    const int wn   = wid >> 1;
    const int row0 = blockIdx.y * 128, col0 = blockIdx.x * 256;

    float acc[4][4][4];
    #pragma unroll
    for (int i = 0; i < 4; i++)
        #pragma unroll
        for (int j = 0; j < 4; j++)
            #pragma unroll
            for (int r = 0; r < 4; r++) acc[i][j][r] = 0.f;

    auto prefetch = [&](int c, int stg) {
        const int cm  = (c & 15) * 64;
        const int kbA = cm + ((c >= 32) ? 1024 : 0);
        const int kbB = cm + ((c >= 16 && c < 32) ? 1024 : 0);
        #pragma unroll
        for (int i = 0; i < 2; i++) {
            int idx = i * 512 + tid;
            int r = idx >> 3, cc = idx & 7;
            uint32_t off = r * 128 + (((uint32_t)(cc * 16)) ^ ((r & 7) << 4));
            cpa16(sbase + GA(stg) + off, Acat + (size_t)(row0 + r) * KSRC + kbA + cc * 8);
        }
        #pragma unroll
        for (int i = 0; i < 4; i++) {
            int idx = i * 512 + tid;
            int r = idx >> 3, cc = idx & 7;
            uint32_t off = r * 128 + (((uint32_t)(cc * 16)) ^ ((r & 7) << 4));
            cpa16(sbase + GB(stg) + off, Bcat + (size_t)(col0 + r) * KSRC + kbB + cc * 8);
        }
    };

    prefetch(0, 0); CP_COMMIT();
    prefetch(1, 1); CP_COMMIT();

    int sc = 0, s2 = 2;
    for (int c = 0; c < NCHUNK; c++) {
        CP_WAIT1();
        __syncthreads();
        if (c + 2 < NCHUNK) prefetch(c + 2, s2);
        CP_COMMIT();
        const uint32_t sa = sbase + GA(sc);
        const uint32_t sb = sbase + GB(sc);
        #pragma unroll
        for (int ks = 0; ks < 4; ks++) {
            uint32_t af[4][4], bfr[2][4];
            #pragma unroll
            for (int ma = 0; ma < 4; ma++) {
                int r = wm * 64 + ma * 16 + (lane & 15);
                uint32_t off = (uint32_t)(ks * 32 + ((lane >> 4) << 4));
                ldsm_x4(af[ma], sa + r * 128 + (off ^ ((r & 7) << 4)));
            }
            #pragma unroll
            for (int nb = 0; nb < 2; nb++) {
                int r = wn * 32 + nb * 16 + ((lane >> 4) << 3) + (lane & 7);
                uint32_t off = (uint32_t)(ks * 32 + (((lane >> 3) & 1) << 4));
                ldsm_x4(bfr[nb], sb + r * 128 + (off ^ ((r & 7) << 4)));
            }
            #pragma unroll
            for (int ma = 0; ma < 4; ma++)
                #pragma unroll
                for (int na = 0; na < 4; na++)
                    mma16816(acc[ma][na], af[ma],
                             bfr[na >> 1][(na & 1) * 2], bfr[na >> 1][(na & 1) * 2 + 1]);
        }
        sc = (sc == 2) ? 0 : sc + 1;
        s2 = (s2 == 2) ? 0 : s2 + 1;
    }
    __syncthreads();

    const int region = qkv ? (col0 >> 10) : 3;
    const float* XA = (region == 0) ? g_xaq : (region == 2) ? g_xav : nullptr;
    float* LBs = (float*)(smem + G_LB);
    if (qkv && region != 1) {
        const float* Bsrc = (region == 0) ? Bq : Bv;
        const int cbase = col0 & 1023;
        #pragma unroll
        for (int i = 0; i < 4; i++) {
            int idx = i * 512 + tid;
            LBs[idx] = Bsrc[(idx >> 8) * D_ + cbase + (idx & 255)];
        }
        __syncthreads();
    }

    #pragma unroll
    for (int ma = 0; ma < 4; ma++) {
        const int mlo = row0 + wm * 64 + ma * 16 + (lane >> 2);
        const int mhi = mlo + 8;
        float xal[8], xah[8];
        if (XA) {
            #pragma unroll
            for (int r = 0; r < R_; r++) {
                xal[r] = XA[mlo * R_ + r];
                xah[r] = XA[mhi * R_ + r];
            }
        }
        const int tlo = mlo & (T_ - 1), thi = mhi & (T_ - 1);
        #pragma unroll
        for (int na = 0; na < 4; na++) {
            const int n  = col0 + wn * 32 + na * 8 + (lane & 3) * 2;
            const int nl = n - col0;
            float v0 = acc[ma][na][0], v1 = acc[ma][na][1];
            float v2 = acc[ma][na][2], v3 = acc[ma][na][3];
            if (XA) {
                float s0 = 0.f, s1 = 0.f, s2_ = 0.f, s3 = 0.f;
                #pragma unroll
                for (int r = 0; r < R_; r++) {
                    float b0 = LBs[r * 256 + nl], b1 = LBs[r * 256 + nl + 1];
                    s0 += xal[r] * b0; s1 += xal[r] * b1;
                    s2_ += xah[r] * b0; s3 += xah[r] * b1;
                }
                v0 += LORA_SCALE * s0; v1 += LORA_SCALE * s1;
                v2 += LORA_SCALE * s2_; v3 += LORA_SCALE * s3;
            }
            if (region <= 1) {              // RoPE for Q and K
                const int jj = (n & 63) >> 1;
                float sn = g_sin[tlo * 32 + jj], cs = g_cos[tlo * 32 + jj];
                float e = v0, o = v1;
                v0 = e * cs - o * sn; v1 = e * sn + o * cs;
                sn = g_sin[thi * 32 + jj]; cs = g_cos[thi * 32 + jj];
                e = v2; o = v3;
                v2 = e * cs - o * sn; v3 = e * sn + o * cs;
            }
            if (region == 0) { v0 *= QSCALE; v1 *= QSCALE; v2 *= QSCALE; v3 *= QSCALE; }
            if (!qkv) {
                *(float2*)&C[(size_t)mlo * D_ + n] = make_float2(v0, v1);
                *(float2*)&C[(size_t)mhi * D_ + n] = make_float2(v2, v3);
            } else {
                __nv_bfloat16* Chi = (region == 0) ? g_qhi : (region == 1) ? g_khi : g_vhi;
                __nv_bfloat16* Clo = (region == 0) ? g_qlo : (region == 1) ? g_klo : g_vlo;
                const int bq = mlo >> 11, hh = (n & 1023) >> 6, dd = n & 63;
                size_t olo = ((size_t)(bq * H_ + hh) * T_ + tlo) * DH_ + dd;
                size_t ohi = ((size_t)(bq * H_ + hh) * T_ + thi) * DH_ + dd;
                __nv_bfloat16 h0 = __float2bfloat16(v0), h1 = __float2bfloat16(v1);
                __nv_bfloat16 h2 = __float2bfloat16(v2), h3 = __float2bfloat16(v3);
                *(__nv_bfloat162*)&Chi[olo] = __nv_bfloat162(h0, h1);
                *(__nv_bfloat162*)&Chi[ohi] = __nv_bfloat162(h2, h3);
                *(__nv_bfloat162*)&Clo[olo] = __nv_bfloat162(
                    __float2bfloat16(v0 - __bfloat162float(h0)),
                    __float2bfloat16(v1 - __bfloat162float(h1)));
                *(__nv_bfloat162*)&Clo[ohi] = __nv_bfloat162(
                    __float2bfloat16(v2 - __bfloat162float(h2)),
                    __float2bfloat16(v3 - __bfloat162float(h3)));
            }
        }
    }
}

// ================= tensor-core flash attention =================================
// 64KB SMEM (Q region reused as KV buffer 1) -> 2 CTAs/SM with 100% carveout.
#define AQ_HI 0
#define AQ_LO 16384
#define ATILE(buf) ((buf) ? 0 : 32768)       // KHI | KLO | VHI | VLO (8KB each)
#define A_SMEM 65536

__global__ void __launch_bounds__(256, 2)
attn_mma_kernel() {
    extern __shared__ char smem[];
    const uint32_t sbs = smem_u32(smem);
    const int tid = threadIdx.x, lane = tid & 31, w = tid >> 5;
    const int qb = gridDim.x - 1 - blockIdx.x;
    const int h = blockIdx.y, b = blockIdx.z;
    const int bh = b * H_ + h;
    const __nv_bfloat16* qhi = g_qhi + (size_t)bh * T_ * DH_;
    const __nv_bfloat16* qlo = g_qlo + (size_t)bh * T_ * DH_;
    const __nv_bfloat16* khi = g_khi + (size_t)bh * T_ * DH_;
    const __nv_bfloat16* klo = g_klo + (size_t)bh * T_ * DH_;
    const __nv_bfloat16* vhi = g_vhi + (size_t)bh * T_ * DH_;
    const __nv_bfloat16* vlo = g_vlo + (size_t)bh * T_ * DH_;

    {
        const __nv_bfloat16* sq = qhi + (size_t)(qb * 128) * DH_;
        const __nv_bfloat16* sl = qlo + (size_t)(qb * 128) * DH_;
        #pragma unroll
        for (int i = 0; i < 4; i++) {
            int idx = i * 256 + tid;
            int r = idx >> 3, c = idx & 7;
            uint32_t off = r * 128 + (((uint32_t)(c * 16)) ^ ((r & 7) << 4));
            *(uint4*)(smem + AQ_HI + off) = *((const uint4*)(sq + r * DH_) + c);
            *(uint4*)(smem + AQ_LO + off) = *((const uint4*)(sl + r * DH_) + c);
        }
    }
    __syncthreads();

    uint32_t qf[2][4][4];
    #pragma unroll
    for (int s = 0; s < 2; s++) {
        const uint32_t base = sbs + (s ? AQ_LO : AQ_HI);
        #pragma unroll
        for (int ks = 0; ks < 4; ks++) {
            int tsel = lane >> 3;
            int r = 16 * w + (lane & 7) + (tsel & 1) * 8;
            uint32_t off = ((uint32_t)(ks * 32 + ((tsel >> 1) & 1) * 16)) ^ ((r & 7) << 4);
            ldsm_x4(qf[s][ks], base + r * 128 + off);
        }
    }

    auto prefetch = [&](int c, int buf) {
        const int k0 = c * 64;
        const uint32_t tb = sbs + ATILE(buf);
        #pragma unroll
        for (int i = 0; i < 2; i++) {
            int idx = i * 256 + tid;
            int r = idx >> 3, cc = idx & 7;
            uint32_t off = r * 128 + (((uint32_t)(cc * 16)) ^ ((r & 7) << 4));
            const size_t g = (size_t)(k0 + r) * DH_ + cc * 8;
            cpa16(tb + off,         khi + g);
            cpa16(tb + 8192 + off,  klo + g);
            cpa16(tb + 16384 + off, vhi + g);
            cpa16(tb + 24576 + off, vlo + g);
        }
    };

    const int nch = 2 * qb + 2;
    prefetch(0, 0); CP_COMMIT();          // buf0 does NOT overlap Q region

    float o[8][4];
    #pragma unroll
    for (int j = 0; j < 8; j++)
        #pragma unroll
        for (int r = 0; r < 4; r++) o[j][r] = 0.f;
    float m0 = -1e30f, m1 = -1e30f, l0 = 0.f, l1 = 0.f;

    const int wrow0 = qb * 128 + 16 * w;
    const int r0 = wrow0 + (lane >> 2), r1 = r0 + 8;

    for (int c = 0; c < nch; c++) {
        const int buf = c & 1;
        CP_WAIT0();
        __syncthreads();                   // chunk c visible; Q reads / buf^1 done
        if (c + 1 < nch) { prefetch(c + 1, buf ^ 1); CP_COMMIT(); }

        const int k0 = c * 64;
        const uint32_t skh = sbs + ATILE(buf);
        const uint32_t skl = skh + 8192;
        const uint32_t svh = skh + 16384;
        const uint32_t svl = skh + 24576;

        #pragma unroll
        for (int hb = 0; hb < 2; hb++) {
            const int kb0 = k0 + hb * 32;
            if (kb0 > wrow0 + 15) break;

            float s[4][4];
            #pragma unroll
            for (int j = 0; j < 4; j++)
                #pragma unroll
                for (int r = 0; r < 4; r++) s[j][r] = 0.f;

            #pragma unroll
            for (int ks = 0; ks < 4; ks++) {
                #pragma unroll
                for (int jp = 0; jp < 2; jp++) {
                    uint32_t bh_[4], bl_[4];
                    int rr = hb * 32 + jp * 16 + ((lane >> 4) << 3) + (lane & 7);
                    uint32_t off = ((uint32_t)(ks * 32 + (((lane >> 3) & 1) << 4)))
                                   ^ ((rr & 7) << 4);
                    ldsm_x4(bh_, skh + rr * 128 + off);
                    ldsm_x4(bl_, skl + rr * 128 + off);
                    mma16816(s[2*jp],   qf[0][ks], bh_[0], bh_[1]);
                    mma16816(s[2*jp],   qf[0][ks], bl_[0], bl_[1]);
                    mma16816(s[2*jp],   qf[1][ks], bh_[0], bh_[1]);
                    mma16816(s[2*jp+1], qf[0][ks], bh_[2], bh_[3]);
                    mma16816(s[2*jp+1], qf[0][ks], bl_[2], bl_[3]);
                    mma16816(s[2*jp+1], qf[1][ks], bh_[2], bh_[3]);
                }
            }

            if (kb0 + 31 > wrow0) {
                #pragma unroll
                for (int j = 0; j < 4; j++) {
                    int col = kb0 + 8 * j + 2 * (lane & 3);
                    if (col     > r0) s[j][0] = -1e30f;
                    if (col + 1 > r0) s[j][1] = -1e30f;
                    if (col     > r1) s[j][2] = -1e30f;
                    if (col + 1 > r1) s[j][3] = -1e30f;
                }
            }

            float mx0 = -1e30f, mx1 = -1e30f;
            #pragma unroll
            for (int j = 0; j < 4; j++) {
                mx0 = fmaxf(mx0, fmaxf(s[j][0], s[j][1]));
                mx1 = fmaxf(mx1, fmaxf(s[j][2], s[j][3]));
            }
            mx0 = fmaxf(mx0, __shfl_xor_sync(0xffffffffu, mx0, 1));
            mx0 = fmaxf(mx0, __shfl_xor_sync(0xffffffffu, mx0, 2));
            mx1 = fmaxf(mx1, __shfl_xor_sync(0xffffffffu, mx1, 1));
            mx1 = fmaxf(mx1, __shfl_xor_sync(0xffffffffu, mx1, 2));
            float mn0 = fmaxf(m0, mx0), mn1 = fmaxf(m1, mx1);
            bool nochg = __all_sync(0xffffffffu, (mn0 == m0) && (mn1 == m1));
            if (!nochg) {
                float cr0 = ex2f(m0 - mn0), cr1 = ex2f(m1 - mn1);
                l0 *= cr0; l1 *= cr1;
                #pragma unroll
                for (int j = 0; j < 8; j++) {
                    o[j][0] *= cr0; o[j][1] *= cr0;
                    o[j][2] *= cr1; o[j][3] *= cr1;
                }
                m0 = mn0; m1 = mn1;
            }

            uint32_t ph[4][2], pl[4][2];
            #pragma unroll
            for (int j = 0; j < 4; j++) {
                float p0 = ex2f(s[j][0] - m0), p1 = ex2f(s[j][1] - m0);
                float p2 = ex2f(s[j][2] - m1), p3 = ex2f(s[j][3] - m1);
                l0 += p0 + p1; l1 += p2 + p3;
                __nv_bfloat16 b0 = __float2bfloat16(p0), b1 = __float2bfloat16(p1);
                __nv_bfloat16 b2 = __float2bfloat16(p2), b3 = __float2bfloat16(p3);
                ph[j][0] = pack_bf16x2(__bfloat162float(b0), __bfloat162float(b1));
                ph[j][1] = pack_bf16x2(__bfloat162float(b2), __bfloat162float(b3));
                pl[j][0] = pack_bf16x2(p0 - __bfloat162float(b0), p1 - __bfloat162float(b1));
                pl[j][1] = pack_bf16x2(p2 - __bfloat162float(b2), p3 - __bfloat162float(b3));
            }

            #pragma unroll
            for (int kk = 0; kk < 2; kk++) {
                uint32_t ahi[4] = {ph[2*kk][0], ph[2*kk][1], ph[2*kk+1][0], ph[2*kk+1][1]};
                uint32_t alo[4] = {pl[2*kk][0], pl[2*kk][1], pl[2*kk+1][0], pl[2*kk+1][1]};
                #pragma unroll
                for (int jp = 0; jp < 4; jp++) {
                    uint32_t vh_[4], vl_[4];
                    int tsel = lane >> 3;
                    int key = hb * 32 + 16 * kk + (tsel & 1) * 8 + (lane & 7);
                    uint32_t off = ((uint32_t)((16 * jp + ((tsel >> 1) & 1) * 8) * 2))
                                   ^ ((key & 7) << 4);
                    ldsm_x4_t(vh_, svh + key * 128 + off);
                    ldsm_x4_t(vl_, svl + key * 128 + off);
                    mma16816(o[2*jp],   ahi, vh_[0], vh_[1]);
                    mma16816(o[2*jp],   ahi, vl_[0], vl_[1]);
                    mma16816(o[2*jp],   alo, vh_[0], vh_[1]);
                    mma16816(o[2*jp+1], ahi, vh_[2], vh_[3]);
                    mma16816(o[2*jp+1], ahi, vl_[2], vl_[3]);
                    mma16816(o[2*jp+1], alo, vh_[2], vh_[3]);
                }
            }
        }
    }

    l0 += __shfl_xor_sync(0xffffffffu, l0, 1);
    l0 += __shfl_xor_sync(0xffffffffu, l0, 2);
    l1 += __shfl_xor_sync(0xffffffffu, l1, 1);
    l1 += __shfl_xor_sync(0xffffffffu, l1, 2);
    const float i0 = 1.f / l0, i1 = 1.f / l1;

    const int tok0 = b * T_ + r0, tok1 = b * T_ + r1;
    #pragma unroll
    for (int j = 0; j < 8; j++) {
        const int n = h * DH_ + 8 * j + 2 * (lane & 3);
        float v0 = o[j][0] * i0, v1 = o[j][1] * i0;
        float v2 = o[j][2] * i1, v3 = o[j][3] * i1;
        __nv_bfloat16 h0 = __float2bfloat16(v0), h1 = __float2bfloat16(v1);
        __nv_bfloat16 h2 = __float2bfloat16(v2), h3 = __float2bfloat16(v3);
        __nv_bfloat162 hi0(h0, h1), hi1(h2, h3);
        __nv_bfloat162 lo0(__float2bfloat16(v0 - __bfloat162float(h0)),
                           __float2bfloat16(v1 - __bfloat162float(h1)));
        __nv_bfloat162 lo1(__float2bfloat16(v2 - __bfloat162float(h2)),
                           __float2bfloat16(v3 - __bfloat162float(h3)));
        size_t p0 = (size_t)tok0 * KSRC + n;
        size_t p1 = (size_t)tok1 * KSRC + n;
        *(__nv_bfloat162*)&g_aocat[p0]        = hi0;
        *(__nv_bfloat162*)&g_aocat[p0 + 1024] = lo0;
        *(__nv_bfloat162*)&g_aocat[p1]        = hi1;
        *(__nv_bfloat162*)&g_aocat[p1 + 1024] = lo1;
    }
}

// ---------------- launch --------------------------------------------------------
extern "C" void kernel_launch(void* const* d_in, const int* in_sizes, int n_in,
                              void* d_out, int out_size) {
    const float* X  = (const float*)d_in[0];
    const float* wq = (const float*)d_in[1];
    const float* wk = (const float*)d_in[2];
    const float* wv = (const float*)d_in[3];
    const float* wo = (const float*)d_in[4];
    const float* Aq = (const float*)d_in[5];
    const float* Bq = (const float*)d_in[6];
    const float* Av = (const float*)d_in[7];
    const float* Bv = (const float*)d_in[8];
    float* out = (float*)d_out;

    __nv_bfloat16 *xcat, *aocat, *wtqkv, *wto;
    cudaGetSymbolAddress((void**)&xcat,  g_xcat);
    cudaGetSymbolAddress((void**)&aocat, g_aocat);
    cudaGetSymbolAddress((void**)&wtqkv, g_wtqkv);
    cudaGetSymbolAddress((void**)&wto,   g_wto);

    cudaFuncSetAttribute(gemm_fused_kernel,
                         cudaFuncAttributeMaxDynamicSharedMemorySize, G_TOTAL);
    cudaFuncSetAttribute(attn_mma_kernel,
                         cudaFuncAttributeMaxDynamicSharedMemorySize, A_SMEM);
    cudaFuncSetAttribute(attn_mma_kernel,
                         cudaFuncAttributePreferredSharedMemoryCarveout, 100);

    sincos_kernel<<<(T_*32 + 255) / 256, 256>>>();
    lora_split_kernel<<<MTOT, 256>>>(X, Aq, Av);
    split_wt_kernel<<<dim3(32, 32, 4), dim3(32, 8)>>>(wq, wk, wv, wo);

    gemm_fused_kernel<<<dim3(12, 64), 512, G_TOTAL>>>(xcat, wtqkv, nullptr, 1, Bq, Bv);

    attn_mma_kernel<<<dim3(T_ / 128, H_, B_), 256, A_SMEM>>>();

    gemm_fused_kernel<<<dim3(4, 64), 512, G_TOTAL>>>(aocat, wto, out, 0, nullptr, nullptr);
}

// round 11
// speedup vs baseline: 3.7069x; 1.0737x over previous
#include <cuda_runtime.h>
#include <cuda_bf16.h>
#include <math.h>
#include <cstdint>

#define B_   4
#define T_   2048
#define D_   1024
#define H_   16
#define DH_  64
#define R_   8
#define MTOT (B_*T_)          // 8192
#define KSRC 2048             // stored split width: [hi | lo]
#define NCHUNK 48             // 3 terms x 16 chunks of 64
#define LORA_SCALE 4.0f
#define QSCALE 0.180336880f   // 0.125 * log2(e)  — exp2-domain logits

// ---------------- scratch (device globals: no allocation allowed) -------------
__device__ float g_xaq[MTOT*R_];
__device__ float g_xav[MTOT*R_];
__device__ float g_sin[T_*32];
__device__ float g_cos[T_*32];
__device__ __nv_bfloat16 g_xcat [MTOT*KSRC];       // [Xhi | Xlo]
__device__ __nv_bfloat16 g_aocat[MTOT*KSRC];       // attention out [hi | lo]
__device__ __nv_bfloat16 g_wtqkv[3072ull*KSRC];    // rows n of [wq|wk|wv], k = [hi|lo]
__device__ __nv_bfloat16 g_wto  [(size_t)D_*KSRC];
// head-major [b,h,t,dh] bf16 split pairs
__device__ __nv_bfloat16 g_qhi[MTOT*D_];
__device__ __nv_bfloat16 g_qlo[MTOT*D_];
__device__ __nv_bfloat16 g_khi[MTOT*D_];
__device__ __nv_bfloat16 g_klo[MTOT*D_];
__device__ __nv_bfloat16 g_vhi[MTOT*D_];
__device__ __nv_bfloat16 g_vlo[MTOT*D_];

// ---------------- warp-level MMA helpers ---------------------------------------
__device__ __forceinline__ uint32_t smem_u32(const void* p) {
    uint32_t a;
    asm("{ .reg .u64 t; cvta.to.shared.u64 t, %1; cvt.u32.u64 %0, t; }" : "=r"(a) : "l"(p));
    return a;
}
__device__ __forceinline__ void ldsm_x4(uint32_t* r, uint32_t addr) {
    asm volatile("ldmatrix.sync.aligned.m8n8.x4.shared.b16 {%0,%1,%2,%3}, [%4];"
                 : "=r"(r[0]), "=r"(r[1]), "=r"(r[2]), "=r"(r[3]) : "r"(addr));
}
__device__ __forceinline__ void ldsm_x4_t(uint32_t* r, uint32_t addr) {
    asm volatile("ldmatrix.sync.aligned.m8n8.x4.trans.shared.b16 {%0,%1,%2,%3}, [%4];"
                 : "=r"(r[0]), "=r"(r[1]), "=r"(r[2]), "=r"(r[3]) : "r"(addr));
}
__device__ __forceinline__ void mma16816(float* d, const uint32_t* a,
                                         uint32_t b0, uint32_t b1) {
    asm volatile("mma.sync.aligned.m16n8k16.row.col.f32.bf16.bf16.f32 "
                 "{%0,%1,%2,%3}, {%4,%5,%6,%7}, {%8,%9}, {%0,%1,%2,%3};"
                 : "+f"(d[0]), "+f"(d[1]), "+f"(d[2]), "+f"(d[3])
                 : "r"(a[0]), "r"(a[1]), "r"(a[2]), "r"(a[3]), "r"(b0), "r"(b1));
}
__device__ __forceinline__ uint32_t pack_bf16x2(float e, float o) {
    uint32_t d;
    asm("cvt.rn.bf16x2.f32 %0, %1, %2;" : "=r"(d) : "f"(o), "f"(e));
    return d;
}
__device__ __forceinline__ float ex2f(float x) {
    float r;
    asm("ex2.approx.ftz.f32 %0, %1;" : "=f"(r) : "f"(x));
    return r;
}
__device__ __forceinline__ void cpa16(uint32_t dst, const void* src) {
    asm volatile("cp.async.cg.shared.global [%0], [%1], 16;" :: "r"(dst), "l"(src) : "memory");
}
#define CP_COMMIT() asm volatile("cp.async.commit_group;" ::: "memory")
#define CP_WAIT1()  asm volatile("cp.async.wait_group 1;"  ::: "memory")
#define CP_WAIT0()  asm volatile("cp.async.wait_group 0;"  ::: "memory")

// ---------------- sin/cos table -----------------------------------------------
__global__ void sincos_kernel() {
    int idx = blockIdx.x * blockDim.x + threadIdx.x;
    if (idx >= T_*32) return;
    int t = idx >> 5, j = idx & 31;
    double theta = (double)t / pow(10000.0, (double)j / 32.0);
    g_sin[idx] = (float)sin(theta);
    g_cos[idx] = (float)cos(theta);
}

// ---------------- fused LoRA down-proj + X split --------------------------------
__global__ void lora_split_kernel(const float* __restrict__ X,
                                  const float* __restrict__ Aq,
                                  const float* __restrict__ Av) {
    __shared__ float xrow[1024];
    const int m = blockIdx.x;
    const int tid = threadIdx.x;
    const int lane = tid & 31, w = tid >> 5;

    float4 x = ((const float4*)(X + (size_t)m * D_))[tid];
    ((float4*)xrow)[tid] = x;

    float xs[4] = {x.x, x.y, x.z, x.w};
    __nv_bfloat16 h[4], l[4];
    #pragma unroll
    for (int i = 0; i < 4; i++) {
        h[i] = __float2bfloat16(xs[i]);
        l[i] = __float2bfloat16(xs[i] - __bfloat162float(h[i]));
    }
    size_t base = (size_t)m * KSRC + tid * 4;
    *(__nv_bfloat162*)&g_xcat[base]      = __nv_bfloat162(h[0], h[1]);
    *(__nv_bfloat162*)&g_xcat[base+2]    = __nv_bfloat162(h[2], h[3]);
    *(__nv_bfloat162*)&g_xcat[base+1024] = __nv_bfloat162(l[0], l[1]);
    *(__nv_bfloat162*)&g_xcat[base+1026] = __nv_bfloat162(l[2], l[3]);
    __syncthreads();

    #pragma unroll
    for (int cc = 0; cc < 2; cc++) {
        int c = w * 2 + cc;
        const float* A = (c < 8) ? Aq : Av;
        int col = c & 7;
        float s = 0.f;
        for (int k = lane; k < D_; k += 32)
            s += xrow[k] * A[k * R_ + col];
        #pragma unroll
        for (int off = 16; off; off >>= 1)
            s += __shfl_down_sync(0xffffffffu, s, off);
        if (lane == 0) {
            float* XA = (c < 8) ? g_xaq : g_xav;
            XA[m * R_ + col] = s;
        }
    }
}

// ---------------- transpose + split weights ------------------------------------
__global__ void split_wt_kernel(const float* __restrict__ W0, const float* __restrict__ W1,
                                const float* __restrict__ W2, const float* __restrict__ W3) {
    const float* Ws[4] = {W0, W1, W2, W3};
    const float* W = Ws[blockIdx.z];
    __shared__ float tile[32][33];
    int bx = blockIdx.x * 32, by = blockIdx.y * 32;
    for (int i = threadIdx.y; i < 32; i += 8)
        tile[i][threadIdx.x] = W[(size_t)(by + i) * D_ + bx + threadIdx.x];
    __syncthreads();
    for (int i = threadIdx.y; i < 32; i += 8) {
        int n = bx + i, k = by + threadIdx.x;
        float x = tile[threadIdx.x][i];
        __nv_bfloat16 h = __float2bfloat16(x);
        __nv_bfloat16 l = __float2bfloat16(x - __bfloat162float(h));
        __nv_bfloat16* out = (blockIdx.z < 3)
            ? g_wtqkv + (size_t)(blockIdx.z * 1024 + n) * KSRC
            : g_wto   + (size_t)n * KSRC;
        out[k]        = h;
        out[1024 + k] = l;
    }
}

// ================= fused HMMA split-bf16 GEMM (128x128 tile, 256 thr) ==========
// 2 CTAs/SM (regs<=128, smem 100KB). 3-stage cp.async ring, single sync/chunk.
// 48 virtual chunks: c<16 -> A:hi B:hi ; 16..31 -> A:hi B:lo ; >=32 -> A:lo B:hi
#define GSTG   32768
#define GA(s)  ((s) * GSTG)
#define GB(s)  ((s) * GSTG + 16384)
#define G_LB   98304
#define G_TOTAL 102400

__global__ void __launch_bounds__(256, 2)
gemm_fused_kernel(const __nv_bfloat16* __restrict__ Acat,
                  const __nv_bfloat16* __restrict__ Bcat,
                  float* __restrict__ C, int qkv,
                  const float* __restrict__ Bq, const float* __restrict__ Bv)
{
    extern __shared__ char smem[];
    const uint32_t sbase = smem_u32(smem);
    const int tid  = threadIdx.x;
    const int lane = tid & 31;
    const int wid  = tid >> 5;          // 0..7
    const int wm   = wid & 1;           // 2 x 64 rows
    const int wn   = wid >> 1;          // 4 x 32 cols
    const int row0 = blockIdx.y * 128, col0 = blockIdx.x * 128;

    float acc[4][4][4];
    #pragma unroll
    for (int i = 0; i < 4; i++)
        #pragma unroll
        for (int j = 0; j < 4; j++)
            #pragma unroll
            for (int r = 0; r < 4; r++) acc[i][j][r] = 0.f;

    auto prefetch = [&](int c, int stg) {
        const int cm  = (c & 15) * 64;
        const int kbA = cm + ((c >= 32) ? 1024 : 0);
        const int kbB = cm + ((c >= 16 && c < 32) ? 1024 : 0);
        #pragma unroll
        for (int i = 0; i < 4; i++) {        // A: 1024 x 16B
            int idx = i * 256 + tid;
            int r = idx >> 3, cc = idx & 7;
            uint32_t off = r * 128 + (((uint32_t)(cc * 16)) ^ ((r & 7) << 4));
            cpa16(sbase + GA(stg) + off, Acat + (size_t)(row0 + r) * KSRC + kbA + cc * 8);
        }
        #pragma unroll
        for (int i = 0; i < 4; i++) {        // B: 1024 x 16B
            int idx = i * 256 + tid;
            int r = idx >> 3, cc = idx & 7;
            uint32_t off = r * 128 + (((uint32_t)(cc * 16)) ^ ((r & 7) << 4));
            cpa16(sbase + GB(stg) + off, Bcat + (size_t)(col0 + r) * KSRC + kbB + cc * 8);
        }
    };

    prefetch(0, 0); CP_COMMIT();
    prefetch(1, 1); CP_COMMIT();

    int sc = 0, s2 = 2;
    for (int c = 0; c < NCHUNK; c++) {
        CP_WAIT1();
        __syncthreads();
        if (c + 2 < NCHUNK) prefetch(c + 2, s2);
        CP_COMMIT();
        const uint32_t sa = sbase + GA(sc);
        const uint32_t sb = sbase + GB(sc);
        #pragma unroll
        for (int ks = 0; ks < 4; ks++) {
            uint32_t af[4][4], bfr[2][4];
            #pragma unroll
            for (int ma = 0; ma < 4; ma++) {
                int r = wm * 64 + ma * 16 + (lane & 15);
                uint32_t off = (uint32_t)(ks * 32 + ((lane >> 4) << 4));
                ldsm_x4(af[ma], sa + r * 128 + (off ^ ((r & 7) << 4)));
            }
            #pragma unroll
            for (int nb = 0; nb < 2; nb++) {
                int r = wn * 32 + nb * 16 + ((lane >> 4) << 3) + (lane & 7);
                uint32_t off = (uint32_t)(ks * 32 + (((lane >> 3) & 1) << 4));
                ldsm_x4(bfr[nb], sb + r * 128 + (off ^ ((r & 7) << 4)));
            }
            #pragma unroll
            for (int ma = 0; ma < 4; ma++)
                #pragma unroll
                for (int na = 0; na < 4; na++)
                    mma16816(acc[ma][na], af[ma],
                             bfr[na >> 1][(na & 1) * 2], bfr[na >> 1][(na & 1) * 2 + 1]);
        }
        sc = (sc == 2) ? 0 : sc + 1;
        s2 = (s2 == 2) ? 0 : s2 + 1;
    }
    __syncthreads();

    const int region = qkv ? (col0 >> 10) : 3;
    const float* XA = (region == 0) ? g_xaq : (region == 2) ? g_xav : nullptr;
    float* LBs = (float*)(smem + G_LB);
    if (qkv && region != 1) {
        const float* Bsrc = (region == 0) ? Bq : Bv;
        const int cbase = col0 & 1023;
        #pragma unroll
        for (int i = 0; i < 4; i++) {
            int idx = i * 256 + tid;
            LBs[idx] = Bsrc[(idx >> 7) * D_ + cbase + (idx & 127)];
        }
        __syncthreads();
    }

    #pragma unroll
    for (int ma = 0; ma < 4; ma++) {
        const int mlo = row0 + wm * 64 + ma * 16 + (lane >> 2);
        const int mhi = mlo + 8;
        float xal[8], xah[8];
        if (XA) {
            #pragma unroll
            for (int r = 0; r < R_; r++) {
                xal[r] = XA[mlo * R_ + r];
                xah[r] = XA[mhi * R_ + r];
            }
        }
        const int tlo = mlo & (T_ - 1), thi = mhi & (T_ - 1);
        #pragma unroll
        for (int na = 0; na < 4; na++) {
            const int n  = col0 + wn * 32 + na * 8 + (lane & 3) * 2;
            const int nl = n - col0;
            float v0 = acc[ma][na][0], v1 = acc[ma][na][1];
            float v2 = acc[ma][na][2], v3 = acc[ma][na][3];
            if (XA) {
                float s0 = 0.f, s1 = 0.f, s2_ = 0.f, s3 = 0.f;
                #pragma unroll
                for (int r = 0; r < R_; r++) {
                    float b0 = LBs[r * 128 + nl], b1 = LBs[r * 128 + nl + 1];
                    s0 += xal[r] * b0; s1 += xal[r] * b1;
                    s2_ += xah[r] * b0; s3 += xah[r] * b1;
                }
                v0 += LORA_SCALE * s0; v1 += LORA_SCALE * s1;
                v2 += LORA_SCALE * s2_; v3 += LORA_SCALE * s3;
            }
            if (region <= 1) {              // RoPE for Q and K
                const int jj = (n & 63) >> 1;
                float sn = g_sin[tlo * 32 + jj], cs = g_cos[tlo * 32 + jj];
                float e = v0, o = v1;
                v0 = e * cs - o * sn; v1 = e * sn + o * cs;
                sn = g_sin[thi * 32 + jj]; cs = g_cos[thi * 32 + jj];
                e = v2; o = v3;
                v2 = e * cs - o * sn; v3 = e * sn + o * cs;
            }
            if (region == 0) { v0 *= QSCALE; v1 *= QSCALE; v2 *= QSCALE; v3 *= QSCALE; }
            if (!qkv) {
                *(float2*)&C[(size_t)mlo * D_ + n] = make_float2(v0, v1);
                *(float2*)&C[(size_t)mhi * D_ + n] = make_float2(v2, v3);
            } else {
                __nv_bfloat16* Chi = (region == 0) ? g_qhi : (region == 1) ? g_khi : g_vhi;
                __nv_bfloat16* Clo = (region == 0) ? g_qlo : (region == 1) ? g_klo : g_vlo;
                const int bq = mlo >> 11, hh = (n & 1023) >> 6, dd = n & 63;
                size_t olo = ((size_t)(bq * H_ + hh) * T_ + tlo) * DH_ + dd;
                size_t ohi = ((size_t)(bq * H_ + hh) * T_ + thi) * DH_ + dd;
                __nv_bfloat16 h0 = __float2bfloat16(v0), h1 = __float2bfloat16(v1);
                __nv_bfloat16 h2 = __float2bfloat16(v2), h3 = __float2bfloat16(v3);
                *(__nv_bfloat162*)&Chi[olo] = __nv_bfloat162(h0, h1);
                *(__nv_bfloat162*)&Chi[ohi] = __nv_bfloat162(h2, h3);
                *(__nv_bfloat162*)&Clo[olo] = __nv_bfloat162(
                    __float2bfloat16(v0 - __bfloat162float(h0)),
                    __float2bfloat16(v1 - __bfloat162float(h1)));
                *(__nv_bfloat162*)&Clo[ohi] = __nv_bfloat162(
                    __float2bfloat16(v2 - __bfloat162float(h2)),
                    __float2bfloat16(v3 - __bfloat162float(h3)));
            }
        }
    }
}

// ================= tensor-core flash attention =================================
// 64KB SMEM (Q region reused as KV buffer 1) -> 2 CTAs/SM with 100% carveout.
#define AQ_HI 0
#define AQ_LO 16384
#define ATILE(buf) ((buf) ? 0 : 32768)       // KHI | KLO | VHI | VLO (8KB each)
#define A_SMEM 65536

__global__ void __launch_bounds__(256, 2)
attn_mma_kernel() {
    extern __shared__ char smem[];
    const uint32_t sbs = smem_u32(smem);
    const int tid = threadIdx.x, lane = tid & 31, w = tid >> 5;
    const int qb = gridDim.x - 1 - blockIdx.x;
    const int h = blockIdx.y, b = blockIdx.z;
    const int bh = b * H_ + h;
    const __nv_bfloat16* qhi = g_qhi + (size_t)bh * T_ * DH_;
    const __nv_bfloat16* qlo = g_qlo + (size_t)bh * T_ * DH_;
    const __nv_bfloat16* khi = g_khi + (size_t)bh * T_ * DH_;
    const __nv_bfloat16* klo = g_klo + (size_t)bh * T_ * DH_;
    const __nv_bfloat16* vhi = g_vhi + (size_t)bh * T_ * DH_;
    const __nv_bfloat16* vlo = g_vlo + (size_t)bh * T_ * DH_;

    {
        const __nv_bfloat16* sq = qhi + (size_t)(qb * 128) * DH_;
        const __nv_bfloat16* sl = qlo + (size_t)(qb * 128) * DH_;
        #pragma unroll
        for (int i = 0; i < 4; i++) {
            int idx = i * 256 + tid;
            int r = idx >> 3, c = idx & 7;
            uint32_t off = r * 128 + (((uint32_t)(c * 16)) ^ ((r & 7) << 4));
            *(uint4*)(smem + AQ_HI + off) = *((const uint4*)(sq + r * DH_) + c);
            *(uint4*)(smem + AQ_LO + off) = *((const uint4*)(sl + r * DH_) + c);
        }
    }
    __syncthreads();

    uint32_t qf[2][4][4];
    #pragma unroll
    for (int s = 0; s < 2; s++) {
        const uint32_t base = sbs + (s ? AQ_LO : AQ_HI);
        #pragma unroll
        for (int ks = 0; ks < 4; ks++) {
            int tsel = lane >> 3;
            int r = 16 * w + (lane & 7) + (tsel & 1) * 8;
            uint32_t off = ((uint32_t)(ks * 32 + ((tsel >> 1) & 1) * 16)) ^ ((r & 7) << 4);
            ldsm_x4(qf[s][ks], base + r * 128 + off);
        }
    }

    auto prefetch = [&](int c, int buf) {
        const int k0 = c * 64;
        const uint32_t tb = sbs + ATILE(buf);
        #pragma unroll
        for (int i = 0; i < 2; i++) {
            int idx = i * 256 + tid;
            int r = idx >> 3, cc = idx & 7;
            uint32_t off = r * 128 + (((uint32_t)(cc * 16)) ^ ((r & 7) << 4));
            const size_t g = (size_t)(k0 + r) * DH_ + cc * 8;
            cpa16(tb + off,         khi + g);
            cpa16(tb + 8192 + off,  klo + g);
            cpa16(tb + 16384 + off, vhi + g);
            cpa16(tb + 24576 + off, vlo + g);
        }
    };

    const int nch = 2 * qb + 2;
    prefetch(0, 0); CP_COMMIT();          // buf0 does NOT overlap Q region

    float o[8][4];
    #pragma unroll
    for (int j = 0; j < 8; j++)
        #pragma unroll
        for (int r = 0; r < 4; r++) o[j][r] = 0.f;
    float m0 = -1e30f, m1 = -1e30f, l0 = 0.f, l1 = 0.f;

    const int wrow0 = qb * 128 + 16 * w;
    const int r0 = wrow0 + (lane >> 2), r1 = r0 + 8;

    for (int c = 0; c < nch; c++) {
        const int buf = c & 1;
        CP_WAIT0();
        __syncthreads();                   // chunk c visible; Q reads / buf^1 done
        if (c + 1 < nch) { prefetch(c + 1, buf ^ 1); CP_COMMIT(); }

        const int k0 = c * 64;
        const uint32_t skh = sbs + ATILE(buf);
        const uint32_t skl = skh + 8192;
        const uint32_t svh = skh + 16384;
        const uint32_t svl = skh + 24576;

        #pragma unroll
        for (int hb = 0; hb < 2; hb++) {
            const int kb0 = k0 + hb * 32;
            if (kb0 > wrow0 + 15) break;

            float s[4][4];
            #pragma unroll
            for (int j = 0; j < 4; j++)
                #pragma unroll
                for (int r = 0; r < 4; r++) s[j][r] = 0.f;

            #pragma unroll
            for (int ks = 0; ks < 4; ks++) {
                #pragma unroll
                for (int jp = 0; jp < 2; jp++) {
                    uint32_t bh_[4], bl_[4];
                    int rr = hb * 32 + jp * 16 + ((lane >> 4) << 3) + (lane & 7);
                    uint32_t off = ((uint32_t)(ks * 32 + (((lane >> 3) & 1) << 4)))
                                   ^ ((rr & 7) << 4);
                    ldsm_x4(bh_, skh + rr * 128 + off);
                    ldsm_x4(bl_, skl + rr * 128 + off);
                    mma16816(s[2*jp],   qf[0][ks], bh_[0], bh_[1]);
                    mma16816(s[2*jp],   qf[0][ks], bl_[0], bl_[1]);
                    mma16816(s[2*jp],   qf[1][ks], bh_[0], bh_[1]);
                    mma16816(s[2*jp+1], qf[0][ks], bh_[2], bh_[3]);
                    mma16816(s[2*jp+1], qf[0][ks], bl_[2], bl_[3]);
                    mma16816(s[2*jp+1], qf[1][ks], bh_[2], bh_[3]);
                }
            }

            if (kb0 + 31 > wrow0) {
                #pragma unroll
                for (int j = 0; j < 4; j++) {
                    int col = kb0 + 8 * j + 2 * (lane & 3);
                    if (col     > r0) s[j][0] = -1e30f;
                    if (col + 1 > r0) s[j][1] = -1e30f;
                    if (col     > r1) s[j][2] = -1e30f;
                    if (col + 1 > r1) s[j][3] = -1e30f;
                }
            }

            float mx0 = -1e30f, mx1 = -1e30f;
            #pragma unroll
            for (int j = 0; j < 4; j++) {
                mx0 = fmaxf(mx0, fmaxf(s[j][0], s[j][1]));
                mx1 = fmaxf(mx1, fmaxf(s[j][2], s[j][3]));
            }
            mx0 = fmaxf(mx0, __shfl_xor_sync(0xffffffffu, mx0, 1));
            mx0 = fmaxf(mx0, __shfl_xor_sync(0xffffffffu, mx0, 2));
            mx1 = fmaxf(mx1, __shfl_xor_sync(0xffffffffu, mx1, 1));
            mx1 = fmaxf(mx1, __shfl_xor_sync(0xffffffffu, mx1, 2));
            float mn0 = fmaxf(m0, mx0), mn1 = fmaxf(m1, mx1);
            bool nochg = __all_sync(0xffffffffu, (mn0 == m0) && (mn1 == m1));
            if (!nochg) {
                float cr0 = ex2f(m0 - mn0), cr1 = ex2f(m1 - mn1);
                l0 *= cr0; l1 *= cr1;
                #pragma unroll
                for (int j = 0; j < 8; j++) {
                    o[j][0] *= cr0; o[j][1] *= cr0;
                    o[j][2] *= cr1; o[j][3] *= cr1;
                }
                m0 = mn0; m1 = mn1;
            }

            uint32_t ph[4][2], pl[4][2];
            #pragma unroll
            for (int j = 0; j < 4; j++) {
                float p0 = ex2f(s[j][0] - m0), p1 = ex2f(s[j][1] - m0);
                float p2 = ex2f(s[j][2] - m1), p3 = ex2f(s[j][3] - m1);
                l0 += p0 + p1; l1 += p2 + p3;
                __nv_bfloat16 b0 = __float2bfloat16(p0), b1 = __float2bfloat16(p1);
                __nv_bfloat16 b2 = __float2bfloat16(p2), b3 = __float2bfloat16(p3);
                ph[j][0] = pack_bf16x2(__bfloat162float(b0), __bfloat162float(b1));
                ph[j][1] = pack_bf16x2(__bfloat162float(b2), __bfloat162float(b3));
                pl[j][0] = pack_bf16x2(p0 - __bfloat162float(b0), p1 - __bfloat162float(b1));
                pl[j][1] = pack_bf16x2(p2 - __bfloat162float(b2), p3 - __bfloat162float(b3));
            }

            #pragma unroll
            for (int kk = 0; kk < 2; kk++) {
                uint32_t ahi[4] = {ph[2*kk][0], ph[2*kk][1], ph[2*kk+1][0], ph[2*kk+1][1]};
                uint32_t alo[4] = {pl[2*kk][0], pl[2*kk][1], pl[2*kk+1][0], pl[2*kk+1][1]};
                #pragma unroll
                for (int jp = 0; jp < 4; jp++) {
                    uint32_t vh_[4], vl_[4];
                    int tsel = lane >> 3;
                    int key = hb * 32 + 16 * kk + (tsel & 1) * 8 + (lane & 7);
                    uint32_t off = ((uint32_t)((16 * jp + ((tsel >> 1) & 1) * 8) * 2))
                                   ^ ((key & 7) << 4);
                    ldsm_x4_t(vh_, svh + key * 128 + off);
                    ldsm_x4_t(vl_, svl + key * 128 + off);
                    mma16816(o[2*jp],   ahi, vh_[0], vh_[1]);
                    mma16816(o[2*jp],   ahi, vl_[0], vl_[1]);
                    mma16816(o[2*jp],   alo, vh_[0], vh_[1]);
                    mma16816(o[2*jp+1], ahi, vh_[2], vh_[3]);
                    mma16816(o[2*jp+1], ahi, vl_[2], vl_[3]);
                    mma16816(o[2*jp+1], alo, vh_[2], vh_[3]);
                }
            }
        }
    }

    l0 += __shfl_xor_sync(0xffffffffu, l0, 1);
    l0 += __shfl_xor_sync(0xffffffffu, l0, 2);
    l1 += __shfl_xor_sync(0xffffffffu, l1, 1);
    l1 += __shfl_xor_sync(0xffffffffu, l1, 2);
    const float i0 = 1.f / l0, i1 = 1.f / l1;

    const int tok0 = b * T_ + r0, tok1 = b * T_ + r1;
    #pragma unroll
    for (int j = 0; j < 8; j++) {
        const int n = h * DH_ + 8 * j + 2 * (lane & 3);
        float v0 = o[j][0] * i0, v1 = o[j][1] * i0;
        float v2 = o[j][2] * i1, v3 = o[j][3] * i1;
        __nv_bfloat16 h0 = __float2bfloat16(v0), h1 = __float2bfloat16(v1);
        __nv_bfloat16 h2 = __float2bfloat16(v2), h3 = __float2bfloat16(v3);
        __nv_bfloat162 hi0(h0, h1), hi1(h2, h3);
        __nv_bfloat162 lo0(__float2bfloat16(v0 - __bfloat162float(h0)),
                           __float2bfloat16(v1 - __bfloat162float(h1)));
        __nv_bfloat162 lo1(__float2bfloat16(v2 - __bfloat162float(h2)),
                           __float2bfloat16(v3 - __bfloat162float(h3)));
        size_t p0 = (size_t)tok0 * KSRC + n;
        size_t p1 = (size_t)tok1 * KSRC + n;
        *(__nv_bfloat162*)&g_aocat[p0]        = hi0;
        *(__nv_bfloat162*)&g_aocat[p0 + 1024] = lo0;
        *(__nv_bfloat162*)&g_aocat[p1]        = hi1;
        *(__nv_bfloat162*)&g_aocat[p1 + 1024] = lo1;
    }
}

// ---------------- launch --------------------------------------------------------
extern "C" void kernel_launch(void* const* d_in, const int* in_sizes, int n_in,
                              void* d_out, int out_size) {
    const float* X  = (const float*)d_in[0];
    const float* wq = (const float*)d_in[1];
    const float* wk = (const float*)d_in[2];
    const float* wv = (const float*)d_in[3];
    const float* wo = (const float*)d_in[4];
    const float* Aq = (const float*)d_in[5];
    const float* Bq = (const float*)d_in[6];
    const float* Av = (const float*)d_in[7];
    const float* Bv = (const float*)d_in[8];
    float* out = (float*)d_out;

    __nv_bfloat16 *xcat, *aocat, *wtqkv, *wto;
    cudaGetSymbolAddress((void**)&xcat,  g_xcat);
    cudaGetSymbolAddress((void**)&aocat, g_aocat);
    cudaGetSymbolAddress((void**)&wtqkv, g_wtqkv);
    cudaGetSymbolAddress((void**)&wto,   g_wto);

    cudaFuncSetAttribute(gemm_fused_kernel,
                         cudaFuncAttributeMaxDynamicSharedMemorySize, G_TOTAL);
    cudaFuncSetAttribute(gemm_fused_kernel,
                         cudaFuncAttributePreferredSharedMemoryCarveout, 100);
    cudaFuncSetAttribute(attn_mma_kernel,
                         cudaFuncAttributeMaxDynamicSharedMemorySize, A_SMEM);
    cudaFuncSetAttribute(attn_mma_kernel,
                         cudaFuncAttributePreferredSharedMemoryCarveout, 100);

    sincos_kernel<<<(T_*32 + 255) / 256, 256>>>();
    lora_split_kernel<<<MTOT, 256>>>(X, Aq, Av);
    split_wt_kernel<<<dim3(32, 32, 4), dim3(32, 8)>>>(wq, wk, wv, wo);

    gemm_fused_kernel<<<dim3(24, 64), 256, G_TOTAL>>>(xcat, wtqkv, nullptr, 1, Bq, Bv);

    attn_mma_kernel<<<dim3(T_ / 128, H_, B_), 256, A_SMEM>>>();

    gemm_fused_kernel<<<dim3(8, 64), 256, G_TOTAL>>>(aocat, wto, out, 0, nullptr, nullptr);
}

// round 13
// speedup vs baseline: 4.0999x; 1.1060x over previous
#include <cuda_runtime.h>
#include <cuda_bf16.h>
#include <cuda_fp16.h>
#include <math.h>
#include <cstdint>

#define B_   4
#define T_   2048
#define D_   1024
#define H_   16
#define DH_  64
#define R_   8
#define MTOT (B_*T_)          // 8192
#define KSRC 2048             // stored split width: [hi | lo]
#define NCHUNK 48             // 3 terms x 16 chunks of 64
#define LORA_SCALE 4.0f
#define QSCALE 0.180336880f   // 0.125 * log2(e)  — exp2-domain logits

// ---------------- scratch (device globals: no allocation allowed) -------------
__device__ float g_xaq[MTOT*R_];
__device__ float g_xav[MTOT*R_];
__device__ float g_sin[T_*32];
__device__ float g_cos[T_*32];
__device__ __nv_bfloat16 g_xcat [MTOT*KSRC];       // [Xhi | Xlo]
__device__ __nv_bfloat16 g_aocat[MTOT*KSRC];       // attention out [hi | lo]
__device__ __nv_bfloat16 g_wtqkv[3072ull*KSRC];    // rows n of [wq|wk|wv], k = [hi|lo]
__device__ __nv_bfloat16 g_wto  [(size_t)D_*KSRC];
// head-major [b,h,t,dh]
__device__ __nv_bfloat16 g_qhi[MTOT*D_];
__device__ __nv_bfloat16 g_qlo[MTOT*D_];
__device__ __nv_bfloat16 g_khi[MTOT*D_];
__device__ __nv_bfloat16 g_klo[MTOT*D_];
__device__ __half        g_vhf[MTOT*D_];           // V in fp16 (single term)

// ---------------- warp-level MMA helpers ---------------------------------------
__device__ __forceinline__ uint32_t smem_u32(const void* p) {
    uint32_t a;
    asm("{ .reg .u64 t; cvta.to.shared.u64 t, %1; cvt.u32.u64 %0, t; }" : "=r"(a) : "l"(p));
    return a;
}
__device__ __forceinline__ void ldsm_x4(uint32_t* r, uint32_t addr) {
    asm volatile("ldmatrix.sync.aligned.m8n8.x4.shared.b16 {%0,%1,%2,%3}, [%4];"
                 : "=r"(r[0]), "=r"(r[1]), "=r"(r[2]), "=r"(r[3]) : "r"(addr));
}
__device__ __forceinline__ void ldsm_x4_t(uint32_t* r, uint32_t addr) {
    asm volatile("ldmatrix.sync.aligned.m8n8.x4.trans.shared.b16 {%0,%1,%2,%3}, [%4];"
                 : "=r"(r[0]), "=r"(r[1]), "=r"(r[2]), "=r"(r[3]) : "r"(addr));
}
__device__ __forceinline__ void mma16816(float* d, const uint32_t* a,
                                         uint32_t b0, uint32_t b1) {
    asm volatile("mma.sync.aligned.m16n8k16.row.col.f32.bf16.bf16.f32 "
                 "{%0,%1,%2,%3}, {%4,%5,%6,%7}, {%8,%9}, {%0,%1,%2,%3};"
                 : "+f"(d[0]), "+f"(d[1]), "+f"(d[2]), "+f"(d[3])
                 : "r"(a[0]), "r"(a[1]), "r"(a[2]), "r"(a[3]), "r"(b0), "r"(b1));
}
__device__ __forceinline__ void mma16816h(float* d, const uint32_t* a,
                                          uint32_t b0, uint32_t b1) {
    asm volatile("mma.sync.aligned.m16n8k16.row.col.f32.f16.f16.f32 "
                 "{%0,%1,%2,%3}, {%4,%5,%6,%7}, {%8,%9}, {%0,%1,%2,%3};"
                 : "+f"(d[0]), "+f"(d[1]), "+f"(d[2]), "+f"(d[3])
                 : "r"(a[0]), "r"(a[1]), "r"(a[2]), "r"(a[3]), "r"(b0), "r"(b1));
}
__device__ __forceinline__ uint32_t pack_bf16x2(float e, float o) {
    uint32_t d;
    asm("cvt.rn.bf16x2.f32 %0, %1, %2;" : "=r"(d) : "f"(o), "f"(e));
    return d;
}
__device__ __forceinline__ uint32_t pack_f16x2(float e, float o) {
    uint32_t d;
    asm("cvt.rn.f16x2.f32 %0, %1, %2;" : "=r"(d) : "f"(o), "f"(e));
    return d;
}
__device__ __forceinline__ float ex2f(float x) {
    float r;
    asm("ex2.approx.ftz.f32 %0, %1;" : "=f"(r) : "f"(x));
    return r;
}
__device__ __forceinline__ void cpa16(uint32_t dst, const void* src) {
    asm volatile("cp.async.cg.shared.global [%0], [%1], 16;" :: "r"(dst), "l"(src) : "memory");
}
#define CP_COMMIT() asm volatile("cp.async.commit_group;" ::: "memory")
#define CP_WAIT1()  asm volatile("cp.async.wait_group 1;"  ::: "memory")
#define CP_WAIT0()  asm volatile("cp.async.wait_group 0;"  ::: "memory")

// ---------------- sin/cos table -----------------------------------------------
__global__ void sincos_kernel() {
    int idx = blockIdx.x * blockDim.x + threadIdx.x;
    if (idx >= T_*32) return;
    int t = idx >> 5, j = idx & 31;
    double theta = (double)t / pow(10000.0, (double)j / 32.0);
    g_sin[idx] = (float)sin(theta);
    g_cos[idx] = (float)cos(theta);
}

// ---------------- fused LoRA down-proj + X split --------------------------------
__global__ void lora_split_kernel(const float* __restrict__ X,
                                  const float* __restrict__ Aq,
                                  const float* __restrict__ Av) {
    __shared__ float xrow[1024];
    const int m = blockIdx.x;
    const int tid = threadIdx.x;
    const int lane = tid & 31, w = tid >> 5;

    float4 x = ((const float4*)(X + (size_t)m * D_))[tid];
    ((float4*)xrow)[tid] = x;

    float xs[4] = {x.x, x.y, x.z, x.w};
    __nv_bfloat16 h[4], l[4];
    #pragma unroll
    for (int i = 0; i < 4; i++) {
        h[i] = __float2bfloat16(xs[i]);
        l[i] = __float2bfloat16(xs[i] - __bfloat162float(h[i]));
    }
    size_t base = (size_t)m * KSRC + tid * 4;
    *(__nv_bfloat162*)&g_xcat[base]      = __nv_bfloat162(h[0], h[1]);
    *(__nv_bfloat162*)&g_xcat[base+2]    = __nv_bfloat162(h[2], h[3]);
    *(__nv_bfloat162*)&g_xcat[base+1024] = __nv_bfloat162(l[0], l[1]);
    *(__nv_bfloat162*)&g_xcat[base+1026] = __nv_bfloat162(l[2], l[3]);
    __syncthreads();

    #pragma unroll
    for (int cc = 0; cc < 2; cc++) {
        int c = w * 2 + cc;
        const float* A = (c < 8) ? Aq : Av;
        int col = c & 7;
        float s = 0.f;
        for (int k = lane; k < D_; k += 32)
            s += xrow[k] * A[k * R_ + col];
        #pragma unroll
        for (int off = 16; off; off >>= 1)
            s += __shfl_down_sync(0xffffffffu, s, off);
        if (lane == 0) {
            float* XA = (c < 8) ? g_xaq : g_xav;
            XA[m * R_ + col] = s;
        }
    }
}

// ---------------- transpose + split weights ------------------------------------
__global__ void split_wt_kernel(const float* __restrict__ W0, const float* __restrict__ W1,
                                const float* __restrict__ W2, const float* __restrict__ W3) {
    const float* Ws[4] = {W0, W1, W2, W3};
    const float* W = Ws[blockIdx.z];
    __shared__ float tile[32][33];
    int bx = blockIdx.x * 32, by = blockIdx.y * 32;
    for (int i = threadIdx.y; i < 32; i += 8)
        tile[i][threadIdx.x] = W[(size_t)(by + i) * D_ + bx + threadIdx.x];
    __syncthreads();
    for (int i = threadIdx.y; i < 32; i += 8) {
        int n = bx + i, k = by + threadIdx.x;
        float x = tile[threadIdx.x][i];
        __nv_bfloat16 h = __float2bfloat16(x);
        __nv_bfloat16 l = __float2bfloat16(x - __bfloat162float(h));
        __nv_bfloat16* out = (blockIdx.z < 3)
            ? g_wtqkv + (size_t)(blockIdx.z * 1024 + n) * KSRC
            : g_wto   + (size_t)n * KSRC;
        out[k]        = h;
        out[1024 + k] = l;
    }
}

// ================= fused HMMA split-bf16 GEMM (128x128 tile, 256 thr) ==========
#define GSTG   32768
#define GA(s)  ((s) * GSTG)
#define GB(s)  ((s) * GSTG + 16384)
#define G_LB   98304
#define G_TOTAL 102400

__global__ void __launch_bounds__(256, 2)
gemm_fused_kernel(const __nv_bfloat16* __restrict__ Acat,
                  const __nv_bfloat16* __restrict__ Bcat,
                  float* __restrict__ C, int qkv,
                  const float* __restrict__ Bq, const float* __restrict__ Bv)
{
    extern __shared__ char smem[];
    const uint32_t sbase = smem_u32(smem);
    const int tid  = threadIdx.x;
    const int lane = tid & 31;
    const int wid  = tid >> 5;
    const int wm   = wid & 1;
    const int wn   = wid >> 1;
    const int row0 = blockIdx.y * 128, col0 = blockIdx.x * 128;

    float acc[4][4][4];
    #pragma unroll
    for (int i = 0; i < 4; i++)
        #pragma unroll
        for (int j = 0; j < 4; j++)
            #pragma unroll
            for (int r = 0; r < 4; r++) acc[i][j][r] = 0.f;

    auto prefetch = [&](int c, int stg) {
        const int cm  = (c & 15) * 64;
        const int kbA = cm + ((c >= 32) ? 1024 : 0);
        const int kbB = cm + ((c >= 16 && c < 32) ? 1024 : 0);
        #pragma unroll
        for (int i = 0; i < 4; i++) {
            int idx = i * 256 + tid;
            int r = idx >> 3, cc = idx & 7;
            uint32_t off = r * 128 + (((uint32_t)(cc * 16)) ^ ((r & 7) << 4));
            cpa16(sbase + GA(stg) + off, Acat + (size_t)(row0 + r) * KSRC + kbA + cc * 8);
        }
        #pragma unroll
        for (int i = 0; i < 4; i++) {
            int idx = i * 256 + tid;
            int r = idx >> 3, cc = idx & 7;
            uint32_t off = r * 128 + (((uint32_t)(cc * 16)) ^ ((r & 7) << 4));
            cpa16(sbase + GB(stg) + off, Bcat + (size_t)(col0 + r) * KSRC + kbB + cc * 8);
        }
    };

    prefetch(0, 0); CP_COMMIT();
    prefetch(1, 1); CP_COMMIT();

    int sc = 0, s2 = 2;
    for (int c = 0; c < NCHUNK; c++) {
        CP_WAIT1();
        __syncthreads();
        if (c + 2 < NCHUNK) prefetch(c + 2, s2);
        CP_COMMIT();
        const uint32_t sa = sbase + GA(sc);
        const uint32_t sb = sbase + GB(sc);
        #pragma unroll
        for (int ks = 0; ks < 4; ks++) {
            uint32_t af[4][4], bfr[2][4];
            #pragma unroll
            for (int ma = 0; ma < 4; ma++) {
                int r = wm * 64 + ma * 16 + (lane & 15);
                uint32_t off = (uint32_t)(ks * 32 + ((lane >> 4) << 4));
                ldsm_x4(af[ma], sa + r * 128 + (off ^ ((r & 7) << 4)));
            }
            #pragma unroll
            for (int nb = 0; nb < 2; nb++) {
                int r = wn * 32 + nb * 16 + ((lane >> 4) << 3) + (lane & 7);
                uint32_t off = (uint32_t)(ks * 32 + (((lane >> 3) & 1) << 4));
                ldsm_x4(bfr[nb], sb + r * 128 + (off ^ ((r & 7) << 4)));
            }
            #pragma unroll
            for (int ma = 0; ma < 4; ma++)
                #pragma unroll
                for (int na = 0; na < 4; na++)
                    mma16816(acc[ma][na], af[ma],
                             bfr[na >> 1][(na & 1) * 2], bfr[na >> 1][(na & 1) * 2 + 1]);
        }
        sc = (sc == 2) ? 0 : sc + 1;
        s2 = (s2 == 2) ? 0 : s2 + 1;
    }
    __syncthreads();

    const int region = qkv ? (col0 >> 10) : 3;
    const float* XA = (region == 0) ? g_xaq : (region == 2) ? g_xav : nullptr;
    float* LBs = (float*)(smem + G_LB);
    if (qkv && region != 1) {
        const float* Bsrc = (region == 0) ? Bq : Bv;
        const int cbase = col0 & 1023;
        #pragma unroll
        for (int i = 0; i < 4; i++) {
            int idx = i * 256 + tid;
            LBs[idx] = Bsrc[(idx >> 7) * D_ + cbase + (idx & 127)];
        }
        __syncthreads();
    }

    #pragma unroll
    for (int ma = 0; ma < 4; ma++) {
        const int mlo = row0 + wm * 64 + ma * 16 + (lane >> 2);
        const int mhi = mlo + 8;
        float xal[8], xah[8];
        if (XA) {
            #pragma unroll
            for (int r = 0; r < R_; r++) {
                xal[r] = XA[mlo * R_ + r];
                xah[r] = XA[mhi * R_ + r];
            }
        }
        const int tlo = mlo & (T_ - 1), thi = mhi & (T_ - 1);
        #pragma unroll
        for (int na = 0; na < 4; na++) {
            const int n  = col0 + wn * 32 + na * 8 + (lane & 3) * 2;
            const int nl = n - col0;
            float v0 = acc[ma][na][0], v1 = acc[ma][na][1];
            float v2 = acc[ma][na][2], v3 = acc[ma][na][3];
            if (XA) {
                float s0 = 0.f, s1 = 0.f, s2_ = 0.f, s3 = 0.f;
                #pragma unroll
                for (int r = 0; r < R_; r++) {
                    float b0 = LBs[r * 128 + nl], b1 = LBs[r * 128 + nl + 1];
                    s0 += xal[r] * b0; s1 += xal[r] * b1;
                    s2_ += xah[r] * b0; s3 += xah[r] * b1;
                }
                v0 += LORA_SCALE * s0; v1 += LORA_SCALE * s1;
                v2 += LORA_SCALE * s2_; v3 += LORA_SCALE * s3;
            }
            if (region <= 1) {              // RoPE for Q and K
                const int jj = (n & 63) >> 1;
                float sn = g_sin[tlo * 32 + jj], cs = g_cos[tlo * 32 + jj];
                float e = v0, o = v1;
                v0 = e * cs - o * sn; v1 = e * sn + o * cs;
                sn = g_sin[thi * 32 + jj]; cs = g_cos[thi * 32 + jj];
                e = v2; o = v3;
                v2 = e * cs - o * sn; v3 = e * sn + o * cs;
            }
            if (region == 0) { v0 *= QSCALE; v1 *= QSCALE; v2 *= QSCALE; v3 *= QSCALE; }
            if (!qkv) {
                *(float2*)&C[(size_t)mlo * D_ + n] = make_float2(v0, v1);
                *(float2*)&C[(size_t)mhi * D_ + n] = make_float2(v2, v3);
            } else {
                const int bq = mlo >> 11, hh = (n & 1023) >> 6, dd = n & 63;
                size_t olo = ((size_t)(bq * H_ + hh) * T_ + tlo) * DH_ + dd;
                size_t ohi = ((size_t)(bq * H_ + hh) * T_ + thi) * DH_ + dd;
                if (region == 2) {          // V: single fp16 term
                    *(__half2*)&g_vhf[olo] = __floats2half2_rn(v0, v1);
                    *(__half2*)&g_vhf[ohi] = __floats2half2_rn(v2, v3);
                } else {
                    __nv_bfloat16* Chi = (region == 0) ? g_qhi : g_khi;
                    __nv_bfloat16* Clo = (region == 0) ? g_qlo : g_klo;
                    __nv_bfloat16 h0 = __float2bfloat16(v0), h1 = __float2bfloat16(v1);
                    __nv_bfloat16 h2 = __float2bfloat16(v2), h3 = __float2bfloat16(v3);
                    *(__nv_bfloat162*)&Chi[olo] = __nv_bfloat162(h0, h1);
                    *(__nv_bfloat162*)&Chi[ohi] = __nv_bfloat162(h2, h3);
                    *(__nv_bfloat162*)&Clo[olo] = __nv_bfloat162(
                        __float2bfloat16(v0 - __bfloat162float(h0)),
                        __float2bfloat16(v1 - __bfloat162float(h1)));
                    *(__nv_bfloat162*)&Clo[ohi] = __nv_bfloat162(
                        __float2bfloat16(v2 - __bfloat162float(h2)),
                        __float2bfloat16(v3 - __bfloat162float(h3)));
                }
            }
        }
    }
}

// ================= tensor-core flash attention =================================
// S: 3-term split-bf16.  PV: single-term fp16 P x fp16 V.
// Tiles per chunk: KHI | KLO | VHF (8KB each, 24KB). buf1 reuses Q region.
#define AQ_HI 0
#define AQ_LO 16384
#define ATILE(buf) ((buf) ? 0 : 32768)
#define A_SMEM 57344

__global__ void __launch_bounds__(256, 2)
attn_mma_kernel() {
    extern __shared__ char smem[];
    const uint32_t sbs = smem_u32(smem);
    const int tid = threadIdx.x, lane = tid & 31, w = tid >> 5;
    const int qb = gridDim.x - 1 - blockIdx.x;
    const int h = blockIdx.y, b = blockIdx.z;
    const int bh = b * H_ + h;
    const __nv_bfloat16* qhi = g_qhi + (size_t)bh * T_ * DH_;
    const __nv_bfloat16* qlo = g_qlo + (size_t)bh * T_ * DH_;
    const __nv_bfloat16* khi = g_khi + (size_t)bh * T_ * DH_;
    const __nv_bfloat16* klo = g_klo + (size_t)bh * T_ * DH_;
    const __half*        vhf = g_vhf + (size_t)bh * T_ * DH_;

    {
        const __nv_bfloat16* sq = qhi + (size_t)(qb * 128) * DH_;
        const __nv_bfloat16* sl = qlo + (size_t)(qb * 128) * DH_;
        #pragma unroll
        for (int i = 0; i < 4; i++) {
            int idx = i * 256 + tid;
            int r = idx >> 3, c = idx & 7;
            uint32_t off = r * 128 + (((uint32_t)(c * 16)) ^ ((r & 7) << 4));
            *(uint4*)(smem + AQ_HI + off) = *((const uint4*)(sq + r * DH_) + c);
            *(uint4*)(smem + AQ_LO + off) = *((const uint4*)(sl + r * DH_) + c);
        }
    }
    __syncthreads();

    uint32_t qf[2][4][4];
    #pragma unroll
    for (int s = 0; s < 2; s++) {
        const uint32_t base = sbs + (s ? AQ_LO : AQ_HI);
        #pragma unroll
        for (int ks = 0; ks < 4; ks++) {
            int tsel = lane >> 3;
            int r = 16 * w + (lane & 7) + (tsel & 1) * 8;
            uint32_t off = ((uint32_t)(ks * 32 + ((tsel >> 1) & 1) * 16)) ^ ((r & 7) << 4);
            ldsm_x4(qf[s][ks], base + r * 128 + off);
        }
    }

    auto prefetch = [&](int c, int buf) {
        const int k0 = c * 64;
        const uint32_t tb = sbs + ATILE(buf);
        #pragma unroll
        for (int i = 0; i < 2; i++) {
            int idx = i * 256 + tid;
            int r = idx >> 3, cc = idx & 7;
            uint32_t off = r * 128 + (((uint32_t)(cc * 16)) ^ ((r & 7) << 4));
            const size_t g = (size_t)(k0 + r) * DH_ + cc * 8;
            cpa16(tb + off,         khi + g);
            cpa16(tb + 8192 + off,  klo + g);
            cpa16(tb + 16384 + off, vhf + g);
        }
    };

    const int nch = 2 * qb + 2;
    prefetch(0, 0); CP_COMMIT();          // buf0 does NOT overlap Q region

    float o[8][4];
    #pragma unroll
    for (int j = 0; j < 8; j++)
        #pragma unroll
        for (int r = 0; r < 4; r++) o[j][r] = 0.f;
    float m0 = -1e30f, m1 = -1e30f, l0 = 0.f, l1 = 0.f;

    const int wrow0 = qb * 128 + 16 * w;
    const int r0 = wrow0 + (lane >> 2), r1 = r0 + 8;

    for (int c = 0; c < nch; c++) {
        const int buf = c & 1;
        CP_WAIT0();
        __syncthreads();                   // chunk c visible; Q reads / buf^1 done
        if (c + 1 < nch) { prefetch(c + 1, buf ^ 1); CP_COMMIT(); }

        const int k0 = c * 64;
        const uint32_t skh = sbs + ATILE(buf);
        const uint32_t skl = skh + 8192;
        const uint32_t svf = skh + 16384;

        #pragma unroll
        for (int hb = 0; hb < 2; hb++) {
            const int kb0 = k0 + hb * 32;
            if (kb0 > wrow0 + 15) break;

            float s[4][4];
            #pragma unroll
            for (int j = 0; j < 4; j++)
                #pragma unroll
                for (int r = 0; r < 4; r++) s[j][r] = 0.f;

            #pragma unroll
            for (int ks = 0; ks < 4; ks++) {
                #pragma unroll
                for (int jp = 0; jp < 2; jp++) {
                    uint32_t bh_[4], bl_[4];
                    int rr = hb * 32 + jp * 16 + ((lane >> 4) << 3) + (lane & 7);
                    uint32_t off = ((uint32_t)(ks * 32 + (((lane >> 3) & 1) << 4)))
                                   ^ ((rr & 7) << 4);
                    ldsm_x4(bh_, skh + rr * 128 + off);
                    ldsm_x4(bl_, skl + rr * 128 + off);
                    mma16816(s[2*jp],   qf[0][ks], bh_[0], bh_[1]);
                    mma16816(s[2*jp],   qf[0][ks], bl_[0], bl_[1]);
                    mma16816(s[2*jp],   qf[1][ks], bh_[0], bh_[1]);
                    mma16816(s[2*jp+1], qf[0][ks], bh_[2], bh_[3]);
                    mma16816(s[2*jp+1], qf[0][ks], bl_[2], bl_[3]);
                    mma16816(s[2*jp+1], qf[1][ks], bh_[2], bh_[3]);
                }
            }

            if (kb0 + 31 > wrow0) {
                #pragma unroll
                for (int j = 0; j < 4; j++) {
                    int col = kb0 + 8 * j + 2 * (lane & 3);
                    if (col     > r0) s[j][0] = -1e30f;
                    if (col + 1 > r0) s[j][1] = -1e30f;
                    if (col     > r1) s[j][2] = -1e30f;
                    if (col + 1 > r1) s[j][3] = -1e30f;
                }
            }

            float mx0 = -1e30f, mx1 = -1e30f;
            #pragma unroll
            for (int j = 0; j < 4; j++) {
                mx0 = fmaxf(mx0, fmaxf(s[j][0], s[j][1]));
                mx1 = fmaxf(mx1, fmaxf(s[j][2], s[j][3]));
            }
            mx0 = fmaxf(mx0, __shfl_xor_sync(0xffffffffu, mx0, 1));
            mx0 = fmaxf(mx0, __shfl_xor_sync(0xffffffffu, mx0, 2));
            mx1 = fmaxf(mx1, __shfl_xor_sync(0xffffffffu, mx1, 1));
            mx1 = fmaxf(mx1, __shfl_xor_sync(0xffffffffu, mx1, 2));
            float mn0 = fmaxf(m0, mx0), mn1 = fmaxf(m1, mx1);
            bool nochg = __all_sync(0xffffffffu, (mn0 == m0) && (mn1 == m1));
            if (!nochg) {
                float cr0 = ex2f(m0 - mn0), cr1 = ex2f(m1 - mn1);
                l0 *= cr0; l1 *= cr1;
                #pragma unroll
                for (int j = 0; j < 8; j++) {
                    o[j][0] *= cr0; o[j][1] *= cr0;
                    o[j][2] *= cr1; o[j][3] *= cr1;
                }
                m0 = mn0; m1 = mn1;
            }

            uint32_t ph[4][2];
            #pragma unroll
            for (int j = 0; j < 4; j++) {
                float p0 = ex2f(s[j][0] - m0), p1 = ex2f(s[j][1] - m0);
                float p2 = ex2f(s[j][2] - m1), p3 = ex2f(s[j][3] - m1);
                l0 += p0 + p1; l1 += p2 + p3;          // exact fp32 denominator
                ph[j][0] = pack_f16x2(p0, p1);
                ph[j][1] = pack_f16x2(p2, p3);
            }

            #pragma unroll
            for (int kk = 0; kk < 2; kk++) {
                uint32_t ahi[4] = {ph[2*kk][0], ph[2*kk][1], ph[2*kk+1][0], ph[2*kk+1][1]};
                #pragma unroll
                for (int jp = 0; jp < 4; jp++) {
                    uint32_t vh_[4];
                    int tsel = lane >> 3;
                    int key = hb * 32 + 16 * kk + (tsel & 1) * 8 + (lane & 7);
                    uint32_t off = ((uint32_t)((16 * jp + ((tsel >> 1) & 1) * 8) * 2))
                                   ^ ((key & 7) << 4);
                    ldsm_x4_t(vh_, svf + key * 128 + off);
                    mma16816h(o[2*jp],   ahi, vh_[0], vh_[1]);
                    mma16816h(o[2*jp+1], ahi, vh_[2], vh_[3]);
                }
            }
        }
    }

    l0 += __shfl_xor_sync(0xffffffffu, l0, 1);
    l0 += __shfl_xor_sync(0xffffffffu, l0, 2);
    l1 += __shfl_xor_sync(0xffffffffu, l1, 1);
    l1 += __shfl_xor_sync(0xffffffffu, l1, 2);
    const float i0 = 1.f / l0, i1 = 1.f / l1;

    const int tok0 = b * T_ + r0, tok1 = b * T_ + r1;
    #pragma unroll
    for (int j = 0; j < 8; j++) {
        const int n = h * DH_ + 8 * j + 2 * (lane & 3);
        float v0 = o[j][0] * i0, v1 = o[j][1] * i0;
        float v2 = o[j][2] * i1, v3 = o[j][3] * i1;
        __nv_bfloat16 h0 = __float2bfloat16(v0), h1 = __float2bfloat16(v1);
        __nv_bfloat16 h2 = __float2bfloat16(v2), h3 = __float2bfloat16(v3);
        __nv_bfloat162 hi0(h0, h1), hi1(h2, h3);
        __nv_bfloat162 lo0(__float2bfloat16(v0 - __bfloat162float(h0)),
                           __float2bfloat16(v1 - __bfloat162float(h1)));
        __nv_bfloat162 lo1(__float2bfloat16(v2 - __bfloat162float(h2)),
                           __float2bfloat16(v3 - __bfloat162float(h3)));
        size_t p0 = (size_t)tok0 * KSRC + n;
        size_t p1 = (size_t)tok1 * KSRC + n;
        *(__nv_bfloat162*)&g_aocat[p0]        = hi0;
        *(__nv_bfloat162*)&g_aocat[p0 + 1024] = lo0;
        *(__nv_bfloat162*)&g_aocat[p1]        = hi1;
        *(__nv_bfloat162*)&g_aocat[p1 + 1024] = lo1;
    }
}

// ---------------- launch --------------------------------------------------------
extern "C" void kernel_launch(void* const* d_in, const int* in_sizes, int n_in,
                              void* d_out, int out_size) {
    const float* X  = (const float*)d_in[0];
    const float* wq = (const float*)d_in[1];
    const float* wk = (const float*)d_in[2];
    const float* wv = (const float*)d_in[3];
    const float* wo = (const float*)d_in[4];
    const float* Aq = (const float*)d_in[5];
    const float* Bq = (const float*)d_in[6];
    const float* Av = (const float*)d_in[7];
    const float* Bv = (const float*)d_in[8];
    float* out = (float*)d_out;

    __nv_bfloat16 *xcat, *aocat, *wtqkv, *wto;
    cudaGetSymbolAddress((void**)&xcat,  g_xcat);
    cudaGetSymbolAddress((void**)&aocat, g_aocat);
    cudaGetSymbolAddress((void**)&wtqkv, g_wtqkv);
    cudaGetSymbolAddress((void**)&wto,   g_wto);

    cudaFuncSetAttribute(gemm_fused_kernel,
                         cudaFuncAttributeMaxDynamicSharedMemorySize, G_TOTAL);
    cudaFuncSetAttribute(gemm_fused_kernel,
                         cudaFuncAttributePreferredSharedMemoryCarveout, 100);
    cudaFuncSetAttribute(attn_mma_kernel,
                         cudaFuncAttributeMaxDynamicSharedMemorySize, A_SMEM);
    cudaFuncSetAttribute(attn_mma_kernel,
                         cudaFuncAttributePreferredSharedMemoryCarveout, 100);

    sincos_kernel<<<(T_*32 + 255) / 256, 256>>>();
    lora_split_kernel<<<MTOT, 256>>>(X, Aq, Av);
    split_wt_kernel<<<dim3(32, 32, 4), dim3(32, 8)>>>(wq, wk, wv, wo);

    gemm_fused_kernel<<<dim3(24, 64), 256, G_TOTAL>>>(xcat, wtqkv, nullptr, 1, Bq, Bv);

    attn_mma_kernel<<<dim3(T_ / 128, H_, B_), 256, A_SMEM>>>();

    gemm_fused_kernel<<<dim3(8, 64), 256, G_TOTAL>>>(aocat, wto, out, 0, nullptr, nullptr);
}

// round 14
// speedup vs baseline: 4.6123x; 1.1250x over previous
#include <cuda_runtime.h>
#include <cuda_bf16.h>
#include <cuda_fp16.h>
#include <math.h>
#include <cstdint>

#define B_   4
#define T_   2048
#define D_   1024
#define H_   16
#define DH_  64
#define R_   8
#define MTOT (B_*T_)          // 8192
#define KSRC 2048             // stored split width: [hi | lo]
#define NCHUNK 48             // 3 terms x 16 chunks of 64
#define LORA_SCALE 4.0f
#define QSCALE 0.180336880f   // 0.125 * log2(e)  — exp2-domain logits

// ---------------- scratch (device globals: no allocation allowed) -------------
__device__ float g_xaq[MTOT*R_];
__device__ float g_xav[MTOT*R_];
__device__ float g_sin[T_*32];
__device__ float g_cos[T_*32];
__device__ __nv_bfloat16 g_xcat [MTOT*KSRC];       // [Xhi | Xlo]
__device__ __nv_bfloat16 g_aocat[MTOT*KSRC];       // attention out [hi | lo]
__device__ __nv_bfloat16 g_wtqkv[3072ull*KSRC];    // rows n of [wq|wk|wv], k = [hi|lo]
__device__ __nv_bfloat16 g_wto  [(size_t)D_*KSRC];
// head-major [b,h,t,dh], single-term fp16
__device__ __half g_qhf[MTOT*D_];
__device__ __half g_khf[MTOT*D_];
__device__ __half g_vhf[MTOT*D_];

// ---------------- warp-level MMA helpers ---------------------------------------
__device__ __forceinline__ uint32_t smem_u32(const void* p) {
    uint32_t a;
    asm("{ .reg .u64 t; cvta.to.shared.u64 t, %1; cvt.u32.u64 %0, t; }" : "=r"(a) : "l"(p));
    return a;
}
__device__ __forceinline__ void ldsm_x4(uint32_t* r, uint32_t addr) {
    asm volatile("ldmatrix.sync.aligned.m8n8.x4.shared.b16 {%0,%1,%2,%3}, [%4];"
                 : "=r"(r[0]), "=r"(r[1]), "=r"(r[2]), "=r"(r[3]) : "r"(addr));
}
__device__ __forceinline__ void ldsm_x4_t(uint32_t* r, uint32_t addr) {
    asm volatile("ldmatrix.sync.aligned.m8n8.x4.trans.shared.b16 {%0,%1,%2,%3}, [%4];"
                 : "=r"(r[0]), "=r"(r[1]), "=r"(r[2]), "=r"(r[3]) : "r"(addr));
}
__device__ __forceinline__ void mma16816(float* d, const uint32_t* a,
                                         uint32_t b0, uint32_t b1) {
    asm volatile("mma.sync.aligned.m16n8k16.row.col.f32.bf16.bf16.f32 "
                 "{%0,%1,%2,%3}, {%4,%5,%6,%7}, {%8,%9}, {%0,%1,%2,%3};"
                 : "+f"(d[0]), "+f"(d[1]), "+f"(d[2]), "+f"(d[3])
                 : "r"(a[0]), "r"(a[1]), "r"(a[2]), "r"(a[3]), "r"(b0), "r"(b1));
}
__device__ __forceinline__ void mma16816h(float* d, const uint32_t* a,
                                          uint32_t b0, uint32_t b1) {
    asm volatile("mma.sync.aligned.m16n8k16.row.col.f32.f16.f16.f32 "
                 "{%0,%1,%2,%3}, {%4,%5,%6,%7}, {%8,%9}, {%0,%1,%2,%3};"
                 : "+f"(d[0]), "+f"(d[1]), "+f"(d[2]), "+f"(d[3])
                 : "r"(a[0]), "r"(a[1]), "r"(a[2]), "r"(a[3]), "r"(b0), "r"(b1));
}
__device__ __forceinline__ uint32_t pack_f16x2(float e, float o) {
    uint32_t d;
    asm("cvt.rn.f16x2.f32 %0, %1, %2;" : "=r"(d) : "f"(o), "f"(e));
    return d;
}
__device__ __forceinline__ float ex2f(float x) {
    float r;
    asm("ex2.approx.ftz.f32 %0, %1;" : "=f"(r) : "f"(x));
    return r;
}
__device__ __forceinline__ void cpa16(uint32_t dst, const void* src) {
    asm volatile("cp.async.cg.shared.global [%0], [%1], 16;" :: "r"(dst), "l"(src) : "memory");
}
#define CP_COMMIT() asm volatile("cp.async.commit_group;" ::: "memory")
#define CP_WAIT1()  asm volatile("cp.async.wait_group 1;"  ::: "memory")
#define CP_WAIT0()  asm volatile("cp.async.wait_group 0;"  ::: "memory")

// ---------------- sin/cos table -----------------------------------------------
__global__ void sincos_kernel() {
    int idx = blockIdx.x * blockDim.x + threadIdx.x;
    if (idx >= T_*32) return;
    int t = idx >> 5, j = idx & 31;
    double theta = (double)t / pow(10000.0, (double)j / 32.0);
    g_sin[idx] = (float)sin(theta);
    g_cos[idx] = (float)cos(theta);
}

// ---------------- fused LoRA down-proj + X split --------------------------------
__global__ void lora_split_kernel(const float* __restrict__ X,
                                  const float* __restrict__ Aq,
                                  const float* __restrict__ Av) {
    __shared__ float xrow[1024];
    const int m = blockIdx.x;
    const int tid = threadIdx.x;
    const int lane = tid & 31, w = tid >> 5;

    float4 x = ((const float4*)(X + (size_t)m * D_))[tid];
    ((float4*)xrow)[tid] = x;

    float xs[4] = {x.x, x.y, x.z, x.w};
    __nv_bfloat16 h[4], l[4];
    #pragma unroll
    for (int i = 0; i < 4; i++) {
        h[i] = __float2bfloat16(xs[i]);
        l[i] = __float2bfloat16(xs[i] - __bfloat162float(h[i]));
    }
    size_t base = (size_t)m * KSRC + tid * 4;
    *(__nv_bfloat162*)&g_xcat[base]      = __nv_bfloat162(h[0], h[1]);
    *(__nv_bfloat162*)&g_xcat[base+2]    = __nv_bfloat162(h[2], h[3]);
    *(__nv_bfloat162*)&g_xcat[base+1024] = __nv_bfloat162(l[0], l[1]);
    *(__nv_bfloat162*)&g_xcat[base+1026] = __nv_bfloat162(l[2], l[3]);
    __syncthreads();

    #pragma unroll
    for (int cc = 0; cc < 2; cc++) {
        int c = w * 2 + cc;
        const float* A = (c < 8) ? Aq : Av;
        int col = c & 7;
        float s = 0.f;
        for (int k = lane; k < D_; k += 32)
            s += xrow[k] * A[k * R_ + col];
        #pragma unroll
        for (int off = 16; off; off >>= 1)
            s += __shfl_down_sync(0xffffffffu, s, off);
        if (lane == 0) {
            float* XA = (c < 8) ? g_xaq : g_xav;
            XA[m * R_ + col] = s;
        }
    }
}

// ---------------- transpose + split weights ------------------------------------
__global__ void split_wt_kernel(const float* __restrict__ W0, const float* __restrict__ W1,
                                const float* __restrict__ W2, const float* __restrict__ W3) {
    const float* Ws[4] = {W0, W1, W2, W3};
    const float* W = Ws[blockIdx.z];
    __shared__ float tile[32][33];
    int bx = blockIdx.x * 32, by = blockIdx.y * 32;
    for (int i = threadIdx.y; i < 32; i += 8)
        tile[i][threadIdx.x] = W[(size_t)(by + i) * D_ + bx + threadIdx.x];
    __syncthreads();
    for (int i = threadIdx.y; i < 32; i += 8) {
        int n = bx + i, k = by + threadIdx.x;
        float x = tile[threadIdx.x][i];
        __nv_bfloat16 h = __float2bfloat16(x);
        __nv_bfloat16 l = __float2bfloat16(x - __bfloat162float(h));
        __nv_bfloat16* out = (blockIdx.z < 3)
            ? g_wtqkv + (size_t)(blockIdx.z * 1024 + n) * KSRC
            : g_wto   + (size_t)n * KSRC;
        out[k]        = h;
        out[1024 + k] = l;
    }
}

// ================= fused HMMA split-bf16 GEMM (128x128 tile, 256 thr) ==========
#define GSTG   32768
#define GA(s)  ((s) * GSTG)
#define GB(s)  ((s) * GSTG + 16384)
#define G_LB   98304
#define G_TOTAL 102400

__global__ void __launch_bounds__(256, 2)
gemm_fused_kernel(const __nv_bfloat16* __restrict__ Acat,
                  const __nv_bfloat16* __restrict__ Bcat,
                  float* __restrict__ C, int qkv,
                  const float* __restrict__ Bq, const float* __restrict__ Bv)
{
    extern __shared__ char smem[];
    const uint32_t sbase = smem_u32(smem);
    const int tid  = threadIdx.x;
    const int lane = tid & 31;
    const int wid  = tid >> 5;
    const int wm   = wid & 1;
    const int wn   = wid >> 1;
    const int row0 = blockIdx.y * 128, col0 = blockIdx.x * 128;

    float acc[4][4][4];
    #pragma unroll
    for (int i = 0; i < 4; i++)
        #pragma unroll
        for (int j = 0; j < 4; j++)
            #pragma unroll
            for (int r = 0; r < 4; r++) acc[i][j][r] = 0.f;

    auto prefetch = [&](int c, int stg) {
        const int cm  = (c & 15) * 64;
        const int kbA = cm + ((c >= 32) ? 1024 : 0);
        const int kbB = cm + ((c >= 16 && c < 32) ? 1024 : 0);
        #pragma unroll
        for (int i = 0; i < 4; i++) {
            int idx = i * 256 + tid;
            int r = idx >> 3, cc = idx & 7;
            uint32_t off = r * 128 + (((uint32_t)(cc * 16)) ^ ((r & 7) << 4));
            cpa16(sbase + GA(stg) + off, Acat + (size_t)(row0 + r) * KSRC + kbA + cc * 8);
        }
        #pragma unroll
        for (int i = 0; i < 4; i++) {
            int idx = i * 256 + tid;
            int r = idx >> 3, cc = idx & 7;
            uint32_t off = r * 128 + (((uint32_t)(cc * 16)) ^ ((r & 7) << 4));
            cpa16(sbase + GB(stg) + off, Bcat + (size_t)(col0 + r) * KSRC + kbB + cc * 8);
        }
    };

    prefetch(0, 0); CP_COMMIT();
    prefetch(1, 1); CP_COMMIT();

    int sc = 0, s2 = 2;
    for (int c = 0; c < NCHUNK; c++) {
        CP_WAIT1();
        __syncthreads();
        if (c + 2 < NCHUNK) prefetch(c + 2, s2);
        CP_COMMIT();
        const uint32_t sa = sbase + GA(sc);
        const uint32_t sb = sbase + GB(sc);
        #pragma unroll
        for (int ks = 0; ks < 4; ks++) {
            uint32_t af[4][4], bfr[2][4];
            #pragma unroll
            for (int ma = 0; ma < 4; ma++) {
                int r = wm * 64 + ma * 16 + (lane & 15);
                uint32_t off = (uint32_t)(ks * 32 + ((lane >> 4) << 4));
                ldsm_x4(af[ma], sa + r * 128 + (off ^ ((r & 7) << 4)));
            }
            #pragma unroll
            for (int nb = 0; nb < 2; nb++) {
                int r = wn * 32 + nb * 16 + ((lane >> 4) << 3) + (lane & 7);
                uint32_t off = (uint32_t)(ks * 32 + (((lane >> 3) & 1) << 4));
                ldsm_x4(bfr[nb], sb + r * 128 + (off ^ ((r & 7) << 4)));
            }
            #pragma unroll
            for (int ma = 0; ma < 4; ma++)
                #pragma unroll
                for (int na = 0; na < 4; na++)
                    mma16816(acc[ma][na], af[ma],
                             bfr[na >> 1][(na & 1) * 2], bfr[na >> 1][(na & 1) * 2 + 1]);
        }
        sc = (sc == 2) ? 0 : sc + 1;
        s2 = (s2 == 2) ? 0 : s2 + 1;
    }
    __syncthreads();

    const int region = qkv ? (col0 >> 10) : 3;
    const float* XA = (region == 0) ? g_xaq : (region == 2) ? g_xav : nullptr;
    float* LBs = (float*)(smem + G_LB);
    if (qkv && region != 1) {
        const float* Bsrc = (region == 0) ? Bq : Bv;
        const int cbase = col0 & 1023;
        #pragma unroll
        for (int i = 0; i < 4; i++) {
            int idx = i * 256 + tid;
            LBs[idx] = Bsrc[(idx >> 7) * D_ + cbase + (idx & 127)];
        }
        __syncthreads();
    }

    #pragma unroll
    for (int ma = 0; ma < 4; ma++) {
        const int mlo = row0 + wm * 64 + ma * 16 + (lane >> 2);
        const int mhi = mlo + 8;
        float xal[8], xah[8];
        if (XA) {
            #pragma unroll
            for (int r = 0; r < R_; r++) {
                xal[r] = XA[mlo * R_ + r];
                xah[r] = XA[mhi * R_ + r];
            }
        }
        const int tlo = mlo & (T_ - 1), thi = mhi & (T_ - 1);
        #pragma unroll
        for (int na = 0; na < 4; na++) {
            const int n  = col0 + wn * 32 + na * 8 + (lane & 3) * 2;
            const int nl = n - col0;
            float v0 = acc[ma][na][0], v1 = acc[ma][na][1];
            float v2 = acc[ma][na][2], v3 = acc[ma][na][3];
            if (XA) {
                float s0 = 0.f, s1 = 0.f, s2_ = 0.f, s3 = 0.f;
                #pragma unroll
                for (int r = 0; r < R_; r++) {
                    float b0 = LBs[r * 128 + nl], b1 = LBs[r * 128 + nl + 1];
                    s0 += xal[r] * b0; s1 += xal[r] * b1;
                    s2_ += xah[r] * b0; s3 += xah[r] * b1;
                }
                v0 += LORA_SCALE * s0; v1 += LORA_SCALE * s1;
                v2 += LORA_SCALE * s2_; v3 += LORA_SCALE * s3;
            }
            if (region <= 1) {              // RoPE for Q and K
                const int jj = (n & 63) >> 1;
                float sn = g_sin[tlo * 32 + jj], cs = g_cos[tlo * 32 + jj];
                float e = v0, o = v1;
                v0 = e * cs - o * sn; v1 = e * sn + o * cs;
                sn = g_sin[thi * 32 + jj]; cs = g_cos[thi * 32 + jj];
                e = v2; o = v3;
                v2 = e * cs - o * sn; v3 = e * sn + o * cs;
            }
            if (region == 0) { v0 *= QSCALE; v1 *= QSCALE; v2 *= QSCALE; v3 *= QSCALE; }
            if (!qkv) {
                *(float2*)&C[(size_t)mlo * D_ + n] = make_float2(v0, v1);
                *(float2*)&C[(size_t)mhi * D_ + n] = make_float2(v2, v3);
            } else {
                const int bq = mlo >> 11, hh = (n & 1023) >> 6, dd = n & 63;
                size_t olo = ((size_t)(bq * H_ + hh) * T_ + tlo) * DH_ + dd;
                size_t ohi = ((size_t)(bq * H_ + hh) * T_ + thi) * DH_ + dd;
                __half* dst = (region == 0) ? g_qhf : (region == 1) ? g_khf : g_vhf;
                *(__half2*)&dst[olo] = __floats2half2_rn(v0, v1);
                *(__half2*)&dst[ohi] = __floats2half2_rn(v2, v3);
            }
        }
    }
}

// ================= tensor-core flash attention =================================
// Single-term fp16 for S and PV.  Q tile 16KB; per-chunk tiles KHF|VHF (16KB x2).
#define AQ 0
#define ATILE(buf) (16384 + (buf) * 16384)
#define A_SMEM 49152

__global__ void __launch_bounds__(256, 2)
attn_mma_kernel() {
    extern __shared__ char smem[];
    const uint32_t sbs = smem_u32(smem);
    const int tid = threadIdx.x, lane = tid & 31, w = tid >> 5;
    const int qb = gridDim.x - 1 - blockIdx.x;
    const int h = blockIdx.y, b = blockIdx.z;
    const int bh = b * H_ + h;
    const __half* qhf = g_qhf + (size_t)bh * T_ * DH_;
    const __half* khf = g_khf + (size_t)bh * T_ * DH_;
    const __half* vhf = g_vhf + (size_t)bh * T_ * DH_;

    {
        const __half* sq = qhf + (size_t)(qb * 128) * DH_;
        #pragma unroll
        for (int i = 0; i < 4; i++) {
            int idx = i * 256 + tid;
            int r = idx >> 3, c = idx & 7;
            uint32_t off = r * 128 + (((uint32_t)(c * 16)) ^ ((r & 7) << 4));
            *(uint4*)(smem + AQ + off) = *((const uint4*)(sq + r * DH_) + c);
        }
    }
    __syncthreads();

    uint32_t qf[4][4];
    #pragma unroll
    for (int ks = 0; ks < 4; ks++) {
        int tsel = lane >> 3;
        int r = 16 * w + (lane & 7) + (tsel & 1) * 8;
        uint32_t off = ((uint32_t)(ks * 32 + ((tsel >> 1) & 1) * 16)) ^ ((r & 7) << 4);
        ldsm_x4(qf[ks], sbs + AQ + r * 128 + off);
    }

    auto prefetch = [&](int c, int buf) {
        const int k0 = c * 64;
        const uint32_t tb = sbs + ATILE(buf);
        #pragma unroll
        for (int i = 0; i < 2; i++) {
            int idx = i * 256 + tid;
            int r = idx >> 3, cc = idx & 7;
            uint32_t off = r * 128 + (((uint32_t)(cc * 16)) ^ ((r & 7) << 4));
            const size_t g = (size_t)(k0 + r) * DH_ + cc * 8;
            cpa16(tb + off,        khf + g);
            cpa16(tb + 8192 + off, vhf + g);
        }
    };

    const int nch = 2 * qb + 2;
    prefetch(0, 0); CP_COMMIT();

    float o[8][4];
    #pragma unroll
    for (int j = 0; j < 8; j++)
        #pragma unroll
        for (int r = 0; r < 4; r++) o[j][r] = 0.f;
    float m0 = -1e30f, m1 = -1e30f, l0 = 0.f, l1 = 0.f;

    const int wrow0 = qb * 128 + 16 * w;
    const int r0 = wrow0 + (lane >> 2), r1 = r0 + 8;

    for (int c = 0; c < nch; c++) {
        const int buf = c & 1;
        CP_WAIT0();
        __syncthreads();
        if (c + 1 < nch) { prefetch(c + 1, buf ^ 1); CP_COMMIT(); }

        const int k0 = c * 64;
        const uint32_t skf = sbs + ATILE(buf);
        const uint32_t svf = skf + 8192;

        #pragma unroll
        for (int hb = 0; hb < 2; hb++) {
            const int kb0 = k0 + hb * 32;
            if (kb0 > wrow0 + 15) break;

            float s[4][4];
            #pragma unroll
            for (int j = 0; j < 4; j++)
                #pragma unroll
                for (int r = 0; r < 4; r++) s[j][r] = 0.f;

            #pragma unroll
            for (int ks = 0; ks < 4; ks++) {
                #pragma unroll
                for (int jp = 0; jp < 2; jp++) {
                    uint32_t kh_[4];
                    int rr = hb * 32 + jp * 16 + ((lane >> 4) << 3) + (lane & 7);
                    uint32_t off = ((uint32_t)(ks * 32 + (((lane >> 3) & 1) << 4)))
                                   ^ ((rr & 7) << 4);
                    ldsm_x4(kh_, skf + rr * 128 + off);
                    mma16816h(s[2*jp],   qf[ks], kh_[0], kh_[1]);
                    mma16816h(s[2*jp+1], qf[ks], kh_[2], kh_[3]);
                }
            }

            if (kb0 + 31 > wrow0) {
                #pragma unroll
                for (int j = 0; j < 4; j++) {
                    int col = kb0 + 8 * j + 2 * (lane & 3);
                    if (col     > r0) s[j][0] = -1e30f;
                    if (col + 1 > r0) s[j][1] = -1e30f;
                    if (col     > r1) s[j][2] = -1e30f;
                    if (col + 1 > r1) s[j][3] = -1e30f;
                }
            }

            float mx0 = -1e30f, mx1 = -1e30f;
            #pragma unroll
            for (int j = 0; j < 4; j++) {
                mx0 = fmaxf(mx0, fmaxf(s[j][0], s[j][1]));
                mx1 = fmaxf(mx1, fmaxf(s[j][2], s[j][3]));
            }
            mx0 = fmaxf(mx0, __shfl_xor_sync(0xffffffffu, mx0, 1));
            mx0 = fmaxf(mx0, __shfl_xor_sync(0xffffffffu, mx0, 2));
            mx1 = fmaxf(mx1, __shfl_xor_sync(0xffffffffu, mx1, 1));
            mx1 = fmaxf(mx1, __shfl_xor_sync(0xffffffffu, mx1, 2));
            float mn0 = fmaxf(m0, mx0), mn1 = fmaxf(m1, mx1);
            bool nochg = __all_sync(0xffffffffu, (mn0 == m0) && (mn1 == m1));
            if (!nochg) {
                float cr0 = ex2f(m0 - mn0), cr1 = ex2f(m1 - mn1);
                l0 *= cr0; l1 *= cr1;
                #pragma unroll
                for (int j = 0; j < 8; j++) {
                    o[j][0] *= cr0; o[j][1] *= cr0;
                    o[j][2] *= cr1; o[j][3] *= cr1;
                }
                m0 = mn0; m1 = mn1;
            }

            uint32_t ph[4][2];
            #pragma unroll
            for (int j = 0; j < 4; j++) {
                float p0 = ex2f(s[j][0] - m0), p1 = ex2f(s[j][1] - m0);
                float p2 = ex2f(s[j][2] - m1), p3 = ex2f(s[j][3] - m1);
                l0 += p0 + p1; l1 += p2 + p3;          // exact fp32 denominator
                ph[j][0] = pack_f16x2(p0, p1);
                ph[j][1] = pack_f16x2(p2, p3);
            }

            #pragma unroll
            for (int kk = 0; kk < 2; kk++) {
                uint32_t ahi[4] = {ph[2*kk][0], ph[2*kk][1], ph[2*kk+1][0], ph[2*kk+1][1]};
                #pragma unroll
                for (int jp = 0; jp < 4; jp++) {
                    uint32_t vh_[4];
                    int tsel = lane >> 3;
                    int key = hb * 32 + 16 * kk + (tsel & 1) * 8 + (lane & 7);
                    uint32_t off = ((uint32_t)((16 * jp + ((tsel >> 1) & 1) * 8) * 2))
                                   ^ ((key & 7) << 4);
                    ldsm_x4_t(vh_, svf + key * 128 + off);
                    mma16816h(o[2*jp],   ahi, vh_[0], vh_[1]);
                    mma16816h(o[2*jp+1], ahi, vh_[2], vh_[3]);
                }
            }
        }
    }

    l0 += __shfl_xor_sync(0xffffffffu, l0, 1);
    l0 += __shfl_xor_sync(0xffffffffu, l0, 2);
    l1 += __shfl_xor_sync(0xffffffffu, l1, 1);
    l1 += __shfl_xor_sync(0xffffffffu, l1, 2);
    const float i0 = 1.f / l0, i1 = 1.f / l1;

    const int tok0 = b * T_ + r0, tok1 = b * T_ + r1;
    #pragma unroll
    for (int j = 0; j < 8; j++) {
        const int n = h * DH_ + 8 * j + 2 * (lane & 3);
        float v0 = o[j][0] * i0, v1 = o[j][1] * i0;
        float v2 = o[j][2] * i1, v3 = o[j][3] * i1;
        __nv_bfloat16 h0 = __float2bfloat16(v0), h1 = __float2bfloat16(v1);
        __nv_bfloat16 h2 = __float2bfloat16(v2), h3 = __float2bfloat16(v3);
        __nv_bfloat162 hi0(h0, h1), hi1(h2, h3);
        __nv_bfloat162 lo0(__float2bfloat16(v0 - __bfloat162float(h0)),
                           __float2bfloat16(v1 - __bfloat162float(h1)));
        __nv_bfloat162 lo1(__float2bfloat16(v2 - __bfloat162float(h2)),
                           __float2bfloat16(v3 - __bfloat162float(h3)));
        size_t p0 = (size_t)tok0 * KSRC + n;
        size_t p1 = (size_t)tok1 * KSRC + n;
        *(__nv_bfloat162*)&g_aocat[p0]        = hi0;
        *(__nv_bfloat162*)&g_aocat[p0 + 1024] = lo0;
        *(__nv_bfloat162*)&g_aocat[p1]        = hi1;
        *(__nv_bfloat162*)&g_aocat[p1 + 1024] = lo1;
    }
}

// ---------------- launch --------------------------------------------------------
extern "C" void kernel_launch(void* const* d_in, const int* in_sizes, int n_in,
                              void* d_out, int out_size) {
    const float* X  = (const float*)d_in[0];
    const float* wq = (const float*)d_in[1];
    const float* wk = (const float*)d_in[2];
    const float* wv = (const float*)d_in[3];
    const float* wo = (const float*)d_in[4];
    const float* Aq = (const float*)d_in[5];
    const float* Bq = (const float*)d_in[6];
    const float* Av = (const float*)d_in[7];
    const float* Bv = (const float*)d_in[8];
    float* out = (float*)d_out;

    __nv_bfloat16 *xcat, *aocat, *wtqkv, *wto;
    cudaGetSymbolAddress((void**)&xcat,  g_xcat);
    cudaGetSymbolAddress((void**)&aocat, g_aocat);
    cudaGetSymbolAddress((void**)&wtqkv, g_wtqkv);
    cudaGetSymbolAddress((void**)&wto,   g_wto);

    cudaFuncSetAttribute(gemm_fused_kernel,
                         cudaFuncAttributeMaxDynamicSharedMemorySize, G_TOTAL);
    cudaFuncSetAttribute(gemm_fused_kernel,
                         cudaFuncAttributePreferredSharedMemoryCarveout, 100);
    cudaFuncSetAttribute(attn_mma_kernel,
                         cudaFuncAttributeMaxDynamicSharedMemorySize, A_SMEM);
    cudaFuncSetAttribute(attn_mma_kernel,
                         cudaFuncAttributePreferredSharedMemoryCarveout, 100);

    sincos_kernel<<<(T_*32 + 255) / 256, 256>>>();
    lora_split_kernel<<<MTOT, 256>>>(X, Aq, Av);
    split_wt_kernel<<<dim3(32, 32, 4), dim3(32, 8)>>>(wq, wk, wv, wo);

    gemm_fused_kernel<<<dim3(24, 64), 256, G_TOTAL>>>(xcat, wtqkv, nullptr, 1, Bq, Bv);

    attn_mma_kernel<<<dim3(T_ / 128, H_, B_), 256, A_SMEM>>>();

    gemm_fused_kernel<<<dim3(8, 64), 256, G_TOTAL>>>(aocat, wto, out, 0, nullptr, nullptr);
}

// round 15
// speedup vs baseline: 5.7151x; 1.2391x over previous
#include <cuda_runtime.h>
#include <cuda_bf16.h>
#include <cuda_fp16.h>
#include <math.h>
#include <cstdint>

#define B_   4
#define T_   2048
#define D_   1024
#define H_   16
#define DH_  64
#define R_   8
#define MTOT (B_*T_)          // 8192
#define KSRC 2048             // A storage: [hi | lo] fp16
#define WK   1024             // weight storage: single fp16
#define NSLICE 16             // K / 64
#define LORA_SCALE 4.0f
#define QSCALE 0.180336880f   // 0.125 * log2(e)  — exp2-domain logits

// ---------------- scratch (device globals: no allocation allowed) -------------
__device__ float g_xaq[MTOT*R_];
__device__ float g_xav[MTOT*R_];
__device__ float g_sin[T_*32];
__device__ float g_cos[T_*32];
__device__ __half g_xcat [MTOT*KSRC];      // [Xhi | Xlo] fp16
__device__ __half g_aocat[MTOT*KSRC];      // attention out [hi | lo] fp16
__device__ __half g_wtqkv[3072ull*WK];     // rows n of [wq|wk|wv], fp16
__device__ __half g_wto  [(size_t)D_*WK];
// head-major [b,h,t,dh], single-term fp16
__device__ __half g_qhf[MTOT*D_];
__device__ __half g_khf[MTOT*D_];
__device__ __half g_vhf[MTOT*D_];

// ---------------- warp-level MMA helpers ---------------------------------------
__device__ __forceinline__ uint32_t smem_u32(const void* p) {
    uint32_t a;
    asm("{ .reg .u64 t; cvta.to.shared.u64 t, %1; cvt.u32.u64 %0, t; }" : "=r"(a) : "l"(p));
    return a;
}
__device__ __forceinline__ void ldsm_x4(uint32_t* r, uint32_t addr) {
    asm volatile("ldmatrix.sync.aligned.m8n8.x4.shared.b16 {%0,%1,%2,%3}, [%4];"
                 : "=r"(r[0]), "=r"(r[1]), "=r"(r[2]), "=r"(r[3]) : "r"(addr));
}
__device__ __forceinline__ void ldsm_x4_t(uint32_t* r, uint32_t addr) {
    asm volatile("ldmatrix.sync.aligned.m8n8.x4.trans.shared.b16 {%0,%1,%2,%3}, [%4];"
                 : "=r"(r[0]), "=r"(r[1]), "=r"(r[2]), "=r"(r[3]) : "r"(addr));
}
__device__ __forceinline__ void mma16816h(float* d, const uint32_t* a,
                                          uint32_t b0, uint32_t b1) {
    asm volatile("mma.sync.aligned.m16n8k16.row.col.f32.f16.f16.f32 "
                 "{%0,%1,%2,%3}, {%4,%5,%6,%7}, {%8,%9}, {%0,%1,%2,%3};"
                 : "+f"(d[0]), "+f"(d[1]), "+f"(d[2]), "+f"(d[3])
                 : "r"(a[0]), "r"(a[1]), "r"(a[2]), "r"(a[3]), "r"(b0), "r"(b1));
}
__device__ __forceinline__ uint32_t pack_f16x2(float e, float o) {
    uint32_t d;
    asm("cvt.rn.f16x2.f32 %0, %1, %2;" : "=r"(d) : "f"(o), "f"(e));
    return d;
}
__device__ __forceinline__ float ex2f(float x) {
    float r;
    asm("ex2.approx.ftz.f32 %0, %1;" : "=f"(r) : "f"(x));
    return r;
}
__device__ __forceinline__ void cpa16(uint32_t dst, const void* src) {
    asm volatile("cp.async.cg.shared.global [%0], [%1], 16;" :: "r"(dst), "l"(src) : "memory");
}
#define CP_COMMIT() asm volatile("cp.async.commit_group;" ::: "memory")
#define CP_WAIT0()  asm volatile("cp.async.wait_group 0;"  ::: "memory")

// ---------------- sin/cos table -----------------------------------------------
__global__ void sincos_kernel() {
    int idx = blockIdx.x * blockDim.x + threadIdx.x;
    if (idx >= T_*32) return;
    int t = idx >> 5, j = idx & 31;
    double theta = (double)t / pow(10000.0, (double)j / 32.0);
    g_sin[idx] = (float)sin(theta);
    g_cos[idx] = (float)cos(theta);
}

// ---------------- fused LoRA down-proj + X split (fp16 2-term) ------------------
__global__ void lora_split_kernel(const float* __restrict__ X,
                                  const float* __restrict__ Aq,
                                  const float* __restrict__ Av) {
    __shared__ float xrow[1024];
    const int m = blockIdx.x;
    const int tid = threadIdx.x;
    const int lane = tid & 31, w = tid >> 5;

    float4 x = ((const float4*)(X + (size_t)m * D_))[tid];
    ((float4*)xrow)[tid] = x;

    float xs[4] = {x.x, x.y, x.z, x.w};
    __half h[4];
    float  l[4];
    #pragma unroll
    for (int i = 0; i < 4; i++) {
        h[i] = __float2half_rn(xs[i]);
        l[i] = xs[i] - __half2float(h[i]);
    }
    size_t base = (size_t)m * KSRC + tid * 4;
    *(__half2*)&g_xcat[base]      = __halves2half2(h[0], h[1]);
    *(__half2*)&g_xcat[base+2]    = __halves2half2(h[2], h[3]);
    *(__half2*)&g_xcat[base+1024] = __floats2half2_rn(l[0], l[1]);
    *(__half2*)&g_xcat[base+1026] = __floats2half2_rn(l[2], l[3]);
    __syncthreads();

    #pragma unroll
    for (int cc = 0; cc < 2; cc++) {
        int c = w * 2 + cc;
        const float* A = (c < 8) ? Aq : Av;
        int col = c & 7;
        float s = 0.f;
        for (int k = lane; k < D_; k += 32)
            s += xrow[k] * A[k * R_ + col];
        #pragma unroll
        for (int off = 16; off; off >>= 1)
            s += __shfl_down_sync(0xffffffffu, s, off);
        if (lane == 0) {
            float* XA = (c < 8) ? g_xaq : g_xav;
            XA[m * R_ + col] = s;
        }
    }
}

// ---------------- transpose weights -> fp16 -------------------------------------
__global__ void split_wt_kernel(const float* __restrict__ W0, const float* __restrict__ W1,
                                const float* __restrict__ W2, const float* __restrict__ W3) {
    const float* Ws[4] = {W0, W1, W2, W3};
    const float* W = Ws[blockIdx.z];
    __shared__ float tile[32][33];
    int bx = blockIdx.x * 32, by = blockIdx.y * 32;
    for (int i = threadIdx.y; i < 32; i += 8)
        tile[i][threadIdx.x] = W[(size_t)(by + i) * D_ + bx + threadIdx.x];
    __syncthreads();
    for (int i = threadIdx.y; i < 32; i += 8) {
        int n = bx + i, k = by + threadIdx.x;
        float x = tile[threadIdx.x][i];
        __half* out = (blockIdx.z < 3)
            ? g_wtqkv + (size_t)(blockIdx.z * 1024 + n) * WK
            : g_wto   + (size_t)n * WK;
        out[k] = __float2half_rn(x);
    }
}

// ================= fused fp16 GEMM (128x128 tile, 256 thr, 2-term A) ===========
// 16 k-slices; per slice load Ah|Al|B once, two MMA passes (Ah*B + Al*B).
#define GSTG   49152                    // Ah 16K | Al 16K | B 16K
#define GAH(s) ((s) * GSTG)
#define GAL(s) ((s) * GSTG + 16384)
#define GB(s)  ((s) * GSTG + 32768)
#define G_LB   98304
#define G_TOTAL 102400

__global__ void __launch_bounds__(256, 2)
gemm_fused_kernel(const __half* __restrict__ Acat,
                  const __half* __restrict__ Bcat,
                  float* __restrict__ C, int qkv,
                  const float* __restrict__ Bq, const float* __restrict__ Bv)
{
    extern __shared__ char smem[];
    const uint32_t sbase = smem_u32(smem);
    const int tid  = threadIdx.x;
    const int lane = tid & 31;
    const int wid  = tid >> 5;
    const int wm   = wid & 1;
    const int wn   = wid >> 1;
    const int row0 = blockIdx.y * 128, col0 = blockIdx.x * 128;

    float acc[4][4][4];
    #pragma unroll
    for (int i = 0; i < 4; i++)
        #pragma unroll
        for (int j = 0; j < 4; j++)
            #pragma unroll
            for (int r = 0; r < 4; r++) acc[i][j][r] = 0.f;

    auto prefetch = [&](int sl, int stg) {
        const int kb = sl * 64;
        #pragma unroll
        for (int i = 0; i < 4; i++) {
            int idx = i * 256 + tid;
            int r = idx >> 3, cc = idx & 7;
            uint32_t off = r * 128 + (((uint32_t)(cc * 16)) ^ ((r & 7) << 4));
            cpa16(sbase + GAH(stg) + off, Acat + (size_t)(row0 + r) * KSRC + kb + cc * 8);
            cpa16(sbase + GAL(stg) + off, Acat + (size_t)(row0 + r) * KSRC + 1024 + kb + cc * 8);
            cpa16(sbase + GB(stg)  + off, Bcat + (size_t)(col0 + r) * WK + kb + cc * 8);
        }
    };

    prefetch(0, 0); CP_COMMIT();

    for (int c = 0; c < NSLICE; c++) {
        const int stg = c & 1;
        CP_WAIT0();
        __syncthreads();
        if (c + 1 < NSLICE) { prefetch(c + 1, stg ^ 1); CP_COMMIT(); }
        const uint32_t sb = sbase + GB(stg);
        #pragma unroll
        for (int pass = 0; pass < 2; pass++) {
            const uint32_t sa = sbase + (pass ? GAL(stg) : GAH(stg));
            #pragma unroll
            for (int ks = 0; ks < 4; ks++) {
                uint32_t af[4][4], bfr[2][4];
                #pragma unroll
                for (int ma = 0; ma < 4; ma++) {
                    int r = wm * 64 + ma * 16 + (lane & 15);
                    uint32_t off = (uint32_t)(ks * 32 + ((lane >> 4) << 4));
                    ldsm_x4(af[ma], sa + r * 128 + (off ^ ((r & 7) << 4)));
                }
                #pragma unroll
                for (int nb = 0; nb < 2; nb++) {
                    int r = wn * 32 + nb * 16 + ((lane >> 4) << 3) + (lane & 7);
                    uint32_t off = (uint32_t)(ks * 32 + (((lane >> 3) & 1) << 4));
                    ldsm_x4(bfr[nb], sb + r * 128 + (off ^ ((r & 7) << 4)));
                }
                #pragma unroll
                for (int ma = 0; ma < 4; ma++)
                    #pragma unroll
                    for (int na = 0; na < 4; na++)
                        mma16816h(acc[ma][na], af[ma],
                                  bfr[na >> 1][(na & 1) * 2], bfr[na >> 1][(na & 1) * 2 + 1]);
            }
        }
    }
    __syncthreads();

    const int region = qkv ? (col0 >> 10) : 3;
    const float* XA = (region == 0) ? g_xaq : (region == 2) ? g_xav : nullptr;
    float* LBs = (float*)(smem + G_LB);
    if (qkv && region != 1) {
        const float* Bsrc = (region == 0) ? Bq : Bv;
        const int cbase = col0 & 1023;
        #pragma unroll
        for (int i = 0; i < 4; i++) {
            int idx = i * 256 + tid;
            LBs[idx] = Bsrc[(idx >> 7) * D_ + cbase + (idx & 127)];
        }
        __syncthreads();
    }

    #pragma unroll
    for (int ma = 0; ma < 4; ma++) {
        const int mlo = row0 + wm * 64 + ma * 16 + (lane >> 2);
        const int mhi = mlo + 8;
        float xal[8], xah[8];
        if (XA) {
            #pragma unroll
            for (int r = 0; r < R_; r++) {
                xal[r] = XA[mlo * R_ + r];
                xah[r] = XA[mhi * R_ + r];
            }
        }
        const int tlo = mlo & (T_ - 1), thi = mhi & (T_ - 1);
        #pragma unroll
        for (int na = 0; na < 4; na++) {
            const int n  = col0 + wn * 32 + na * 8 + (lane & 3) * 2;
            const int nl = n - col0;
            float v0 = acc[ma][na][0], v1 = acc[ma][na][1];
            float v2 = acc[ma][na][2], v3 = acc[ma][na][3];
            if (XA) {
                float s0 = 0.f, s1 = 0.f, s2_ = 0.f, s3 = 0.f;
                #pragma unroll
                for (int r = 0; r < R_; r++) {
                    float b0 = LBs[r * 128 + nl], b1 = LBs[r * 128 + nl + 1];
                    s0 += xal[r] * b0; s1 += xal[r] * b1;
                    s2_ += xah[r] * b0; s3 += xah[r] * b1;
                }
                v0 += LORA_SCALE * s0; v1 += LORA_SCALE * s1;
                v2 += LORA_SCALE * s2_; v3 += LORA_SCALE * s3;
            }
            if (region <= 1) {              // RoPE for Q and K
                const int jj = (n & 63) >> 1;
                float sn = g_sin[tlo * 32 + jj], cs = g_cos[tlo * 32 + jj];
                float e = v0, o = v1;
                v0 = e * cs - o * sn; v1 = e * sn + o * cs;
                sn = g_sin[thi * 32 + jj]; cs = g_cos[thi * 32 + jj];
                e = v2; o = v3;
                v2 = e * cs - o * sn; v3 = e * sn + o * cs;
            }
            if (region == 0) { v0 *= QSCALE; v1 *= QSCALE; v2 *= QSCALE; v3 *= QSCALE; }
            if (!qkv) {
                *(float2*)&C[(size_t)mlo * D_ + n] = make_float2(v0, v1);
                *(float2*)&C[(size_t)mhi * D_ + n] = make_float2(v2, v3);
            } else {
                const int bq = mlo >> 11, hh = (n & 1023) >> 6, dd = n & 63;
                size_t olo = ((size_t)(bq * H_ + hh) * T_ + tlo) * DH_ + dd;
                size_t ohi = ((size_t)(bq * H_ + hh) * T_ + thi) * DH_ + dd;
                __half* dst = (region == 0) ? g_qhf : (region == 1) ? g_khf : g_vhf;
                *(__half2*)&dst[olo] = __floats2half2_rn(v0, v1);
                *(__half2*)&dst[ohi] = __floats2half2_rn(v2, v3);
            }
        }
    }
}

// ================= tensor-core flash attention =================================
// Single-term fp16 for S and PV.  Q tile 16KB; per-chunk tiles KHF|VHF (16KB x2).
#define AQ 0
#define ATILE(buf) (16384 + (buf) * 16384)
#define A_SMEM 49152

__global__ void __launch_bounds__(256, 2)
attn_mma_kernel() {
    extern __shared__ char smem[];
    const uint32_t sbs = smem_u32(smem);
    const int tid = threadIdx.x, lane = tid & 31, w = tid >> 5;
    const int qb = gridDim.x - 1 - blockIdx.x;
    const int h = blockIdx.y, b = blockIdx.z;
    const int bh = b * H_ + h;
    const __half* qhf = g_qhf + (size_t)bh * T_ * DH_;
    const __half* khf = g_khf + (size_t)bh * T_ * DH_;
    const __half* vhf = g_vhf + (size_t)bh * T_ * DH_;

    {
        const __half* sq = qhf + (size_t)(qb * 128) * DH_;
        #pragma unroll
        for (int i = 0; i < 4; i++) {
            int idx = i * 256 + tid;
            int r = idx >> 3, c = idx & 7;
            uint32_t off = r * 128 + (((uint32_t)(c * 16)) ^ ((r & 7) << 4));
            *(uint4*)(smem + AQ + off) = *((const uint4*)(sq + r * DH_) + c);
        }
    }
    __syncthreads();

    uint32_t qf[4][4];
    #pragma unroll
    for (int ks = 0; ks < 4; ks++) {
        int tsel = lane >> 3;
        int r = 16 * w + (lane & 7) + (tsel & 1) * 8;
        uint32_t off = ((uint32_t)(ks * 32 + ((tsel >> 1) & 1) * 16)) ^ ((r & 7) << 4);
        ldsm_x4(qf[ks], sbs + AQ + r * 128 + off);
    }

    auto prefetch = [&](int c, int buf) {
        const int k0 = c * 64;
        const uint32_t tb = sbs + ATILE(buf);
        #pragma unroll
        for (int i = 0; i < 2; i++) {
            int idx = i * 256 + tid;
            int r = idx >> 3, cc = idx & 7;
            uint32_t off = r * 128 + (((uint32_t)(cc * 16)) ^ ((r & 7) << 4));
            const size_t g = (size_t)(k0 + r) * DH_ + cc * 8;
            cpa16(tb + off,        khf + g);
            cpa16(tb + 8192 + off, vhf + g);
        }
    };

    const int nch = 2 * qb + 2;
    prefetch(0, 0); CP_COMMIT();

    float o[8][4];
    #pragma unroll
    for (int j = 0; j < 8; j++)
        #pragma unroll
        for (int r = 0; r < 4; r++) o[j][r] = 0.f;
    float m0 = -1e30f, m1 = -1e30f, l0 = 0.f, l1 = 0.f;

    const int wrow0 = qb * 128 + 16 * w;
    const int r0 = wrow0 + (lane >> 2), r1 = r0 + 8;

    for (int c = 0; c < nch; c++) {
        const int buf = c & 1;
        CP_WAIT0();
        __syncthreads();
        if (c + 1 < nch) { prefetch(c + 1, buf ^ 1); CP_COMMIT(); }

        const int k0 = c * 64;
        const uint32_t skf = sbs + ATILE(buf);
        const uint32_t svf = skf + 8192;

        #pragma unroll
        for (int hb = 0; hb < 2; hb++) {
            const int kb0 = k0 + hb * 32;
            if (kb0 > wrow0 + 15) break;

            float s[4][4];
            #pragma unroll
            for (int j = 0; j < 4; j++)
                #pragma unroll
                for (int r = 0; r < 4; r++) s[j][r] = 0.f;

            #pragma unroll
            for (int ks = 0; ks < 4; ks++) {
                #pragma unroll
                for (int jp = 0; jp < 2; jp++) {
                    uint32_t kh_[4];
                    int rr = hb * 32 + jp * 16 + ((lane >> 4) << 3) + (lane & 7);
                    uint32_t off = ((uint32_t)(ks * 32 + (((lane >> 3) & 1) << 4)))
                                   ^ ((rr & 7) << 4);
                    ldsm_x4(kh_, skf + rr * 128 + off);
                    mma16816h(s[2*jp],   qf[ks], kh_[0], kh_[1]);
                    mma16816h(s[2*jp+1], qf[ks], kh_[2], kh_[3]);
                }
            }

            if (kb0 + 31 > wrow0) {
                #pragma unroll
                for (int j = 0; j < 4; j++) {
                    int col = kb0 + 8 * j + 2 * (lane & 3);
                    if (col     > r0) s[j][0] = -1e30f;
                    if (col + 1 > r0) s[j][1] = -1e30f;
                    if (col     > r1) s[j][2] = -1e30f;
                    if (col + 1 > r1) s[j][3] = -1e30f;
                }
            }

            float mx0 = -1e30f, mx1 = -1e30f;
            #pragma unroll
            for (int j = 0; j < 4; j++) {
                mx0 = fmaxf(mx0, fmaxf(s[j][0], s[j][1]));
                mx1 = fmaxf(mx1, fmaxf(s[j][2], s[j][3]));
            }
            mx0 = fmaxf(mx0, __shfl_xor_sync(0xffffffffu, mx0, 1));
            mx0 = fmaxf(mx0, __shfl_xor_sync(0xffffffffu, mx0, 2));
            mx1 = fmaxf(mx1, __shfl_xor_sync(0xffffffffu, mx1, 1));
            mx1 = fmaxf(mx1, __shfl_xor_sync(0xffffffffu, mx1, 2));
            float mn0 = fmaxf(m0, mx0), mn1 = fmaxf(m1, mx1);
            bool nochg = __all_sync(0xffffffffu, (mn0 == m0) && (mn1 == m1));
            if (!nochg) {
                float cr0 = ex2f(m0 - mn0), cr1 = ex2f(m1 - mn1);
                l0 *= cr0; l1 *= cr1;
                #pragma unroll
                for (int j = 0; j < 8; j++) {
                    o[j][0] *= cr0; o[j][1] *= cr0;
                    o[j][2] *= cr1; o[j][3] *= cr1;
                }
                m0 = mn0; m1 = mn1;
            }

            uint32_t ph[4][2];
            #pragma unroll
            for (int j = 0; j < 4; j++) {
                float p0 = ex2f(s[j][0] - m0), p1 = ex2f(s[j][1] - m0);
                float p2 = ex2f(s[j][2] - m1), p3 = ex2f(s[j][3] - m1);
                l0 += p0 + p1; l1 += p2 + p3;          // exact fp32 denominator
                ph[j][0] = pack_f16x2(p0, p1);
                ph[j][1] = pack_f16x2(p2, p3);
            }

            #pragma unroll
            for (int kk = 0; kk < 2; kk++) {
                uint32_t ahi[4] = {ph[2*kk][0], ph[2*kk][1], ph[2*kk+1][0], ph[2*kk+1][1]};
                #pragma unroll
                for (int jp = 0; jp < 4; jp++) {
                    uint32_t vh_[4];
                    int tsel = lane >> 3;
                    int key = hb * 32 + 16 * kk + (tsel & 1) * 8 + (lane & 7);
                    uint32_t off = ((uint32_t)((16 * jp + ((tsel >> 1) & 1) * 8) * 2))
                                   ^ ((key & 7) << 4);
                    ldsm_x4_t(vh_, svf + key * 128 + off);
                    mma16816h(o[2*jp],   ahi, vh_[0], vh_[1]);
                    mma16816h(o[2*jp+1], ahi, vh_[2], vh_[3]);
                }
            }
        }
    }

    l0 += __shfl_xor_sync(0xffffffffu, l0, 1);
    l0 += __shfl_xor_sync(0xffffffffu, l0, 2);
    l1 += __shfl_xor_sync(0xffffffffu, l1, 1);
    l1 += __shfl_xor_sync(0xffffffffu, l1, 2);
    const float i0 = 1.f / l0, i1 = 1.f / l1;

    const int tok0 = b * T_ + r0, tok1 = b * T_ + r1;
    #pragma unroll
    for (int j = 0; j < 8; j++) {
        const int n = h * DH_ + 8 * j + 2 * (lane & 3);
        float v0 = o[j][0] * i0, v1 = o[j][1] * i0;
        float v2 = o[j][2] * i1, v3 = o[j][3] * i1;
        __half h0 = __float2half_rn(v0), h1 = __float2half_rn(v1);
        __half h2 = __float2half_rn(v2), h3 = __float2half_rn(v3);
        size_t p0 = (size_t)tok0 * KSRC + n;
        size_t p1 = (size_t)tok1 * KSRC + n;
        *(__half2*)&g_aocat[p0]        = __halves2half2(h0, h1);
        *(__half2*)&g_aocat[p0 + 1024] = __floats2half2_rn(v0 - __half2float(h0),
                                                           v1 - __half2float(h1));
        *(__half2*)&g_aocat[p1]        = __halves2half2(h2, h3);
        *(__half2*)&g_aocat[p1 + 1024] = __floats2half2_rn(v2 - __half2float(h2),
                                                           v3 - __half2float(h3));
    }
}

// ---------------- launch --------------------------------------------------------
extern "C" void kernel_launch(void* const* d_in, const int* in_sizes, int n_in,
                              void* d_out, int out_size) {
    const float* X  = (const float*)d_in[0];
    const float* wq = (const float*)d_in[1];
    const float* wk = (const float*)d_in[2];
    const float* wv = (const float*)d_in[3];
    const float* wo = (const float*)d_in[4];
    const float* Aq = (const float*)d_in[5];
    const float* Bq = (const float*)d_in[6];
    const float* Av = (const float*)d_in[7];
    const float* Bv = (const float*)d_in[8];
    float* out = (float*)d_out;

    __half *xcat, *aocat, *wtqkv, *wto;
    cudaGetSymbolAddress((void**)&xcat,  g_xcat);
    cudaGetSymbolAddress((void**)&aocat, g_aocat);
    cudaGetSymbolAddress((void**)&wtqkv, g_wtqkv);
    cudaGetSymbolAddress((void**)&wto,   g_wto);

    cudaFuncSetAttribute(gemm_fused_kernel,
                         cudaFuncAttributeMaxDynamicSharedMemorySize, G_TOTAL);
    cudaFuncSetAttribute(gemm_fused_kernel,
                         cudaFuncAttributePreferredSharedMemoryCarveout, 100);
    cudaFuncSetAttribute(attn_mma_kernel,
                         cudaFuncAttributeMaxDynamicSharedMemorySize, A_SMEM);
    cudaFuncSetAttribute(attn_mma_kernel,
                         cudaFuncAttributePreferredSharedMemoryCarveout, 100);

    sincos_kernel<<<(T_*32 + 255) / 256, 256>>>();
    lora_split_kernel<<<MTOT, 256>>>(X, Aq, Av);
    split_wt_kernel<<<dim3(32, 32, 4), dim3(32, 8)>>>(wq, wk, wv, wo);

    gemm_fused_kernel<<<dim3(24, 64), 256, G_TOTAL>>>(xcat, wtqkv, nullptr, 1, Bq, Bv);

    attn_mma_kernel<<<dim3(T_ / 128, H_, B_), 256, A_SMEM>>>();

    gemm_fused_kernel<<<dim3(8, 64), 256, G_TOTAL>>>(aocat, wto, out, 0, nullptr, nullptr);
}

// round 17
// speedup vs baseline: 7.5417x; 1.3196x over previous
#include <cuda_runtime.h>
#include <cuda_bf16.h>
#include <cuda_fp16.h>
#include <math.h>
#include <cstdint>

#define B_   4
#define T_   2048
#define D_   1024
#define H_   16
#define DH_  64
#define R_   8
#define MTOT (B_*T_)          // 8192
#define WK   1024             // fp16 K width (single term everywhere)
#define NSLICE 16             // K / 64
#define LORA_SCALE 4.0f
#define QSCALE 0.180336880f   // 0.125 * log2(e)  — exp2-domain logits

// ---------------- scratch (device globals: no allocation allowed) -------------
__device__ float g_xaq[MTOT*R_];
__device__ float g_xav[MTOT*R_];
__device__ float g_sin[T_*32];
__device__ float g_cos[T_*32];
__device__ __half g_xh [MTOT*WK];          // X fp16 single
__device__ __half g_ao [MTOT*WK];          // attention out fp16 single
__device__ __half g_wtqkv[3072ull*WK];     // rows n of [wq|wk|wv], fp16
__device__ __half g_wto  [(size_t)D_*WK];
// head-major [b,h,t,dh], single-term fp16
__device__ __half g_qhf[MTOT*D_];
__device__ __half g_khf[MTOT*D_];
__device__ __half g_vhf[MTOT*D_];

// ---------------- warp-level MMA helpers ---------------------------------------
__device__ __forceinline__ uint32_t smem_u32(const void* p) {
    uint32_t a;
    asm("{ .reg .u64 t; cvta.to.shared.u64 t, %1; cvt.u32.u64 %0, t; }" : "=r"(a) : "l"(p));
    return a;
}
__device__ __forceinline__ void ldsm_x4(uint32_t* r, uint32_t addr) {
    asm volatile("ldmatrix.sync.aligned.m8n8.x4.shared.b16 {%0,%1,%2,%3}, [%4];"
                 : "=r"(r[0]), "=r"(r[1]), "=r"(r[2]), "=r"(r[3]) : "r"(addr));
}
__device__ __forceinline__ void ldsm_x4_t(uint32_t* r, uint32_t addr) {
    asm volatile("ldmatrix.sync.aligned.m8n8.x4.trans.shared.b16 {%0,%1,%2,%3}, [%4];"
                 : "=r"(r[0]), "=r"(r[1]), "=r"(r[2]), "=r"(r[3]) : "r"(addr));
}
__device__ __forceinline__ void mma16816h(float* d, const uint32_t* a,
                                          uint32_t b0, uint32_t b1) {
    asm volatile("mma.sync.aligned.m16n8k16.row.col.f32.f16.f16.f32 "
                 "{%0,%1,%2,%3}, {%4,%5,%6,%7}, {%8,%9}, {%0,%1,%2,%3};"
                 : "+f"(d[0]), "+f"(d[1]), "+f"(d[2]), "+f"(d[3])
                 : "r"(a[0]), "r"(a[1]), "r"(a[2]), "r"(a[3]), "r"(b0), "r"(b1));
}
__device__ __forceinline__ uint32_t pack_f16x2(float e, float o) {
    uint32_t d;
    asm("cvt.rn.f16x2.f32 %0, %1, %2;" : "=r"(d) : "f"(o), "f"(e));
    return d;
}
__device__ __forceinline__ float ex2f(float x) {
    float r;
    asm("ex2.approx.ftz.f32 %0, %1;" : "=f"(r) : "f"(x));
    return r;
}
__device__ __forceinline__ void cpa16(uint32_t dst, const void* src) {
    asm volatile("cp.async.cg.shared.global [%0], [%1], 16;" :: "r"(dst), "l"(src) : "memory");
}
#define CP_COMMIT() asm volatile("cp.async.commit_group;" ::: "memory")
#define CP_WAIT1()  asm volatile("cp.async.wait_group 1;"  ::: "memory")
#define CP_WAIT0()  asm volatile("cp.async.wait_group 0;"  ::: "memory")

// ---------------- sin/cos table -----------------------------------------------
__global__ void sincos_kernel() {
    int idx = blockIdx.x * blockDim.x + threadIdx.x;
    if (idx >= T_*32) return;
    int t = idx >> 5, j = idx & 31;
    double theta = (double)t / pow(10000.0, (double)j / 32.0);
    g_sin[idx] = (float)sin(theta);
    g_cos[idx] = (float)cos(theta);
}

// ---------------- fused LoRA down-proj + X -> fp16 ------------------------------
__global__ void lora_split_kernel(const float* __restrict__ X,
                                  const float* __restrict__ Aq,
                                  const float* __restrict__ Av) {
    __shared__ float xrow[1024];
    const int m = blockIdx.x;
    const int tid = threadIdx.x;
    const int lane = tid & 31, w = tid >> 5;

    float4 x = ((const float4*)(X + (size_t)m * D_))[tid];
    ((float4*)xrow)[tid] = x;

    size_t base = (size_t)m * WK + tid * 4;
    *(__half2*)&g_xh[base]   = __floats2half2_rn(x.x, x.y);
    *(__half2*)&g_xh[base+2] = __floats2half2_rn(x.z, x.w);
    __syncthreads();

    #pragma unroll
    for (int cc = 0; cc < 2; cc++) {
        int c = w * 2 + cc;
        const float* A = (c < 8) ? Aq : Av;
        int col = c & 7;
        float s = 0.f;
        for (int k = lane; k < D_; k += 32)
            s += xrow[k] * A[k * R_ + col];
        #pragma unroll
        for (int off = 16; off; off >>= 1)
            s += __shfl_down_sync(0xffffffffu, s, off);
        if (lane == 0) {
            float* XA = (c < 8) ? g_xaq : g_xav;
            XA[m * R_ + col] = s;
        }
    }
}

// ---------------- transpose weights -> fp16 -------------------------------------
__global__ void split_wt_kernel(const float* __restrict__ W0, const float* __restrict__ W1,
                                const float* __restrict__ W2, const float* __restrict__ W3) {
    const float* Ws[4] = {W0, W1, W2, W3};
    const float* W = Ws[blockIdx.z];
    __shared__ float tile[32][33];
    int bx = blockIdx.x * 32, by = blockIdx.y * 32;
    for (int i = threadIdx.y; i < 32; i += 8)
        tile[i][threadIdx.x] = W[(size_t)(by + i) * D_ + bx + threadIdx.x];
    __syncthreads();
    for (int i = threadIdx.y; i < 32; i += 8) {
        int n = bx + i, k = by + threadIdx.x;
        float x = tile[threadIdx.x][i];
        __half* out = (blockIdx.z < 3)
            ? g_wtqkv + (size_t)(blockIdx.z * 1024 + n) * WK
            : g_wto   + (size_t)n * WK;
        out[k] = __float2half_rn(x);
    }
}

// ================= fused fp16 GEMM (128x128 tile, 256 thr, single pass) ========
// 3-stage cp.async ring, single sync per slice. 2 CTAs/SM.
#define GSTG   32768                    // A 16K | B 16K
#define GA(s)  ((s) * GSTG)
#define GB(s)  ((s) * GSTG + 16384)
#define G_LB   98304
#define G_TOTAL 102400

__global__ void __launch_bounds__(256, 2)
gemm_fused_kernel(const __half* __restrict__ Acat,
                  const __half* __restrict__ Bcat,
                  float* __restrict__ C, int qkv,
                  const float* __restrict__ Bq, const float* __restrict__ Bv)
{
    extern __shared__ char smem[];
    const uint32_t sbase = smem_u32(smem);
    const int tid  = threadIdx.x;
    const int lane = tid & 31;
    const int wid  = tid >> 5;
    const int wm   = wid & 1;
    const int wn   = wid >> 1;
    const int row0 = blockIdx.y * 128, col0 = blockIdx.x * 128;

    float acc[4][4][4];
    #pragma unroll
    for (int i = 0; i < 4; i++)
        #pragma unroll
        for (int j = 0; j < 4; j++)
            #pragma unroll
            for (int r = 0; r < 4; r++) acc[i][j][r] = 0.f;

    auto prefetch = [&](int sl, int stg) {
        const int kb = sl * 64;
        #pragma unroll
        for (int i = 0; i < 4; i++) {
            int idx = i * 256 + tid;
            int r = idx >> 3, cc = idx & 7;
            uint32_t off = r * 128 + (((uint32_t)(cc * 16)) ^ ((r & 7) << 4));
            cpa16(sbase + GA(stg) + off, Acat + (size_t)(row0 + r) * WK + kb + cc * 8);
            cpa16(sbase + GB(stg) + off, Bcat + (size_t)(col0 + r) * WK + kb + cc * 8);
        }
    };

    prefetch(0, 0); CP_COMMIT();
    prefetch(1, 1); CP_COMMIT();

    int sc = 0, s2 = 2;
    for (int c = 0; c < NSLICE; c++) {
        CP_WAIT1();
        __syncthreads();
        if (c + 2 < NSLICE) prefetch(c + 2, s2);
        CP_COMMIT();
        const uint32_t sa = sbase + GA(sc);
        const uint32_t sb = sbase + GB(sc);
        #pragma unroll
        for (int ks = 0; ks < 4; ks++) {
            uint32_t af[4][4], bfr[2][4];
            #pragma unroll
            for (int ma = 0; ma < 4; ma++) {
                int r = wm * 64 + ma * 16 + (lane & 15);
                uint32_t off = (uint32_t)(ks * 32 + ((lane >> 4) << 4));
                ldsm_x4(af[ma], sa + r * 128 + (off ^ ((r & 7) << 4)));
            }
            #pragma unroll
            for (int nb = 0; nb < 2; nb++) {
                int r = wn * 32 + nb * 16 + ((lane >> 4) << 3) + (lane & 7);
                uint32_t off = (uint32_t)(ks * 32 + (((lane >> 3) & 1) << 4));
                ldsm_x4(bfr[nb], sb + r * 128 + (off ^ ((r & 7) << 4)));
            }
            #pragma unroll
            for (int ma = 0; ma < 4; ma++)
                #pragma unroll
                for (int na = 0; na < 4; na++)
                    mma16816h(acc[ma][na], af[ma],
                              bfr[na >> 1][(na & 1) * 2], bfr[na >> 1][(na & 1) * 2 + 1]);
        }
        sc = (sc == 2) ? 0 : sc + 1;
        s2 = (s2 == 2) ? 0 : s2 + 1;
    }
    __syncthreads();

    const int region = qkv ? (col0 >> 10) : 3;
    const float* XA = (region == 0) ? g_xaq : (region == 2) ? g_xav : nullptr;
    float* LBs = (float*)(smem + G_LB);
    if (qkv && region != 1) {
        const float* Bsrc = (region == 0) ? Bq : Bv;
        const int cbase = col0 & 1023;
        #pragma unroll
        for (int i = 0; i < 4; i++) {
            int idx = i * 256 + tid;
            LBs[idx] = Bsrc[(idx >> 7) * D_ + cbase + (idx & 127)];
        }
        __syncthreads();
    }

    #pragma unroll
    for (int ma = 0; ma < 4; ma++) {
        const int mlo = row0 + wm * 64 + ma * 16 + (lane >> 2);
        const int mhi = mlo + 8;
        float xal[8], xah[8];
        if (XA) {
            #pragma unroll
            for (int r = 0; r < R_; r++) {
                xal[r] = XA[mlo * R_ + r];
                xah[r] = XA[mhi * R_ + r];
            }
        }
        const int tlo = mlo & (T_ - 1), thi = mhi & (T_ - 1);
        #pragma unroll
        for (int na = 0; na < 4; na++) {
            const int n  = col0 + wn * 32 + na * 8 + (lane & 3) * 2;
            const int nl = n - col0;
            float v0 = acc[ma][na][0], v1 = acc[ma][na][1];
            float v2 = acc[ma][na][2], v3 = acc[ma][na][3];
            if (XA) {
                float s0 = 0.f, s1 = 0.f, s2_ = 0.f, s3 = 0.f;
                #pragma unroll
                for (int r = 0; r < R_; r++) {
                    float b0 = LBs[r * 128 + nl], b1 = LBs[r * 128 + nl + 1];
                    s0 += xal[r] * b0; s1 += xal[r] * b1;
                    s2_ += xah[r] * b0; s3 += xah[r] * b1;
                }
                v0 += LORA_SCALE * s0; v1 += LORA_SCALE * s1;
                v2 += LORA_SCALE * s2_; v3 += LORA_SCALE * s3;
            }
            if (region <= 1) {              // RoPE for Q and K
                const int jj = (n & 63) >> 1;
                float sn = g_sin[tlo * 32 + jj], cs = g_cos[tlo * 32 + jj];
                float e = v0, o = v1;
                v0 = e * cs - o * sn; v1 = e * sn + o * cs;
                sn = g_sin[thi * 32 + jj]; cs = g_cos[thi * 32 + jj];
                e = v2; o = v3;
                v2 = e * cs - o * sn; v3 = e * sn + o * cs;
            }
            if (region == 0) { v0 *= QSCALE; v1 *= QSCALE; v2 *= QSCALE; v3 *= QSCALE; }
            if (!qkv) {
                *(float2*)&C[(size_t)mlo * D_ + n] = make_float2(v0, v1);
                *(float2*)&C[(size_t)mhi * D_ + n] = make_float2(v2, v3);
            } else {
                const int bq = mlo >> 11, hh = (n & 1023) >> 6, dd = n & 63;
                size_t olo = ((size_t)(bq * H_ + hh) * T_ + tlo) * DH_ + dd;
                size_t ohi = ((size_t)(bq * H_ + hh) * T_ + thi) * DH_ + dd;
                __half* dst = (region == 0) ? g_qhf : (region == 1) ? g_khf : g_vhf;
                *(__half2*)&dst[olo] = __floats2half2_rn(v0, v1);
                *(__half2*)&dst[ohi] = __floats2half2_rn(v2, v3);
            }
        }
    }
}

// ================= tensor-core flash attention =================================
// Single-term fp16 for S and PV.  Q tile 16KB; per-chunk tiles KHF|VHF (16KB x2).
#define AQ 0
#define ATILE(buf) (16384 + (buf) * 16384)
#define A_SMEM 49152

__global__ void __launch_bounds__(256, 2)
attn_mma_kernel() {
    extern __shared__ char smem[];
    const uint32_t sbs = smem_u32(smem);
    const int tid = threadIdx.x, lane = tid & 31, w = tid >> 5;
    const int qb = gridDim.x - 1 - blockIdx.x;
    const int h = blockIdx.y, b = blockIdx.z;
    const int bh = b * H_ + h;
    const __half* qhf = g_qhf + (size_t)bh * T_ * DH_;
    const __half* khf = g_khf + (size_t)bh * T_ * DH_;
    const __half* vhf = g_vhf + (size_t)bh * T_ * DH_;

    {
        const __half* sq = qhf + (size_t)(qb * 128) * DH_;
        #pragma unroll
        for (int i = 0; i < 4; i++) {
            int idx = i * 256 + tid;
            int r = idx >> 3, c = idx & 7;
            uint32_t off = r * 128 + (((uint32_t)(c * 16)) ^ ((r & 7) << 4));
            *(uint4*)(smem + AQ + off) = *((const uint4*)(sq + r * DH_) + c);
        }
    }
    __syncthreads();

    uint32_t qf[4][4];
    #pragma unroll
    for (int ks = 0; ks < 4; ks++) {
        int tsel = lane >> 3;
        int r = 16 * w + (lane & 7) + (tsel & 1) * 8;
        uint32_t off = ((uint32_t)(ks * 32 + ((tsel >> 1) & 1) * 16)) ^ ((r & 7) << 4);
        ldsm_x4(qf[ks], sbs + AQ + r * 128 + off);
    }

    auto prefetch = [&](int c, int buf) {
        const int k0 = c * 64;
        const uint32_t tb = sbs + ATILE(buf);
        #pragma unroll
        for (int i = 0; i < 2; i++) {
            int idx = i * 256 + tid;
            int r = idx >> 3, cc = idx & 7;
            uint32_t off = r * 128 + (((uint32_t)(cc * 16)) ^ ((r & 7) << 4));
            const size_t g = (size_t)(k0 + r) * DH_ + cc * 8;
            cpa16(tb + off,        khf + g);
            cpa16(tb + 8192 + off, vhf + g);
        }
    };

    const int nch = 2 * qb + 2;
    prefetch(0, 0); CP_COMMIT();

    float o[8][4];
    #pragma unroll
    for (int j = 0; j < 8; j++)
        #pragma unroll
        for (int r = 0; r < 4; r++) o[j][r] = 0.f;
    float m0 = -1e30f, m1 = -1e30f, l0 = 0.f, l1 = 0.f;

    const int wrow0 = qb * 128 + 16 * w;
    const int r0 = wrow0 + (lane >> 2), r1 = r0 + 8;

    for (int c = 0; c < nch; c++) {
        const int buf = c & 1;
        CP_WAIT0();
        __syncthreads();
        if (c + 1 < nch) { prefetch(c + 1, buf ^ 1); CP_COMMIT(); }

        const int k0 = c * 64;
        const uint32_t skf = sbs + ATILE(buf);
        const uint32_t svf = skf + 8192;

        #pragma unroll
        for (int hb = 0; hb < 2; hb++) {
            const int kb0 = k0 + hb * 32;
            if (kb0 > wrow0 + 15) break;

            float s[4][4];
            #pragma unroll
            for (int j = 0; j < 4; j++)
                #pragma unroll
                for (int r = 0; r < 4; r++) s[j][r] = 0.f;

            #pragma unroll
            for (int ks = 0; ks < 4; ks++) {
                #pragma unroll
                for (int jp = 0; jp < 2; jp++) {
                    uint32_t kh_[4];
                    int rr = hb * 32 + jp * 16 + ((lane >> 4) << 3) + (lane & 7);
                    uint32_t off = ((uint32_t)(ks * 32 + (((lane >> 3) & 1) << 4)))
                                   ^ ((rr & 7) << 4);
                    ldsm_x4(kh_, skf + rr * 128 + off);
                    mma16816h(s[2*jp],   qf[ks], kh_[0], kh_[1]);
                    mma16816h(s[2*jp+1], qf[ks], kh_[2], kh_[3]);
                }
            }

            if (kb0 + 31 > wrow0) {
                #pragma unroll
                for (int j = 0; j < 4; j++) {
                    int col = kb0 + 8 * j + 2 * (lane & 3);
                    if (col     > r0) s[j][0] = -1e30f;
                    if (col + 1 > r0) s[j][1] = -1e30f;
                    if (col     > r1) s[j][2] = -1e30f;
                    if (col + 1 > r1) s[j][3] = -1e30f;
                }
            }

            float mx0 = -1e30f, mx1 = -1e30f;
            #pragma unroll
            for (int j = 0; j < 4; j++) {
                mx0 = fmaxf(mx0, fmaxf(s[j][0], s[j][1]));
                mx1 = fmaxf(mx1, fmaxf(s[j][2], s[j][3]));
            }
            mx0 = fmaxf(mx0, __shfl_xor_sync(0xffffffffu, mx0, 1));
            mx0 = fmaxf(mx0, __shfl_xor_sync(0xffffffffu, mx0, 2));
            mx1 = fmaxf(mx1, __shfl_xor_sync(0xffffffffu, mx1, 1));
            mx1 = fmaxf(mx1, __shfl_xor_sync(0xffffffffu, mx1, 2));
            float mn0 = fmaxf(m0, mx0), mn1 = fmaxf(m1, mx1);
            bool nochg = __all_sync(0xffffffffu, (mn0 == m0) && (mn1 == m1));
            if (!nochg) {
                float cr0 = ex2f(m0 - mn0), cr1 = ex2f(m1 - mn1);
                l0 *= cr0; l1 *= cr1;
                #pragma unroll
                for (int j = 0; j < 8; j++) {
                    o[j][0] *= cr0; o[j][1] *= cr0;
                    o[j][2] *= cr1; o[j][3] *= cr1;
                }
                m0 = mn0; m1 = mn1;
            }

            uint32_t ph[4][2];
            #pragma unroll
            for (int j = 0; j < 4; j++) {
                float p0 = ex2f(s[j][0] - m0), p1 = ex2f(s[j][1] - m0);
                float p2 = ex2f(s[j][2] - m1), p3 = ex2f(s[j][3] - m1);
                l0 += p0 + p1; l1 += p2 + p3;          // exact fp32 denominator
                ph[j][0] = pack_f16x2(p0, p1);
                ph[j][1] = pack_f16x2(p2, p3);
            }

            #pragma unroll
            for (int kk = 0; kk < 2; kk++) {
                uint32_t ahi[4] = {ph[2*kk][0], ph[2*kk][1], ph[2*kk+1][0], ph[2*kk+1][1]};
                #pragma unroll
                for (int jp = 0; jp < 4; jp++) {
                    uint32_t vh_[4];
                    int tsel = lane >> 3;
                    int key = hb * 32 + 16 * kk + (tsel & 1) * 8 + (lane & 7);
                    uint32_t off = ((uint32_t)((16 * jp + ((tsel >> 1) & 1) * 8) * 2))
                                   ^ ((key & 7) << 4);
                    ldsm_x4_t(vh_, svf + key * 128 + off);
                    mma16816h(o[2*jp],   ahi, vh_[0], vh_[1]);
                    mma16816h(o[2*jp+1], ahi, vh_[2], vh_[3]);
                }
            }
        }
    }

    l0 += __shfl_xor_sync(0xffffffffu, l0, 1);
    l0 += __shfl_xor_sync(0xffffffffu, l0, 2);
    l1 += __shfl_xor_sync(0xffffffffu, l1, 1);
    l1 += __shfl_xor_sync(0xffffffffu, l1, 2);
    const float i0 = 1.f / l0, i1 = 1.f / l1;

    const int tok0 = b * T_ + r0, tok1 = b * T_ + r1;
    #pragma unroll
    for (int j = 0; j < 8; j++) {
        const int n = h * DH_ + 8 * j + 2 * (lane & 3);
        size_t p0 = (size_t)tok0 * WK + n;
        size_t p1 = (size_t)tok1 * WK + n;
        *(__half2*)&g_ao[p0] = __floats2half2_rn(o[j][0] * i0, o[j][1] * i0);
        *(__half2*)&g_ao[p1] = __floats2half2_rn(o[j][2] * i1, o[j][3] * i1);
    }
}

// ---------------- launch --------------------------------------------------------
extern "C" void kernel_launch(void* const* d_in, const int* in_sizes, int n_in,
                              void* d_out, int out_size) {
    const float* X  = (const float*)d_in[0];
    const float* wq = (const float*)d_in[1];
    const float* wk = (const float*)d_in[2];
    const float* wv = (const float*)d_in[3];
    const float* wo = (const float*)d_in[4];
    const float* Aq = (const float*)d_in[5];
    const float* Bq = (const float*)d_in[6];
    const float* Av = (const float*)d_in[7];
    const float* Bv = (const float*)d_in[8];
    float* out = (float*)d_out;

    __half *xh, *ao, *wtqkv, *wto;
    cudaGetSymbolAddress((void**)&xh,    g_xh);
    cudaGetSymbolAddress((void**)&ao,    g_ao);
    cudaGetSymbolAddress((void**)&wtqkv, g_wtqkv);
    cudaGetSymbolAddress((void**)&wto,   g_wto);

    cudaFuncSetAttribute(gemm_fused_kernel,
                         cudaFuncAttributeMaxDynamicSharedMemorySize, G_TOTAL);
    cudaFuncSetAttribute(gemm_fused_kernel,
                         cudaFuncAttributePreferredSharedMemoryCarveout, 100);
    cudaFuncSetAttribute(attn_mma_kernel,
                         cudaFuncAttributeMaxDynamicSharedMemorySize, A_SMEM);
    cudaFuncSetAttribute(attn_mma_kernel,
                         cudaFuncAttributePreferredSharedMemoryCarveout, 100);

    sincos_kernel<<<(T_*32 + 255) / 256, 256>>>();
    lora_split_kernel<<<MTOT, 256>>>(X, Aq, Av);
    split_wt_kernel<<<dim3(32, 32, 4), dim3(32, 8)>>>(wq, wk, wv, wo);

    gemm_fused_kernel<<<dim3(24, 64), 256, G_TOTAL>>>(xh, wtqkv, nullptr, 1, Bq, Bv);

    attn_mma_kernel<<<dim3(T_ / 128, H_, B_), 256, A_SMEM>>>();

    gemm_fused_kernel<<<dim3(8, 64), 256, G_TOTAL>>>(ao, wto, out, 0, nullptr, nullptr);
}